// round 1
// baseline (speedup 1.0000x reference)
#include <cuda_runtime.h>
#include <math.h>

// ---------------------------------------------------------------------------
// Problem constants: B=1, DIM=256, HEADS=8, HD=32, H=W=64 -> N=4096, MLP=1024
// Layout everywhere: [C][N] (NCHW flattened), row stride N=4096 floats.
// ---------------------------------------------------------------------------
#define NPIX 4096
#define DIMC 256
#define MLPC 1024

// Scratch (device globals; no cudaMalloc allowed)
__device__ float g_xd[NPIX];
__device__ float g_r1[DIMC * NPIX];
__device__ float g_pe[DIMC * NPIX];
__device__ float g_rgbln[DIMC * NPIX];
__device__ float g_dptln[DIMC * NPIX];
__device__ float g_q[DIMC * NPIX];
__device__ float g_k[DIMC * NPIX];
__device__ float g_v[DIMC * NPIX];
__device__ float g_fused[DIMC * NPIX];
__device__ float g_o[DIMC * NPIX];
__device__ float g_oln[DIMC * NPIX];
__device__ float g_h[MLPC * NPIX];
__device__ float g_o2[DIMC * NPIX];

// Fast exp: exp(x) = 2^(x*log2e); degree-6 Taylor for 2^f on [0,1) (~1.5e-5
// rel err), exponent via int bit trick. Avoids MUFU pipe (rt 8/SMSP would
// cost ~1ms for 134M softmax exps); pure FMA instead.
__device__ __forceinline__ float fexp(float x) {
    float t = fmaxf(x * 1.4426950408889634f, -126.0f);
    float fi = floorf(t);
    float f = t - fi;
    float p = 1.5403530e-4f;
    p = fmaf(p, f, 1.3333558e-3f);
    p = fmaf(p, f, 9.6181291e-3f);
    p = fmaf(p, f, 5.5504109e-2f);
    p = fmaf(p, f, 2.4022651e-1f);
    p = fmaf(p, f, 6.9314718e-1f);
    p = fmaf(p, f, 1.0f);
    int ei = (int)fi;
    float s = __int_as_float((ei + 127) << 23);
    return p * s;
}

// ---------------------------------------------------------------------------
// Bilinear 16x downsample of 1024x1024 -> 64x64, align_corners=False.
// Sample point = 16i+7.5 -> average of 4 pixels.
// ---------------------------------------------------------------------------
__global__ void downsample_kernel(const float* __restrict__ x, float* __restrict__ xd) {
    int p = blockIdx.x * 256 + threadIdx.x;
    int i = p >> 6, j = p & 63;
    int base = (16 * i + 7) * 1024 + (16 * j + 7);
    xd[p] = 0.25f * (x[base] + x[base + 1] + x[base + 1024] + x[base + 1025]);
}

// conv3x3 (1 in-channel, 256 out) + bias + relu. One block per out channel.
__global__ void conv3_kernel(const float* __restrict__ xd, const float* __restrict__ w,
                             const float* __restrict__ bias, float* __restrict__ y) {
    __shared__ float s_xd[NPIX];
    int tid = threadIdx.x;
    int o = blockIdx.x;
    for (int e = tid; e < NPIX; e += 256) s_xd[e] = xd[e];
    __syncthreads();
    float wr[9];
#pragma unroll
    for (int t = 0; t < 9; ++t) wr[t] = w[o * 9 + t];
    float bv = bias[o];
    for (int it = 0; it < 16; ++it) {
        int p = tid + it * 256;
        int i = p >> 6, j = p & 63;
        float acc = bv;
#pragma unroll
        for (int di = 0; di < 3; ++di) {
            int ii = i + di - 1;
            if (ii < 0 || ii > 63) continue;
#pragma unroll
            for (int dj = 0; dj < 3; ++dj) {
                int jj = j + dj - 1;
                if (jj < 0 || jj > 63) continue;
                acc = fmaf(wr[di * 3 + dj], s_xd[ii * 64 + jj], acc);
            }
        }
        y[o * NPIX + p] = fmaxf(acc, 0.0f);
    }
}

// ---------------------------------------------------------------------------
// Generic GEMM: Y[m][n] = act(sum_k W[m][k] X[k][n] + bias[m]) (+ res[m][n])
// 64x64 tile, BK=16, 256 threads, 4x4 per-thread microtile, float4 smem reads.
// ACT: 0 none, 1 relu, 2 exact gelu.
// ---------------------------------------------------------------------------
template <int ACT, int HAS_RES>
__global__ void gemm_kernel(const float* __restrict__ W, const float* __restrict__ X,
                            const float* __restrict__ bias, const float* __restrict__ res,
                            float* __restrict__ Y, int M, int K, int N) {
    __shared__ float Ws[16][68];
    __shared__ float Xs[16][64];
    int tid = threadIdx.x;
    int tx = tid & 15, ty = tid >> 4;
    int n0 = blockIdx.x * 64;
    int m0 = blockIdx.y * 64;
    float acc[4][4];
#pragma unroll
    for (int i = 0; i < 4; ++i)
#pragma unroll
        for (int j = 0; j < 4; ++j) acc[i][j] = 0.0f;

    for (int k0 = 0; k0 < K; k0 += 16) {
        __syncthreads();
#pragma unroll
        for (int i = 0; i < 4; ++i) {
            int e = tid + i * 256;
            int m = e >> 4, k = e & 15;
            Ws[k][m] = W[(m0 + m) * K + k0 + k];
        }
#pragma unroll
        for (int i = 0; i < 4; ++i) {
            int e = tid + i * 256;
            int k = e >> 6, n = e & 63;
            Xs[k][n] = X[(k0 + k) * N + n0 + n];
        }
        __syncthreads();
#pragma unroll
        for (int k = 0; k < 16; ++k) {
            float4 a = *(const float4*)&Ws[k][ty * 4];
            float4 b = *(const float4*)&Xs[k][tx * 4];
            acc[0][0] = fmaf(a.x, b.x, acc[0][0]);
            acc[0][1] = fmaf(a.x, b.y, acc[0][1]);
            acc[0][2] = fmaf(a.x, b.z, acc[0][2]);
            acc[0][3] = fmaf(a.x, b.w, acc[0][3]);
            acc[1][0] = fmaf(a.y, b.x, acc[1][0]);
            acc[1][1] = fmaf(a.y, b.y, acc[1][1]);
            acc[1][2] = fmaf(a.y, b.z, acc[1][2]);
            acc[1][3] = fmaf(a.y, b.w, acc[1][3]);
            acc[2][0] = fmaf(a.z, b.x, acc[2][0]);
            acc[2][1] = fmaf(a.z, b.y, acc[2][1]);
            acc[2][2] = fmaf(a.z, b.z, acc[2][2]);
            acc[2][3] = fmaf(a.z, b.w, acc[2][3]);
            acc[3][0] = fmaf(a.w, b.x, acc[3][0]);
            acc[3][1] = fmaf(a.w, b.y, acc[3][1]);
            acc[3][2] = fmaf(a.w, b.z, acc[3][2]);
            acc[3][3] = fmaf(a.w, b.w, acc[3][3]);
        }
    }
#pragma unroll
    for (int i = 0; i < 4; ++i) {
        int m = m0 + ty * 4 + i;
        float bv = bias[m];
#pragma unroll
        for (int j = 0; j < 4; ++j) {
            int n = n0 + tx * 4 + j;
            float v = acc[i][j] + bv;
            if (ACT == 1) v = fmaxf(v, 0.0f);
            if (ACT == 2) v = 0.5f * v * (1.0f + erff(v * 0.70710678118654752f));
            if (HAS_RES) v += res[m * N + n];
            Y[m * N + n] = v;
        }
    }
}

// ---------------------------------------------------------------------------
// Channel LayerNorm over C=256 for each of 4096 pixels, optional
// (+ pos_emb[c] + pe[c][p]) fused epilogue. Coalesced: thread = pixel.
// ---------------------------------------------------------------------------
__global__ void ln_kernel(const float* __restrict__ x, const float* __restrict__ g,
                          const float* __restrict__ b, const float* __restrict__ pos,
                          const float* __restrict__ pe, float* __restrict__ y) {
    int p = blockIdx.x * 256 + threadIdx.x;
    float sum = 0.0f, sq = 0.0f;
#pragma unroll 8
    for (int c = 0; c < DIMC; ++c) {
        float v = x[c * NPIX + p];
        sum += v;
        sq = fmaf(v, v, sq);
    }
    float mean = sum * (1.0f / DIMC);
    float var = sq * (1.0f / DIMC) - mean * mean;
    float rstd = rsqrtf(var + 1e-5f);
#pragma unroll 4
    for (int c = 0; c < DIMC; ++c) {
        float v = (x[c * NPIX + p] - mean) * rstd * g[c] + b[c];
        if (pos != nullptr) v += pos[c];
        if (pe != nullptr) v += pe[c * NPIX + p];
        y[c * NPIX + p] = v;
    }
}

// ---------------------------------------------------------------------------
// Flash attention, fp32. Q/K/V layout: [head][d(32)][n(4096)].
// Block: (head, 64-query tile), 256 threads = 64 rows x 4-way d/m split.
// Streams 64 key tiles of 64, online softmax, O accum in registers.
// ---------------------------------------------------------------------------
__global__ void flash_kernel(const float* __restrict__ Q, const float* __restrict__ K,
                             const float* __restrict__ V, const float* __restrict__ scale_ptr,
                             float* __restrict__ O) {
    __shared__ float Qs[64][36];   // [q][d], padded, float4-aligned
    __shared__ float Ks[32][68];   // [d][m], padded, float4-aligned
    __shared__ float Vs[64][36];   // [m][d] (transposed), float4-aligned
    __shared__ float Ps[64][68];   // [q][m], padded, float4-aligned

    int h = blockIdx.y;
    int n0 = blockIdx.x * 64;
    int tid = threadIdx.x;
    int q = tid >> 2;       // query row 0..63
    int dp = tid & 3;       // 4-way split
    int mb = dp * 16;       // score column range
    int db = dp * 8;        // output d range

    float inv_scale = 1.0f / scale_ptr[0];
    const float* Qh = Q + h * 32 * NPIX;
    const float* Kh = K + h * 32 * NPIX;
    const float* Vh = V + h * 32 * NPIX;

    for (int e = tid; e < 2048; e += 256) {
        int d = e >> 6, qq = e & 63;
        Qs[qq][d] = Qh[d * NPIX + n0 + qq] * inv_scale;
    }

    float m_run = -1e30f, l_run = 0.0f;
    float acc[8];
#pragma unroll
    for (int j = 0; j < 8; ++j) acc[j] = 0.0f;

    for (int kt = 0; kt < 64; ++kt) {
        int m0 = kt * 64;
        __syncthreads();  // prior tile's smem reads done (also covers Qs on kt=0)
        for (int e = tid; e < 2048; e += 256) {
            int d = e >> 6, mm = e & 63;
            Ks[d][mm] = Kh[d * NPIX + m0 + mm];
            Vs[mm][d] = Vh[d * NPIX + m0 + mm];
        }
        __syncthreads();

        // scores: s[jj] = sum_d Qs[q][d] * Ks[d][mb+jj]
        float s[16];
#pragma unroll
        for (int jj = 0; jj < 16; ++jj) s[jj] = 0.0f;
#pragma unroll
        for (int d4 = 0; d4 < 8; ++d4) {
            float4 qv = *(const float4*)&Qs[q][d4 * 4];
            float qa[4] = {qv.x, qv.y, qv.z, qv.w};
#pragma unroll
            for (int dd = 0; dd < 4; ++dd) {
                int d = d4 * 4 + dd;
#pragma unroll
                for (int c = 0; c < 4; ++c) {
                    float4 kv = *(const float4*)&Ks[d][mb + c * 4];
                    s[c * 4 + 0] = fmaf(qa[dd], kv.x, s[c * 4 + 0]);
                    s[c * 4 + 1] = fmaf(qa[dd], kv.y, s[c * 4 + 1]);
                    s[c * 4 + 2] = fmaf(qa[dd], kv.z, s[c * 4 + 2]);
                    s[c * 4 + 3] = fmaf(qa[dd], kv.w, s[c * 4 + 3]);
                }
            }
        }

        // online softmax over the row (4 threads per row, same warp)
        float tmax = s[0];
#pragma unroll
        for (int jj = 1; jj < 16; ++jj) tmax = fmaxf(tmax, s[jj]);
        tmax = fmaxf(tmax, __shfl_xor_sync(0xffffffffu, tmax, 1));
        tmax = fmaxf(tmax, __shfl_xor_sync(0xffffffffu, tmax, 2));
        float m_new = fmaxf(m_run, tmax);
        float corr = fexp(m_run - m_new);
        float psum = 0.0f;
#pragma unroll
        for (int jj = 0; jj < 16; ++jj) {
            float pv = fexp(s[jj] - m_new);
            Ps[q][mb + jj] = pv;
            psum += pv;
        }
        psum += __shfl_xor_sync(0xffffffffu, psum, 1);
        psum += __shfl_xor_sync(0xffffffffu, psum, 2);
        l_run = l_run * corr + psum;
        m_run = m_new;
#pragma unroll
        for (int j = 0; j < 8; ++j) acc[j] *= corr;
        __syncwarp();  // row's 4 writers are in this warp

        // O[q][db..db+7] += sum_m Ps[q][m] * V[m][d]
#pragma unroll
        for (int mm = 0; mm < 64; ++mm) {
            float pv = Ps[q][mm];
            float4 v0 = *(const float4*)&Vs[mm][db];
            float4 v1 = *(const float4*)&Vs[mm][db + 4];
            acc[0] = fmaf(pv, v0.x, acc[0]);
            acc[1] = fmaf(pv, v0.y, acc[1]);
            acc[2] = fmaf(pv, v0.z, acc[2]);
            acc[3] = fmaf(pv, v0.w, acc[3]);
            acc[4] = fmaf(pv, v1.x, acc[4]);
            acc[5] = fmaf(pv, v1.y, acc[5]);
            acc[6] = fmaf(pv, v1.z, acc[6]);
            acc[7] = fmaf(pv, v1.w, acc[7]);
        }
    }

    float rl = 1.0f / l_run;
#pragma unroll
    for (int j = 0; j < 8; ++j)
        O[(h * 32 + db + j) * NPIX + n0 + q] = acc[j] * rl;
}

// ---------------------------------------------------------------------------
extern "C" void kernel_launch(void* const* d_in, const int* in_sizes, int n_in,
                              void* d_out, int out_size) {
    const float* rgb   = (const float*)d_in[0];
    const float* dpt   = (const float*)d_in[1];
    const float* xdpt  = (const float*)d_in[2];
    const float* wq    = (const float*)d_in[3];
    const float* bq    = (const float*)d_in[4];
    const float* wk    = (const float*)d_in[5];
    const float* bk    = (const float*)d_in[6];
    const float* wv    = (const float*)d_in[7];
    const float* bv    = (const float*)d_in[8];
    const float* wo    = (const float*)d_in[9];
    const float* bo    = (const float*)d_in[10];
    const float* ga_rgb = (const float*)d_in[11];
    const float* be_rgb = (const float*)d_in[12];
    const float* ga_dpt = (const float*)d_in[13];
    const float* be_dpt = (const float*)d_in[14];
    const float* ga1   = (const float*)d_in[15];
    const float* be1   = (const float*)d_in[16];
    const float* ga2   = (const float*)d_in[17];
    const float* be2   = (const float*)d_in[18];
    const float* w_mlp1 = (const float*)d_in[19];
    const float* b_mlp1 = (const float*)d_in[20];
    const float* w_mlp2 = (const float*)d_in[21];
    const float* b_mlp2 = (const float*)d_in[22];
    const float* w_de1 = (const float*)d_in[23];
    const float* b_de1 = (const float*)d_in[24];
    const float* w_de2 = (const float*)d_in[25];
    const float* b_de2 = (const float*)d_in[26];
    const float* pos_emb = (const float*)d_in[27];
    const float* scale = (const float*)d_in[28];
    float* out = (float*)d_out;

    float *p_xd, *p_r1, *p_pe, *p_rgbln, *p_dptln, *p_q, *p_k, *p_v;
    float *p_fused, *p_o, *p_oln, *p_h, *p_o2;
    cudaGetSymbolAddress((void**)&p_xd, g_xd);
    cudaGetSymbolAddress((void**)&p_r1, g_r1);
    cudaGetSymbolAddress((void**)&p_pe, g_pe);
    cudaGetSymbolAddress((void**)&p_rgbln, g_rgbln);
    cudaGetSymbolAddress((void**)&p_dptln, g_dptln);
    cudaGetSymbolAddress((void**)&p_q, g_q);
    cudaGetSymbolAddress((void**)&p_k, g_k);
    cudaGetSymbolAddress((void**)&p_v, g_v);
    cudaGetSymbolAddress((void**)&p_fused, g_fused);
    cudaGetSymbolAddress((void**)&p_o, g_o);
    cudaGetSymbolAddress((void**)&p_oln, g_oln);
    cudaGetSymbolAddress((void**)&p_h, g_h);
    cudaGetSymbolAddress((void**)&p_o2, g_o2);

    // depth positional-embedding path
    downsample_kernel<<<16, 256>>>(xdpt, p_xd);
    conv3_kernel<<<256, 256>>>(p_xd, w_de1, b_de1, p_r1);
    gemm_kernel<0, 0><<<dim3(64, 4), 256>>>(w_de2, p_r1, b_de2, nullptr, p_pe, 256, 256, NPIX);

    // LN(+pos+pe) on both streams
    ln_kernel<<<16, 256>>>(rgb, ga_rgb, be_rgb, pos_emb, p_pe, p_rgbln);
    ln_kernel<<<16, 256>>>(dpt, ga_dpt, be_dpt, pos_emb, p_pe, p_dptln);

    // QKV projections
    gemm_kernel<0, 0><<<dim3(64, 4), 256>>>(wq, p_rgbln, bq, nullptr, p_q, 256, 256, NPIX);
    gemm_kernel<0, 0><<<dim3(64, 4), 256>>>(wk, p_dptln, bk, nullptr, p_k, 256, 256, NPIX);
    gemm_kernel<0, 0><<<dim3(64, 4), 256>>>(wv, p_dptln, bv, nullptr, p_v, 256, 256, NPIX);

    // flash attention (8 heads x 64 query-tiles)
    flash_kernel<<<dim3(64, 8), 256>>>(p_q, p_k, p_v, scale, p_fused);

    // output proj + residual, LN
    gemm_kernel<0, 1><<<dim3(64, 4), 256>>>(wo, p_fused, bo, rgb, p_o, 256, 256, NPIX);
    ln_kernel<<<16, 256>>>(p_o, ga1, be1, nullptr, nullptr, p_oln);

    // MLP (exact gelu), residual, final LN -> d_out
    gemm_kernel<2, 0><<<dim3(64, 16), 256>>>(w_mlp1, p_oln, b_mlp1, nullptr, p_h, MLPC, 256, NPIX);
    gemm_kernel<0, 1><<<dim3(64, 4), 256>>>(w_mlp2, p_h, b_mlp2, p_oln, p_o2, 256, MLPC, NPIX);
    ln_kernel<<<16, 256>>>(p_o2, ga2, be2, nullptr, nullptr, out);
}

// round 3
// speedup vs baseline: 1.1246x; 1.1246x over previous
#include <cuda_runtime.h>
#include <math.h>
#include <stdint.h>

// ---------------------------------------------------------------------------
// B=1, DIM=256, HEADS=8, HD=32, H=W=64 -> N=4096, MLP=1024
// Layout: [C][N] (NCHW flattened), row stride N=4096 floats.
// ---------------------------------------------------------------------------
#define NPIX 4096
#define DIMC 256
#define MLPC 1024

__device__ float g_xd[NPIX];
__device__ float g_r1[DIMC * NPIX];
__device__ float g_pe[DIMC * NPIX];
__device__ float g_rgbln[DIMC * NPIX];
__device__ float g_dptln[DIMC * NPIX];
__device__ float g_q[DIMC * NPIX];
__device__ float g_k[DIMC * NPIX];
__device__ float g_v[DIMC * NPIX];
__device__ float g_fused[DIMC * NPIX];
__device__ float g_o[DIMC * NPIX];
__device__ float g_oln[DIMC * NPIX];
__device__ float g_h[MLPC * NPIX];
__device__ float g_o2[DIMC * NPIX];

__device__ __forceinline__ uint32_t f2tf32(float x) {
    uint32_t u;
    asm("cvt.rna.tf32.f32 %0, %1;" : "=r"(u) : "f"(x));
    return u;
}

// Fast exp on FMA pipe (softmax; avoids MUFU rt=8 bottleneck)
__device__ __forceinline__ float fexp(float x) {
    float t = fmaxf(x * 1.4426950408889634f, -126.0f);
    float fi = floorf(t);
    float f = t - fi;
    float p = 1.5403530e-4f;
    p = fmaf(p, f, 1.3333558e-3f);
    p = fmaf(p, f, 9.6181291e-3f);
    p = fmaf(p, f, 5.5504109e-2f);
    p = fmaf(p, f, 2.4022651e-1f);
    p = fmaf(p, f, 6.9314718e-1f);
    p = fmaf(p, f, 1.0f);
    int ei = (int)fi;
    float s = __int_as_float((ei + 127) << 23);
    return p * s;
}

// ---------------------------------------------------------------------------
// Bilinear 16x downsample 1024x1024 -> 64x64 (align_corners=False)
// ---------------------------------------------------------------------------
__global__ void downsample_kernel(const float* __restrict__ x, float* __restrict__ xd) {
    int p = blockIdx.x * 256 + threadIdx.x;
    int i = p >> 6, j = p & 63;
    int base = (16 * i + 7) * 1024 + (16 * j + 7);
    xd[p] = 0.25f * (x[base] + x[base + 1] + x[base + 1024] + x[base + 1025]);
}

// conv3x3 (1 in, 256 out) + bias + relu
__global__ void conv3_kernel(const float* __restrict__ xd, const float* __restrict__ w,
                             const float* __restrict__ bias, float* __restrict__ y) {
    __shared__ float s_xd[NPIX];
    int tid = threadIdx.x;
    int o = blockIdx.x;
    for (int e = tid; e < NPIX; e += 256) s_xd[e] = xd[e];
    __syncthreads();
    float wr[9];
#pragma unroll
    for (int t = 0; t < 9; ++t) wr[t] = w[o * 9 + t];
    float bv = bias[o];
    for (int it = 0; it < 16; ++it) {
        int p = tid + it * 256;
        int i = p >> 6, j = p & 63;
        float acc = bv;
#pragma unroll
        for (int di = 0; di < 3; ++di) {
            int ii = i + di - 1;
            if (ii < 0 || ii > 63) continue;
#pragma unroll
            for (int dj = 0; dj < 3; ++dj) {
                int jj = j + dj - 1;
                if (jj < 0 || jj > 63) continue;
                acc = fmaf(wr[di * 3 + dj], s_xd[ii * 64 + jj], acc);
            }
        }
        y[o * NPIX + p] = fmaxf(acc, 0.0f);
    }
}

// ---------------------------------------------------------------------------
// Tensor-core GEMM via mma.sync m16n8k8 tf32 (sm_80+ path; tcgen05 is not
// accepted by this toolchain's sm_103 PTX target).
// Y[m][n] = act(sum_k W[m][k] X[k][n] + bias[m]) (+ res[m][n])
// CTA tile 128m x 64n, K chunked by 32, 8 warps of 32x32 warp tiles.
// Smem (dynamic, 55296B): A[2][128][36], B[2][32][72] as tf32 bits.
// Padding strides 36/72 make every fragment LDS phase conflict-free.
// Register-prefetch double buffering over K chunks.
// ---------------------------------------------------------------------------
#define GEMM_SMEM 55296

__device__ __forceinline__ void mma_tf32(float c[4], const uint32_t a[4], const uint32_t b[2]) {
    asm volatile(
        "mma.sync.aligned.m16n8k8.row.col.f32.tf32.tf32.f32 "
        "{%0,%1,%2,%3}, {%4,%5,%6,%7}, {%8,%9}, {%0,%1,%2,%3};"
        : "+f"(c[0]), "+f"(c[1]), "+f"(c[2]), "+f"(c[3])
        : "r"(a[0]), "r"(a[1]), "r"(a[2]), "r"(a[3]), "r"(b[0]), "r"(b[1]));
}

template <int ACT, int HAS_RES>
__global__ void __launch_bounds__(256, 2)
gemm_mma(const float* __restrict__ W, const float* __restrict__ X,
         const float* __restrict__ bias, const float* __restrict__ res,
         float* __restrict__ Y, int M, int K, int N) {
    extern __shared__ uint32_t sm[];
    uint32_t* As[2] = {sm, sm + 4608};            // 128 x 36
    uint32_t* Bs[2] = {sm + 9216, sm + 11520};    // 32 x 72

    int tid = threadIdx.x;
    int wid = tid >> 5, lane = tid & 31;
    int wm = wid >> 1, wn = wid & 1;
    int g = lane >> 2, tg = lane & 3;
    int m0 = blockIdx.y * 128;
    int n0 = blockIdx.x * 64;

    // per-thread gmem load coords
    int ar = tid >> 3;        // A row base (stride 32 over 4 iters)
    int aks = tid & 7;        // A k-slot (4 floats)
    int bk = tid >> 4;        // B k base (stride 16 over 2 iters)
    int bn4 = tid & 15;       // B n-slot (4 floats)

    float4 ra[4], rb[2];
    const int C = K >> 5;

    // prefetch chunk 0
#pragma unroll
    for (int it = 0; it < 4; ++it)
        ra[it] = *(const float4*)(W + (size_t)(m0 + ar + it * 32) * K + aks * 4);
#pragma unroll
    for (int it = 0; it < 2; ++it)
        rb[it] = *(const float4*)(X + (size_t)(bk + it * 16) * N + n0 + bn4 * 4);

    float acc[2][4][4];
#pragma unroll
    for (int t = 0; t < 2; ++t)
#pragma unroll
        for (int u = 0; u < 4; ++u)
#pragma unroll
            for (int e = 0; e < 4; ++e) acc[t][u][e] = 0.0f;

    // store chunk 0
#pragma unroll
    for (int it = 0; it < 4; ++it) {
        uint32_t* d = As[0] + (ar + it * 32) * 36 + aks * 4;
        d[0] = f2tf32(ra[it].x); d[1] = f2tf32(ra[it].y);
        d[2] = f2tf32(ra[it].z); d[3] = f2tf32(ra[it].w);
    }
#pragma unroll
    for (int it = 0; it < 2; ++it) {
        uint32_t* d = Bs[0] + (bk + it * 16) * 72 + bn4 * 4;
        d[0] = f2tf32(rb[it].x); d[1] = f2tf32(rb[it].y);
        d[2] = f2tf32(rb[it].z); d[3] = f2tf32(rb[it].w);
    }
    __syncthreads();

    for (int c = 0; c < C; ++c) {
        // issue next chunk's LDGs before compute
        if (c + 1 < C) {
            int k0 = (c + 1) << 5;
#pragma unroll
            for (int it = 0; it < 4; ++it)
                ra[it] = *(const float4*)(W + (size_t)(m0 + ar + it * 32) * K + k0 + aks * 4);
#pragma unroll
            for (int it = 0; it < 2; ++it)
                rb[it] = *(const float4*)(X + (size_t)(k0 + bk + it * 16) * N + n0 + bn4 * 4);
        }

        const uint32_t* Ab = As[c & 1];
        const uint32_t* Bb = Bs[c & 1];
#pragma unroll
        for (int ks = 0; ks < 4; ++ks) {
            uint32_t a[2][4], b[4][2];
#pragma unroll
            for (int t = 0; t < 2; ++t) {
                int rr = wm * 32 + t * 16 + g;
                int kc = ks * 8 + tg;
                a[t][0] = Ab[rr * 36 + kc];
                a[t][1] = Ab[(rr + 8) * 36 + kc];
                a[t][2] = Ab[rr * 36 + kc + 4];
                a[t][3] = Ab[(rr + 8) * 36 + kc + 4];
            }
#pragma unroll
            for (int u = 0; u < 4; ++u) {
                int nn = wn * 32 + u * 8 + g;
                b[u][0] = Bb[(ks * 8 + tg) * 72 + nn];
                b[u][1] = Bb[(ks * 8 + tg + 4) * 72 + nn];
            }
#pragma unroll
            for (int t = 0; t < 2; ++t)
#pragma unroll
                for (int u = 0; u < 4; ++u) mma_tf32(acc[t][u], a[t], b[u]);
        }
        __syncthreads();
        if (c + 1 < C) {
            int nb = (c + 1) & 1;
#pragma unroll
            for (int it = 0; it < 4; ++it) {
                uint32_t* d = As[nb] + (ar + it * 32) * 36 + aks * 4;
                d[0] = f2tf32(ra[it].x); d[1] = f2tf32(ra[it].y);
                d[2] = f2tf32(ra[it].z); d[3] = f2tf32(ra[it].w);
            }
#pragma unroll
            for (int it = 0; it < 2; ++it) {
                uint32_t* d = Bs[nb] + (bk + it * 16) * 72 + bn4 * 4;
                d[0] = f2tf32(rb[it].x); d[1] = f2tf32(rb[it].y);
                d[2] = f2tf32(rb[it].z); d[3] = f2tf32(rb[it].w);
            }
            __syncthreads();
        }
    }

    // epilogue: bias/act(/res), direct float2 stores (lane quads cover 32B)
#pragma unroll
    for (int t = 0; t < 2; ++t) {
        int m1 = m0 + wm * 32 + t * 16 + g;
        int m2 = m1 + 8;
        float bv1 = bias[m1], bv2 = bias[m2];
#pragma unroll
        for (int u = 0; u < 4; ++u) {
            int n = n0 + wn * 32 + u * 8 + 2 * tg;
            float v0 = acc[t][u][0] + bv1;
            float v1 = acc[t][u][1] + bv1;
            float v2 = acc[t][u][2] + bv2;
            float v3 = acc[t][u][3] + bv2;
            if (ACT == 2) {
                v0 = 0.5f * v0 * (1.0f + erff(v0 * 0.70710678118654752f));
                v1 = 0.5f * v1 * (1.0f + erff(v1 * 0.70710678118654752f));
                v2 = 0.5f * v2 * (1.0f + erff(v2 * 0.70710678118654752f));
                v3 = 0.5f * v3 * (1.0f + erff(v3 * 0.70710678118654752f));
            }
            size_t gi1 = (size_t)m1 * N + n;
            size_t gi2 = (size_t)m2 * N + n;
            if (HAS_RES) {
                float2 r1 = *(const float2*)(res + gi1);
                float2 r2 = *(const float2*)(res + gi2);
                v0 += r1.x; v1 += r1.y; v2 += r2.x; v3 += r2.y;
            }
            *(float2*)(Y + gi1) = make_float2(v0, v1);
            *(float2*)(Y + gi2) = make_float2(v2, v3);
        }
    }
}

// ---------------------------------------------------------------------------
// LayerNorm over C=256 per pixel. 256 thr = 32 pixels x 8 channel groups,
// values register-resident between passes. grid=128.
// ---------------------------------------------------------------------------
__global__ void ln_kernel(const float* __restrict__ x, const float* __restrict__ g,
                          const float* __restrict__ b, const float* __restrict__ pos,
                          const float* __restrict__ pe, float* __restrict__ y) {
    __shared__ float ssum[8][32], ssq[8][32];
    int tid = threadIdx.x;
    int lane = tid & 31, cg = tid >> 5;
    int p = blockIdx.x * 32 + lane;
    const float* xp = x + (size_t)cg * 32 * NPIX + p;
    float v[32];
    float s = 0.0f, q = 0.0f;
#pragma unroll
    for (int i = 0; i < 32; ++i) {
        v[i] = xp[(size_t)i * NPIX];
        s += v[i];
        q = fmaf(v[i], v[i], q);
    }
    ssum[cg][lane] = s;
    ssq[cg][lane] = q;
    __syncthreads();
    float ts = 0.0f, tq = 0.0f;
#pragma unroll
    for (int j = 0; j < 8; ++j) {
        ts += ssum[j][lane];
        tq += ssq[j][lane];
    }
    float mean = ts * (1.0f / DIMC);
    float var = tq * (1.0f / DIMC) - mean * mean;
    float rstd = rsqrtf(var + 1e-5f);
#pragma unroll
    for (int i = 0; i < 32; ++i) {
        int c = cg * 32 + i;
        float o = (v[i] - mean) * rstd * g[c] + b[c];
        if (pos != nullptr) o += pos[c];
        if (pe != nullptr) o += pe[(size_t)c * NPIX + p];
        y[(size_t)c * NPIX + p] = o;
    }
}

// ---------------------------------------------------------------------------
// Flash attention, fp32 SIMT (unchanged, proven). Q/K/V: [head][d(32)][n].
// ---------------------------------------------------------------------------
__global__ void flash_kernel(const float* __restrict__ Q, const float* __restrict__ K,
                             const float* __restrict__ V, const float* __restrict__ scale_ptr,
                             float* __restrict__ O) {
    __shared__ float Qs[64][36];
    __shared__ float Ks[32][68];
    __shared__ float Vs[64][36];
    __shared__ float Ps[64][68];

    int h = blockIdx.y;
    int n0 = blockIdx.x * 64;
    int tid = threadIdx.x;
    int q = tid >> 2;
    int dp = tid & 3;
    int mb = dp * 16;
    int db = dp * 8;

    float inv_scale = 1.0f / scale_ptr[0];
    const float* Qh = Q + h * 32 * NPIX;
    const float* Kh = K + h * 32 * NPIX;
    const float* Vh = V + h * 32 * NPIX;

    for (int e = tid; e < 2048; e += 256) {
        int d = e >> 6, qq = e & 63;
        Qs[qq][d] = Qh[d * NPIX + n0 + qq] * inv_scale;
    }

    float m_run = -1e30f, l_run = 0.0f;
    float acc[8];
#pragma unroll
    for (int j = 0; j < 8; ++j) acc[j] = 0.0f;

    for (int kt = 0; kt < 64; ++kt) {
        int m0 = kt * 64;
        __syncthreads();
        for (int e = tid; e < 2048; e += 256) {
            int d = e >> 6, mm = e & 63;
            Ks[d][mm] = Kh[d * NPIX + m0 + mm];
            Vs[mm][d] = Vh[d * NPIX + m0 + mm];
        }
        __syncthreads();

        float s[16];
#pragma unroll
        for (int jj = 0; jj < 16; ++jj) s[jj] = 0.0f;
#pragma unroll
        for (int d4 = 0; d4 < 8; ++d4) {
            float4 qv = *(const float4*)&Qs[q][d4 * 4];
            float qa[4] = {qv.x, qv.y, qv.z, qv.w};
#pragma unroll
            for (int dd = 0; dd < 4; ++dd) {
                int d = d4 * 4 + dd;
#pragma unroll
                for (int c = 0; c < 4; ++c) {
                    float4 kv = *(const float4*)&Ks[d][mb + c * 4];
                    s[c * 4 + 0] = fmaf(qa[dd], kv.x, s[c * 4 + 0]);
                    s[c * 4 + 1] = fmaf(qa[dd], kv.y, s[c * 4 + 1]);
                    s[c * 4 + 2] = fmaf(qa[dd], kv.z, s[c * 4 + 2]);
                    s[c * 4 + 3] = fmaf(qa[dd], kv.w, s[c * 4 + 3]);
                }
            }
        }

        float tmax = s[0];
#pragma unroll
        for (int jj = 1; jj < 16; ++jj) tmax = fmaxf(tmax, s[jj]);
        tmax = fmaxf(tmax, __shfl_xor_sync(0xffffffffu, tmax, 1));
        tmax = fmaxf(tmax, __shfl_xor_sync(0xffffffffu, tmax, 2));
        float m_new = fmaxf(m_run, tmax);
        float corr = fexp(m_run - m_new);
        float psum = 0.0f;
#pragma unroll
        for (int jj = 0; jj < 16; ++jj) {
            float pv = fexp(s[jj] - m_new);
            Ps[q][mb + jj] = pv;
            psum += pv;
        }
        psum += __shfl_xor_sync(0xffffffffu, psum, 1);
        psum += __shfl_xor_sync(0xffffffffu, psum, 2);
        l_run = l_run * corr + psum;
        m_run = m_new;
#pragma unroll
        for (int j = 0; j < 8; ++j) acc[j] *= corr;
        __syncwarp();

#pragma unroll
        for (int mm = 0; mm < 64; ++mm) {
            float pv = Ps[q][mm];
            float4 v0 = *(const float4*)&Vs[mm][db];
            float4 v1 = *(const float4*)&Vs[mm][db + 4];
            acc[0] = fmaf(pv, v0.x, acc[0]);
            acc[1] = fmaf(pv, v0.y, acc[1]);
            acc[2] = fmaf(pv, v0.z, acc[2]);
            acc[3] = fmaf(pv, v0.w, acc[3]);
            acc[4] = fmaf(pv, v1.x, acc[4]);
            acc[5] = fmaf(pv, v1.y, acc[5]);
            acc[6] = fmaf(pv, v1.z, acc[6]);
            acc[7] = fmaf(pv, v1.w, acc[7]);
        }
    }

    float rl = 1.0f / l_run;
#pragma unroll
    for (int j = 0; j < 8; ++j)
        O[(h * 32 + db + j) * NPIX + n0 + q] = acc[j] * rl;
}

// ---------------------------------------------------------------------------
extern "C" void kernel_launch(void* const* d_in, const int* in_sizes, int n_in,
                              void* d_out, int out_size) {
    const float* rgb   = (const float*)d_in[0];
    const float* dpt   = (const float*)d_in[1];
    const float* xdpt  = (const float*)d_in[2];
    const float* wq    = (const float*)d_in[3];
    const float* bq    = (const float*)d_in[4];
    const float* wk    = (const float*)d_in[5];
    const float* bk    = (const float*)d_in[6];
    const float* wv    = (const float*)d_in[7];
    const float* bv    = (const float*)d_in[8];
    const float* wo    = (const float*)d_in[9];
    const float* bo    = (const float*)d_in[10];
    const float* ga_rgb = (const float*)d_in[11];
    const float* be_rgb = (const float*)d_in[12];
    const float* ga_dpt = (const float*)d_in[13];
    const float* be_dpt = (const float*)d_in[14];
    const float* ga1   = (const float*)d_in[15];
    const float* be1   = (const float*)d_in[16];
    const float* ga2   = (const float*)d_in[17];
    const float* be2   = (const float*)d_in[18];
    const float* w_mlp1 = (const float*)d_in[19];
    const float* b_mlp1 = (const float*)d_in[20];
    const float* w_mlp2 = (const float*)d_in[21];
    const float* b_mlp2 = (const float*)d_in[22];
    const float* w_de1 = (const float*)d_in[23];
    const float* b_de1 = (const float*)d_in[24];
    const float* w_de2 = (const float*)d_in[25];
    const float* b_de2 = (const float*)d_in[26];
    const float* pos_emb = (const float*)d_in[27];
    const float* scale = (const float*)d_in[28];
    float* out = (float*)d_out;

    float *p_xd, *p_r1, *p_pe, *p_rgbln, *p_dptln, *p_q, *p_k, *p_v;
    float *p_fused, *p_o, *p_oln, *p_h, *p_o2;
    cudaGetSymbolAddress((void**)&p_xd, g_xd);
    cudaGetSymbolAddress((void**)&p_r1, g_r1);
    cudaGetSymbolAddress((void**)&p_pe, g_pe);
    cudaGetSymbolAddress((void**)&p_rgbln, g_rgbln);
    cudaGetSymbolAddress((void**)&p_dptln, g_dptln);
    cudaGetSymbolAddress((void**)&p_q, g_q);
    cudaGetSymbolAddress((void**)&p_k, g_k);
    cudaGetSymbolAddress((void**)&p_v, g_v);
    cudaGetSymbolAddress((void**)&p_fused, g_fused);
    cudaGetSymbolAddress((void**)&p_o, g_o);
    cudaGetSymbolAddress((void**)&p_oln, g_oln);
    cudaGetSymbolAddress((void**)&p_h, g_h);
    cudaGetSymbolAddress((void**)&p_o2, g_o2);

    static bool attr_done = false;
    if (!attr_done) {
        cudaFuncSetAttribute(gemm_mma<0, 0>, cudaFuncAttributeMaxDynamicSharedMemorySize, GEMM_SMEM);
        cudaFuncSetAttribute(gemm_mma<0, 1>, cudaFuncAttributeMaxDynamicSharedMemorySize, GEMM_SMEM);
        cudaFuncSetAttribute(gemm_mma<2, 0>, cudaFuncAttributeMaxDynamicSharedMemorySize, GEMM_SMEM);
        attr_done = true;
    }

    // depth positional-embedding path
    downsample_kernel<<<16, 256>>>(xdpt, p_xd);
    conv3_kernel<<<256, 256>>>(p_xd, w_de1, b_de1, p_r1);
    gemm_mma<0, 0><<<dim3(64, 2), 256, GEMM_SMEM>>>(w_de2, p_r1, b_de2, nullptr, p_pe, 256, 256, NPIX);

    // LN(+pos+pe) on both streams
    ln_kernel<<<128, 256>>>(rgb, ga_rgb, be_rgb, pos_emb, p_pe, p_rgbln);
    ln_kernel<<<128, 256>>>(dpt, ga_dpt, be_dpt, pos_emb, p_pe, p_dptln);

    // QKV projections
    gemm_mma<0, 0><<<dim3(64, 2), 256, GEMM_SMEM>>>(wq, p_rgbln, bq, nullptr, p_q, 256, 256, NPIX);
    gemm_mma<0, 0><<<dim3(64, 2), 256, GEMM_SMEM>>>(wk, p_dptln, bk, nullptr, p_k, 256, 256, NPIX);
    gemm_mma<0, 0><<<dim3(64, 2), 256, GEMM_SMEM>>>(wv, p_dptln, bv, nullptr, p_v, 256, 256, NPIX);

    // flash attention (8 heads x 64 query-tiles)
    flash_kernel<<<dim3(64, 8), 256>>>(p_q, p_k, p_v, scale, p_fused);

    // output proj + residual, LN
    gemm_mma<0, 1><<<dim3(64, 2), 256, GEMM_SMEM>>>(wo, p_fused, bo, rgb, p_o, 256, 256, NPIX);
    ln_kernel<<<128, 256>>>(p_o, ga1, be1, nullptr, nullptr, p_oln);

    // MLP (exact gelu), residual, final LN -> d_out
    gemm_mma<2, 0><<<dim3(64, 8), 256, GEMM_SMEM>>>(w_mlp1, p_oln, b_mlp1, nullptr, p_h, MLPC, 256, NPIX);
    gemm_mma<0, 1><<<dim3(64, 2), 256, GEMM_SMEM>>>(w_mlp2, p_h, b_mlp2, p_oln, p_o2, 256, MLPC, NPIX);
    ln_kernel<<<128, 256>>>(p_o2, ga2, be2, nullptr, nullptr, out);
}

// round 4
// speedup vs baseline: 4.9630x; 4.4132x over previous
#include <cuda_runtime.h>
#include <math.h>
#include <stdint.h>

// ---------------------------------------------------------------------------
// B=1, DIM=256, HEADS=8, HD=32, H=W=64 -> N=4096, MLP=1024
// Layout: [C][N] (NCHW flattened), row stride N=4096 floats.
// ---------------------------------------------------------------------------
#define NPIX 4096
#define DIMC 256
#define MLPC 1024

__device__ float g_xd[NPIX];
__device__ float g_r1[DIMC * NPIX];
__device__ float g_pe[DIMC * NPIX];
__device__ float g_rgbln[DIMC * NPIX];
__device__ float g_dptln[DIMC * NPIX];
__device__ float g_q[DIMC * NPIX];
__device__ float g_k[DIMC * NPIX];
__device__ float g_v[DIMC * NPIX];
__device__ float g_fused[DIMC * NPIX];
__device__ float g_o[DIMC * NPIX];
__device__ float g_oln[DIMC * NPIX];
__device__ float g_h[MLPC * NPIX];
__device__ float g_o2[DIMC * NPIX];

__device__ __forceinline__ uint32_t f2tf32(float x) {
    uint32_t u;
    asm("cvt.rna.tf32.f32 %0, %1;" : "=r"(u) : "f"(x));
    return u;
}

// Fast exp on FMA pipe (softmax; avoids MUFU rt=8 bottleneck)
__device__ __forceinline__ float fexp(float x) {
    float t = fmaxf(x * 1.4426950408889634f, -126.0f);
    float fi = floorf(t);
    float f = t - fi;
    float p = 1.5403530e-4f;
    p = fmaf(p, f, 1.3333558e-3f);
    p = fmaf(p, f, 9.6181291e-3f);
    p = fmaf(p, f, 5.5504109e-2f);
    p = fmaf(p, f, 2.4022651e-1f);
    p = fmaf(p, f, 6.9314718e-1f);
    p = fmaf(p, f, 1.0f);
    int ei = (int)fi;
    float s = __int_as_float((ei + 127) << 23);
    return p * s;
}

// m16n8k8 tf32 HMMA (layout empirically validated by R3 gemm)
__device__ __forceinline__ void mma_tf32(float c[4], const uint32_t a[4], const uint32_t b[2]) {
    asm volatile(
        "mma.sync.aligned.m16n8k8.row.col.f32.tf32.tf32.f32 "
        "{%0,%1,%2,%3}, {%4,%5,%6,%7}, {%8,%9}, {%0,%1,%2,%3};"
        : "+f"(c[0]), "+f"(c[1]), "+f"(c[2]), "+f"(c[3])
        : "r"(a[0]), "r"(a[1]), "r"(a[2]), "r"(a[3]), "r"(b[0]), "r"(b[1]));
}

// ---------------------------------------------------------------------------
// Bilinear 16x downsample 1024x1024 -> 64x64 (align_corners=False)
// ---------------------------------------------------------------------------
__global__ void downsample_kernel(const float* __restrict__ x, float* __restrict__ xd) {
    int p = blockIdx.x * 256 + threadIdx.x;
    int i = p >> 6, j = p & 63;
    int base = (16 * i + 7) * 1024 + (16 * j + 7);
    xd[p] = 0.25f * (x[base] + x[base + 1] + x[base + 1024] + x[base + 1025]);
}

// conv3x3 (1 in, 256 out) + bias + relu
__global__ void conv3_kernel(const float* __restrict__ xd, const float* __restrict__ w,
                             const float* __restrict__ bias, float* __restrict__ y) {
    __shared__ float s_xd[NPIX];
    int tid = threadIdx.x;
    int o = blockIdx.x;
    for (int e = tid; e < NPIX; e += 256) s_xd[e] = xd[e];
    __syncthreads();
    float wr[9];
#pragma unroll
    for (int t = 0; t < 9; ++t) wr[t] = w[o * 9 + t];
    float bv = bias[o];
    for (int it = 0; it < 16; ++it) {
        int p = tid + it * 256;
        int i = p >> 6, j = p & 63;
        float acc = bv;
#pragma unroll
        for (int di = 0; di < 3; ++di) {
            int ii = i + di - 1;
            if (ii < 0 || ii > 63) continue;
#pragma unroll
            for (int dj = 0; dj < 3; ++dj) {
                int jj = j + dj - 1;
                if (jj < 0 || jj > 63) continue;
                acc = fmaf(wr[di * 3 + dj], s_xd[ii * 64 + jj], acc);
            }
        }
        y[o * NPIX + p] = fmaxf(acc, 0.0f);
    }
}

// ---------------------------------------------------------------------------
// Tensor-core GEMM (mma.sync tf32) — unchanged from R3 (proven).
// ---------------------------------------------------------------------------
#define GEMM_SMEM 55296

template <int ACT, int HAS_RES>
__global__ void __launch_bounds__(256, 2)
gemm_mma(const float* __restrict__ W, const float* __restrict__ X,
         const float* __restrict__ bias, const float* __restrict__ res,
         float* __restrict__ Y, int M, int K, int N) {
    extern __shared__ uint32_t sm[];
    uint32_t* As[2] = {sm, sm + 4608};            // 128 x 36
    uint32_t* Bs[2] = {sm + 9216, sm + 11520};    // 32 x 72

    int tid = threadIdx.x;
    int wid = tid >> 5, lane = tid & 31;
    int wm = wid >> 1, wn = wid & 1;
    int g = lane >> 2, tg = lane & 3;
    int m0 = blockIdx.y * 128;
    int n0 = blockIdx.x * 64;

    int ar = tid >> 3;
    int aks = tid & 7;
    int bk = tid >> 4;
    int bn4 = tid & 15;

    float4 ra[4], rb[2];
    const int C = K >> 5;

#pragma unroll
    for (int it = 0; it < 4; ++it)
        ra[it] = *(const float4*)(W + (size_t)(m0 + ar + it * 32) * K + aks * 4);
#pragma unroll
    for (int it = 0; it < 2; ++it)
        rb[it] = *(const float4*)(X + (size_t)(bk + it * 16) * N + n0 + bn4 * 4);

    float acc[2][4][4];
#pragma unroll
    for (int t = 0; t < 2; ++t)
#pragma unroll
        for (int u = 0; u < 4; ++u)
#pragma unroll
            for (int e = 0; e < 4; ++e) acc[t][u][e] = 0.0f;

#pragma unroll
    for (int it = 0; it < 4; ++it) {
        uint32_t* d = As[0] + (ar + it * 32) * 36 + aks * 4;
        d[0] = f2tf32(ra[it].x); d[1] = f2tf32(ra[it].y);
        d[2] = f2tf32(ra[it].z); d[3] = f2tf32(ra[it].w);
    }
#pragma unroll
    for (int it = 0; it < 2; ++it) {
        uint32_t* d = Bs[0] + (bk + it * 16) * 72 + bn4 * 4;
        d[0] = f2tf32(rb[it].x); d[1] = f2tf32(rb[it].y);
        d[2] = f2tf32(rb[it].z); d[3] = f2tf32(rb[it].w);
    }
    __syncthreads();

    for (int c = 0; c < C; ++c) {
        if (c + 1 < C) {
            int k0 = (c + 1) << 5;
#pragma unroll
            for (int it = 0; it < 4; ++it)
                ra[it] = *(const float4*)(W + (size_t)(m0 + ar + it * 32) * K + k0 + aks * 4);
#pragma unroll
            for (int it = 0; it < 2; ++it)
                rb[it] = *(const float4*)(X + (size_t)(k0 + bk + it * 16) * N + n0 + bn4 * 4);
        }

        const uint32_t* Ab = As[c & 1];
        const uint32_t* Bb = Bs[c & 1];
#pragma unroll
        for (int ks = 0; ks < 4; ++ks) {
            uint32_t a[2][4], b[4][2];
#pragma unroll
            for (int t = 0; t < 2; ++t) {
                int rr = wm * 32 + t * 16 + g;
                int kc = ks * 8 + tg;
                a[t][0] = Ab[rr * 36 + kc];
                a[t][1] = Ab[(rr + 8) * 36 + kc];
                a[t][2] = Ab[rr * 36 + kc + 4];
                a[t][3] = Ab[(rr + 8) * 36 + kc + 4];
            }
#pragma unroll
            for (int u = 0; u < 4; ++u) {
                int nn = wn * 32 + u * 8 + g;
                b[u][0] = Bb[(ks * 8 + tg) * 72 + nn];
                b[u][1] = Bb[(ks * 8 + tg + 4) * 72 + nn];
            }
#pragma unroll
            for (int t = 0; t < 2; ++t)
#pragma unroll
                for (int u = 0; u < 4; ++u) mma_tf32(acc[t][u], a[t], b[u]);
        }
        __syncthreads();
        if (c + 1 < C) {
            int nb = (c + 1) & 1;
#pragma unroll
            for (int it = 0; it < 4; ++it) {
                uint32_t* d = As[nb] + (ar + it * 32) * 36 + aks * 4;
                d[0] = f2tf32(ra[it].x); d[1] = f2tf32(ra[it].y);
                d[2] = f2tf32(ra[it].z); d[3] = f2tf32(ra[it].w);
            }
#pragma unroll
            for (int it = 0; it < 2; ++it) {
                uint32_t* d = Bs[nb] + (bk + it * 16) * 72 + bn4 * 4;
                d[0] = f2tf32(rb[it].x); d[1] = f2tf32(rb[it].y);
                d[2] = f2tf32(rb[it].z); d[3] = f2tf32(rb[it].w);
            }
            __syncthreads();
        }
    }

#pragma unroll
    for (int t = 0; t < 2; ++t) {
        int m1 = m0 + wm * 32 + t * 16 + g;
        int m2 = m1 + 8;
        float bv1 = bias[m1], bv2 = bias[m2];
#pragma unroll
        for (int u = 0; u < 4; ++u) {
            int n = n0 + wn * 32 + u * 8 + 2 * tg;
            float v0 = acc[t][u][0] + bv1;
            float v1 = acc[t][u][1] + bv1;
            float v2 = acc[t][u][2] + bv2;
            float v3 = acc[t][u][3] + bv2;
            if (ACT == 2) {
                v0 = 0.5f * v0 * (1.0f + erff(v0 * 0.70710678118654752f));
                v1 = 0.5f * v1 * (1.0f + erff(v1 * 0.70710678118654752f));
                v2 = 0.5f * v2 * (1.0f + erff(v2 * 0.70710678118654752f));
                v3 = 0.5f * v3 * (1.0f + erff(v3 * 0.70710678118654752f));
            }
            size_t gi1 = (size_t)m1 * N + n;
            size_t gi2 = (size_t)m2 * N + n;
            if (HAS_RES) {
                float2 r1 = *(const float2*)(res + gi1);
                float2 r2 = *(const float2*)(res + gi2);
                v0 += r1.x; v1 += r1.y; v2 += r2.x; v3 += r2.y;
            }
            *(float2*)(Y + gi1) = make_float2(v0, v1);
            *(float2*)(Y + gi2) = make_float2(v2, v3);
        }
    }
}

// ---------------------------------------------------------------------------
// LayerNorm (proven R3 version). grid=128, 32 pixels x 8 channel groups.
// ---------------------------------------------------------------------------
__global__ void ln_kernel(const float* __restrict__ x, const float* __restrict__ g,
                          const float* __restrict__ b, const float* __restrict__ pos,
                          const float* __restrict__ pe, float* __restrict__ y) {
    __shared__ float ssum[8][32], ssq[8][32];
    int tid = threadIdx.x;
    int lane = tid & 31, cg = tid >> 5;
    int p = blockIdx.x * 32 + lane;
    const float* xp = x + (size_t)cg * 32 * NPIX + p;
    float v[32];
    float s = 0.0f, q = 0.0f;
#pragma unroll
    for (int i = 0; i < 32; ++i) {
        v[i] = xp[(size_t)i * NPIX];
        s += v[i];
        q = fmaf(v[i], v[i], q);
    }
    ssum[cg][lane] = s;
    ssq[cg][lane] = q;
    __syncthreads();
    float ts = 0.0f, tq = 0.0f;
#pragma unroll
    for (int j = 0; j < 8; ++j) {
        ts += ssum[j][lane];
        tq += ssq[j][lane];
    }
    float mean = ts * (1.0f / DIMC);
    float var = tq * (1.0f / DIMC) - mean * mean;
    float rstd = rsqrtf(var + 1e-5f);
#pragma unroll
    for (int i = 0; i < 32; ++i) {
        int c = cg * 32 + i;
        float o = (v[i] - mean) * rstd * g[c] + b[c];
        if (pos != nullptr) o += pos[c];
        if (pe != nullptr) o += pe[(size_t)c * NPIX + p];
        y[(size_t)c * NPIX + p] = o;
    }
}

// ---------------------------------------------------------------------------
// Flash attention on the tensor pipe (mma.sync m16n8k8 tf32).
// Q/K/V layout [head][d(32)][n(4096)]. CTA = (head, 128-query tile),
// 8 warps x m16 rows. Key tiles of 64.
// Smem (dyn, 52736B as u32): Ks[64][36] ([key][d]), Vs[32][68] ([d][key]),
// Ps[128][68] ([q][key], warp-local; doubles as Q staging pre-loop).
// QK: Q A-frags register-resident; K B-frags conflict-free (4g+tg).
// Softmax in accumulator layout, quad shfl reductions, fexp on FMA pipe.
// PV: P->smem (warp-local, __syncwarp only), V B-frags conflict-free.
// Next K/V tile prefetched to regs before each compute block.
// ---------------------------------------------------------------------------
#define FL_SMEM 52736

__global__ void __launch_bounds__(256, 2)
flash_mma(const float* __restrict__ Q, const float* __restrict__ K,
          const float* __restrict__ V, const float* __restrict__ scale_ptr,
          float* __restrict__ O) {
    extern __shared__ uint32_t fsm[];
    uint32_t* Ks = fsm;                  // [64][36]
    uint32_t* Vs = fsm + 2304;           // [32][68]
    uint32_t* Ps = fsm + 2304 + 2176;    // [128][68]

    int tid = threadIdx.x;
    int wid = tid >> 5, lane = tid & 31;
    int g = lane >> 2, tg = lane & 3;
    int h = blockIdx.y;
    int n0 = blockIdx.x * 128;
    int r0 = wid * 16 + g, r1 = r0 + 8;

    const float* Qh = Q + (size_t)h * 32 * NPIX;
    const float* Kh = K + (size_t)h * 32 * NPIX;
    const float* Vh = V + (size_t)h * 32 * NPIX;
    float inv_scale = 1.0f / scale_ptr[0];

    // ---- stage Q[128][32] (scaled, tf32) into Ps region, grab A-fragments
    uint32_t* Qs = Ps;  // [128][36]
#pragma unroll
    for (int it = 0; it < 4; ++it) {
        int t = tid + it * 256;
        int q4 = t & 31, d = t >> 5;
        float4 qv = *(const float4*)(Qh + (size_t)d * NPIX + n0 + q4 * 4);
        Qs[(q4 * 4 + 0) * 36 + d] = f2tf32(qv.x * inv_scale);
        Qs[(q4 * 4 + 1) * 36 + d] = f2tf32(qv.y * inv_scale);
        Qs[(q4 * 4 + 2) * 36 + d] = f2tf32(qv.z * inv_scale);
        Qs[(q4 * 4 + 3) * 36 + d] = f2tf32(qv.w * inv_scale);
    }
    __syncthreads();
    uint32_t qa[4][4];
#pragma unroll
    for (int ks = 0; ks < 4; ++ks) {
        int kc = ks * 8 + tg;
        qa[ks][0] = Qs[r0 * 36 + kc];
        qa[ks][1] = Qs[r1 * 36 + kc];
        qa[ks][2] = Qs[r0 * 36 + kc + 4];
        qa[ks][3] = Qs[r1 * 36 + kc + 4];
    }
    __syncthreads();  // Ps region free for P use

    // ---- per-thread K/V gmem coords
    int kkey = tid & 63, kds = tid >> 6;      // +4 per iter (2 iters)
    int vd = tid >> 4, vms = tid & 15;        // vd +16 on iter 1

    float kr[2][4];
    float4 vr[2];
    // prefetch tile 0
#pragma unroll
    for (int i = 0; i < 2; ++i) {
        int ds = kds + i * 4;
#pragma unroll
        for (int j = 0; j < 4; ++j)
            kr[i][j] = Kh[(size_t)(ds * 4 + j) * NPIX + kkey];
        vr[i] = *(const float4*)(Vh + (size_t)(vd + i * 16) * NPIX + vms * 4);
    }

    float m0s = -1e30f, m1s = -1e30f, l0 = 0.0f, l1 = 0.0f;
    float oa[4][4];
#pragma unroll
    for (int u = 0; u < 4; ++u)
#pragma unroll
        for (int e = 0; e < 4; ++e) oa[u][e] = 0.0f;

    for (int kt = 0; kt < 64; ++kt) {
        __syncthreads();  // everyone done reading Ks/Vs of prev tile
#pragma unroll
        for (int i = 0; i < 2; ++i) {
            int ds = kds + i * 4;
            uint4 t4;
            t4.x = f2tf32(kr[i][0]); t4.y = f2tf32(kr[i][1]);
            t4.z = f2tf32(kr[i][2]); t4.w = f2tf32(kr[i][3]);
            *(uint4*)(Ks + kkey * 36 + ds * 4) = t4;
            uint4 v4;
            v4.x = f2tf32(vr[i].x); v4.y = f2tf32(vr[i].y);
            v4.z = f2tf32(vr[i].z); v4.w = f2tf32(vr[i].w);
            *(uint4*)(Vs + (vd + i * 16) * 68 + vms * 4) = v4;
        }
        __syncthreads();

        if (kt + 1 < 64) {
            int m1g = (kt + 1) * 64;
#pragma unroll
            for (int i = 0; i < 2; ++i) {
                int ds = kds + i * 4;
#pragma unroll
                for (int j = 0; j < 4; ++j)
                    kr[i][j] = Kh[(size_t)(ds * 4 + j) * NPIX + m1g + kkey];
                vr[i] = *(const float4*)(Vh + (size_t)(vd + i * 16) * NPIX + m1g + vms * 4);
            }
        }

        // ---- scores S = Q K^T  (16q x 64key per warp)
        float sc[8][4];
#pragma unroll
        for (int ns = 0; ns < 8; ++ns)
#pragma unroll
            for (int e = 0; e < 4; ++e) sc[ns][e] = 0.0f;
#pragma unroll
        for (int ks = 0; ks < 4; ++ks) {
            int kc = ks * 8 + tg;
#pragma unroll
            for (int ns = 0; ns < 8; ++ns) {
                uint32_t b[2];
                b[0] = Ks[(ns * 8 + g) * 36 + kc];
                b[1] = Ks[(ns * 8 + g) * 36 + kc + 4];
                mma_tf32(sc[ns], qa[ks], b);
            }
        }

        // ---- online softmax (rows r0, r1; quad = 4 lanes per row)
        float mx0 = -1e30f, mx1 = -1e30f;
#pragma unroll
        for (int ns = 0; ns < 8; ++ns) {
            mx0 = fmaxf(mx0, fmaxf(sc[ns][0], sc[ns][1]));
            mx1 = fmaxf(mx1, fmaxf(sc[ns][2], sc[ns][3]));
        }
        mx0 = fmaxf(mx0, __shfl_xor_sync(0xffffffffu, mx0, 1));
        mx0 = fmaxf(mx0, __shfl_xor_sync(0xffffffffu, mx0, 2));
        mx1 = fmaxf(mx1, __shfl_xor_sync(0xffffffffu, mx1, 1));
        mx1 = fmaxf(mx1, __shfl_xor_sync(0xffffffffu, mx1, 2));
        float mn0 = fmaxf(m0s, mx0), mn1 = fmaxf(m1s, mx1);
        float c0f = fexp(m0s - mn0), c1f = fexp(m1s - mn1);
        float rs0 = 0.0f, rs1 = 0.0f;
#pragma unroll
        for (int ns = 0; ns < 8; ++ns) {
            float p0 = fexp(sc[ns][0] - mn0);
            float p1 = fexp(sc[ns][1] - mn0);
            float p2 = fexp(sc[ns][2] - mn1);
            float p3 = fexp(sc[ns][3] - mn1);
            rs0 += p0 + p1;
            rs1 += p2 + p3;
            int cb = ns * 8 + 2 * tg;
            Ps[r0 * 68 + cb] = f2tf32(p0);
            Ps[r0 * 68 + cb + 1] = f2tf32(p1);
            Ps[r1 * 68 + cb] = f2tf32(p2);
            Ps[r1 * 68 + cb + 1] = f2tf32(p3);
        }
        rs0 += __shfl_xor_sync(0xffffffffu, rs0, 1);
        rs0 += __shfl_xor_sync(0xffffffffu, rs0, 2);
        rs1 += __shfl_xor_sync(0xffffffffu, rs1, 1);
        rs1 += __shfl_xor_sync(0xffffffffu, rs1, 2);
        l0 = l0 * c0f + rs0;
        l1 = l1 * c1f + rs1;
        m0s = mn0; m1s = mn1;
#pragma unroll
        for (int u = 0; u < 4; ++u) {
            oa[u][0] *= c0f; oa[u][1] *= c0f;
            oa[u][2] *= c1f; oa[u][3] *= c1f;
        }
        __syncwarp();  // P is warp-local (rows r0/r1 within warp's 16-row band)

        // ---- O += P V  (16q x 32d per warp, k=64 keys)
#pragma unroll
        for (int ks = 0; ks < 8; ++ks) {
            int kc = ks * 8 + tg;
            uint32_t pa[4];
            pa[0] = Ps[r0 * 68 + kc];
            pa[1] = Ps[r1 * 68 + kc];
            pa[2] = Ps[r0 * 68 + kc + 4];
            pa[3] = Ps[r1 * 68 + kc + 4];
#pragma unroll
            for (int ns = 0; ns < 4; ++ns) {
                uint32_t b[2];
                b[0] = Vs[(ns * 8 + g) * 68 + kc];
                b[1] = Vs[(ns * 8 + g) * 68 + kc + 4];
                mma_tf32(oa[ns], pa, b);
            }
        }
        __syncwarp();  // done reading Ps before next tile overwrites
    }

    float il0 = 1.0f / l0, il1 = 1.0f / l1;
#pragma unroll
    for (int ns = 0; ns < 4; ++ns) {
        int d0 = ns * 8 + 2 * tg;
        O[(size_t)(h * 32 + d0) * NPIX + n0 + r0] = oa[ns][0] * il0;
        O[(size_t)(h * 32 + d0 + 1) * NPIX + n0 + r0] = oa[ns][1] * il0;
        O[(size_t)(h * 32 + d0) * NPIX + n0 + r1] = oa[ns][2] * il1;
        O[(size_t)(h * 32 + d0 + 1) * NPIX + n0 + r1] = oa[ns][3] * il1;
    }
}

// ---------------------------------------------------------------------------
extern "C" void kernel_launch(void* const* d_in, const int* in_sizes, int n_in,
                              void* d_out, int out_size) {
    const float* rgb   = (const float*)d_in[0];
    const float* dpt   = (const float*)d_in[1];
    const float* xdpt  = (const float*)d_in[2];
    const float* wq    = (const float*)d_in[3];
    const float* bq    = (const float*)d_in[4];
    const float* wk    = (const float*)d_in[5];
    const float* bk    = (const float*)d_in[6];
    const float* wv    = (const float*)d_in[7];
    const float* bv    = (const float*)d_in[8];
    const float* wo    = (const float*)d_in[9];
    const float* bo    = (const float*)d_in[10];
    const float* ga_rgb = (const float*)d_in[11];
    const float* be_rgb = (const float*)d_in[12];
    const float* ga_dpt = (const float*)d_in[13];
    const float* be_dpt = (const float*)d_in[14];
    const float* ga1   = (const float*)d_in[15];
    const float* be1   = (const float*)d_in[16];
    const float* ga2   = (const float*)d_in[17];
    const float* be2   = (const float*)d_in[18];
    const float* w_mlp1 = (const float*)d_in[19];
    const float* b_mlp1 = (const float*)d_in[20];
    const float* w_mlp2 = (const float*)d_in[21];
    const float* b_mlp2 = (const float*)d_in[22];
    const float* w_de1 = (const float*)d_in[23];
    const float* b_de1 = (const float*)d_in[24];
    const float* w_de2 = (const float*)d_in[25];
    const float* b_de2 = (const float*)d_in[26];
    const float* pos_emb = (const float*)d_in[27];
    const float* scale = (const float*)d_in[28];
    float* out = (float*)d_out;

    float *p_xd, *p_r1, *p_pe, *p_rgbln, *p_dptln, *p_q, *p_k, *p_v;
    float *p_fused, *p_o, *p_oln, *p_h, *p_o2;
    cudaGetSymbolAddress((void**)&p_xd, g_xd);
    cudaGetSymbolAddress((void**)&p_r1, g_r1);
    cudaGetSymbolAddress((void**)&p_pe, g_pe);
    cudaGetSymbolAddress((void**)&p_rgbln, g_rgbln);
    cudaGetSymbolAddress((void**)&p_dptln, g_dptln);
    cudaGetSymbolAddress((void**)&p_q, g_q);
    cudaGetSymbolAddress((void**)&p_k, g_k);
    cudaGetSymbolAddress((void**)&p_v, g_v);
    cudaGetSymbolAddress((void**)&p_fused, g_fused);
    cudaGetSymbolAddress((void**)&p_o, g_o);
    cudaGetSymbolAddress((void**)&p_oln, g_oln);
    cudaGetSymbolAddress((void**)&p_h, g_h);
    cudaGetSymbolAddress((void**)&p_o2, g_o2);

    static bool attr_done = false;
    if (!attr_done) {
        cudaFuncSetAttribute(gemm_mma<0, 0>, cudaFuncAttributeMaxDynamicSharedMemorySize, GEMM_SMEM);
        cudaFuncSetAttribute(gemm_mma<0, 1>, cudaFuncAttributeMaxDynamicSharedMemorySize, GEMM_SMEM);
        cudaFuncSetAttribute(gemm_mma<2, 0>, cudaFuncAttributeMaxDynamicSharedMemorySize, GEMM_SMEM);
        cudaFuncSetAttribute(flash_mma, cudaFuncAttributeMaxDynamicSharedMemorySize, FL_SMEM);
        attr_done = true;
    }

    // depth positional-embedding path
    downsample_kernel<<<16, 256>>>(xdpt, p_xd);
    conv3_kernel<<<256, 256>>>(p_xd, w_de1, b_de1, p_r1);
    gemm_mma<0, 0><<<dim3(64, 2), 256, GEMM_SMEM>>>(w_de2, p_r1, b_de2, nullptr, p_pe, 256, 256, NPIX);

    // LN(+pos+pe) on both streams
    ln_kernel<<<128, 256>>>(rgb, ga_rgb, be_rgb, pos_emb, p_pe, p_rgbln);
    ln_kernel<<<128, 256>>>(dpt, ga_dpt, be_dpt, pos_emb, p_pe, p_dptln);

    // QKV projections
    gemm_mma<0, 0><<<dim3(64, 2), 256, GEMM_SMEM>>>(wq, p_rgbln, bq, nullptr, p_q, 256, 256, NPIX);
    gemm_mma<0, 0><<<dim3(64, 2), 256, GEMM_SMEM>>>(wk, p_dptln, bk, nullptr, p_k, 256, 256, NPIX);
    gemm_mma<0, 0><<<dim3(64, 2), 256, GEMM_SMEM>>>(wv, p_dptln, bv, nullptr, p_v, 256, 256, NPIX);

    // flash attention on tensor pipe (8 heads x 32 q-tiles of 128)
    flash_mma<<<dim3(32, 8), 256, FL_SMEM>>>(p_q, p_k, p_v, scale, p_fused);

    // output proj + residual, LN
    gemm_mma<0, 1><<<dim3(64, 2), 256, GEMM_SMEM>>>(wo, p_fused, bo, rgb, p_o, 256, 256, NPIX);
    ln_kernel<<<128, 256>>>(p_o, ga1, be1, nullptr, nullptr, p_oln);

    // MLP (exact gelu), residual, final LN -> d_out
    gemm_mma<2, 0><<<dim3(64, 8), 256, GEMM_SMEM>>>(w_mlp1, p_oln, b_mlp1, nullptr, p_h, MLPC, 256, NPIX);
    gemm_mma<0, 1><<<dim3(64, 2), 256, GEMM_SMEM>>>(w_mlp2, p_h, b_mlp2, p_oln, p_o2, 256, MLPC, NPIX);
    ln_kernel<<<128, 256>>>(p_o2, ga2, be2, nullptr, nullptr, out);
}

// round 5
// speedup vs baseline: 7.6453x; 1.5405x over previous
#include <cuda_runtime.h>
#include <cuda_fp16.h>
#include <math.h>
#include <stdint.h>

// ---------------------------------------------------------------------------
// B=1, DIM=256, HEADS=8, HD=32, H=W=64 -> N=4096, MLP=1024
// Layout: [C][N] (NCHW flattened), row stride N=4096 floats.
// ---------------------------------------------------------------------------
#define NPIX 4096
#define DIMC 256
#define MLPC 1024

__device__ float g_xd[NPIX];
__device__ float g_r1[DIMC * NPIX];
__device__ float g_pe[DIMC * NPIX];
__device__ float g_rgbln[DIMC * NPIX];
__device__ float g_dptln[DIMC * NPIX];
__device__ float g_q[DIMC * NPIX];
__device__ float g_k[DIMC * NPIX];
__device__ float g_v[DIMC * NPIX];
__device__ float g_fused[DIMC * NPIX];
__device__ float g_o[DIMC * NPIX];
__device__ float g_oln[DIMC * NPIX];
__device__ float g_h[MLPC * NPIX];
__device__ float g_o2[DIMC * NPIX];

__device__ __forceinline__ uint32_t f2tf32(float x) {
    uint32_t u;
    asm("cvt.rna.tf32.f32 %0, %1;" : "=r"(u) : "f"(x));
    return u;
}
// MUFU exp2 (overlaps with tensor + FMA pipes)
__device__ __forceinline__ float fexp2(float x) {
    float y;
    asm("ex2.approx.f32 %0, %1;" : "=f"(y) : "f"(x));
    return y;
}
__device__ __forceinline__ uint32_t packh2(float a, float b) {
    __half2 h = __floats2half2_rn(a, b);
    return *(uint32_t*)&h;
}

// tf32 m16n8k8 HMMA (validated R3/R4)
__device__ __forceinline__ void mma_tf32(float c[4], const uint32_t a[4], const uint32_t b[2]) {
    asm volatile(
        "mma.sync.aligned.m16n8k8.row.col.f32.tf32.tf32.f32 "
        "{%0,%1,%2,%3}, {%4,%5,%6,%7}, {%8,%9}, {%0,%1,%2,%3};"
        : "+f"(c[0]), "+f"(c[1]), "+f"(c[2]), "+f"(c[3])
        : "r"(a[0]), "r"(a[1]), "r"(a[2]), "r"(a[3]), "r"(b[0]), "r"(b[1]));
}
// fp16 m16n8k16 HMMA, fp32 accum (2x rate, half the LDS traffic)
__device__ __forceinline__ void mma_f16(float c[4], const uint32_t a[4], const uint32_t b[2]) {
    asm volatile(
        "mma.sync.aligned.m16n8k16.row.col.f32.f16.f16.f32 "
        "{%0,%1,%2,%3}, {%4,%5,%6,%7}, {%8,%9}, {%0,%1,%2,%3};"
        : "+f"(c[0]), "+f"(c[1]), "+f"(c[2]), "+f"(c[3])
        : "r"(a[0]), "r"(a[1]), "r"(a[2]), "r"(a[3]), "r"(b[0]), "r"(b[1]));
}

// ---------------------------------------------------------------------------
// Bilinear 16x downsample 1024x1024 -> 64x64 (align_corners=False)
// ---------------------------------------------------------------------------
__global__ void downsample_kernel(const float* __restrict__ x, float* __restrict__ xd) {
    int p = blockIdx.x * 256 + threadIdx.x;
    int i = p >> 6, j = p & 63;
    int base = (16 * i + 7) * 1024 + (16 * j + 7);
    xd[p] = 0.25f * (x[base] + x[base + 1] + x[base + 1024] + x[base + 1025]);
}

// conv3x3 (1 in, 256 out) + bias + relu
__global__ void conv3_kernel(const float* __restrict__ xd, const float* __restrict__ w,
                             const float* __restrict__ bias, float* __restrict__ y) {
    __shared__ float s_xd[NPIX];
    int tid = threadIdx.x;
    int o = blockIdx.x;
    for (int e = tid; e < NPIX; e += 256) s_xd[e] = xd[e];
    __syncthreads();
    float wr[9];
#pragma unroll
    for (int t = 0; t < 9; ++t) wr[t] = w[o * 9 + t];
    float bv = bias[o];
    for (int it = 0; it < 16; ++it) {
        int p = tid + it * 256;
        int i = p >> 6, j = p & 63;
        float acc = bv;
#pragma unroll
        for (int di = 0; di < 3; ++di) {
            int ii = i + di - 1;
            if (ii < 0 || ii > 63) continue;
#pragma unroll
            for (int dj = 0; dj < 3; ++dj) {
                int jj = j + dj - 1;
                if (jj < 0 || jj > 63) continue;
                acc = fmaf(wr[di * 3 + dj], s_xd[ii * 64 + jj], acc);
            }
        }
        y[o * NPIX + p] = fmaxf(acc, 0.0f);
    }
}

// ---------------------------------------------------------------------------
// Tensor-core GEMM body (mma.sync tf32) — proven R3/R4 structure, refactored
// into a device function so QKV can share one launch via blockIdx.z.
// ---------------------------------------------------------------------------
#define GEMM_SMEM 55296

template <int ACT, int HAS_RES>
__device__ __forceinline__ void gemm_body(
    const float* __restrict__ W, const float* __restrict__ X,
    const float* __restrict__ bias, const float* __restrict__ res,
    float* __restrict__ Y, int M, int K, int N, int m0, int n0) {
    extern __shared__ uint32_t sm[];
    uint32_t* As[2] = {sm, sm + 4608};            // 128 x 36
    uint32_t* Bs[2] = {sm + 9216, sm + 11520};    // 32 x 72

    int tid = threadIdx.x;
    int wid = tid >> 5, lane = tid & 31;
    int wm = wid >> 1, wn = wid & 1;
    int g = lane >> 2, tg = lane & 3;

    int ar = tid >> 3;
    int aks = tid & 7;
    int bk = tid >> 4;
    int bn4 = tid & 15;

    float4 ra[4], rb[2];
    const int C = K >> 5;

#pragma unroll
    for (int it = 0; it < 4; ++it)
        ra[it] = *(const float4*)(W + (size_t)(m0 + ar + it * 32) * K + aks * 4);
#pragma unroll
    for (int it = 0; it < 2; ++it)
        rb[it] = *(const float4*)(X + (size_t)(bk + it * 16) * N + n0 + bn4 * 4);

    float acc[2][4][4];
#pragma unroll
    for (int t = 0; t < 2; ++t)
#pragma unroll
        for (int u = 0; u < 4; ++u)
#pragma unroll
            for (int e = 0; e < 4; ++e) acc[t][u][e] = 0.0f;

#pragma unroll
    for (int it = 0; it < 4; ++it) {
        uint32_t* d = As[0] + (ar + it * 32) * 36 + aks * 4;
        d[0] = f2tf32(ra[it].x); d[1] = f2tf32(ra[it].y);
        d[2] = f2tf32(ra[it].z); d[3] = f2tf32(ra[it].w);
    }
#pragma unroll
    for (int it = 0; it < 2; ++it) {
        uint32_t* d = Bs[0] + (bk + it * 16) * 72 + bn4 * 4;
        d[0] = f2tf32(rb[it].x); d[1] = f2tf32(rb[it].y);
        d[2] = f2tf32(rb[it].z); d[3] = f2tf32(rb[it].w);
    }
    __syncthreads();

    for (int c = 0; c < C; ++c) {
        if (c + 1 < C) {
            int k0 = (c + 1) << 5;
#pragma unroll
            for (int it = 0; it < 4; ++it)
                ra[it] = *(const float4*)(W + (size_t)(m0 + ar + it * 32) * K + k0 + aks * 4);
#pragma unroll
            for (int it = 0; it < 2; ++it)
                rb[it] = *(const float4*)(X + (size_t)(k0 + bk + it * 16) * N + n0 + bn4 * 4);
        }

        const uint32_t* Ab = As[c & 1];
        const uint32_t* Bb = Bs[c & 1];
#pragma unroll
        for (int ks = 0; ks < 4; ++ks) {
            uint32_t a[2][4], b[4][2];
#pragma unroll
            for (int t = 0; t < 2; ++t) {
                int rr = wm * 32 + t * 16 + g;
                int kc = ks * 8 + tg;
                a[t][0] = Ab[rr * 36 + kc];
                a[t][1] = Ab[(rr + 8) * 36 + kc];
                a[t][2] = Ab[rr * 36 + kc + 4];
                a[t][3] = Ab[(rr + 8) * 36 + kc + 4];
            }
#pragma unroll
            for (int u = 0; u < 4; ++u) {
                int nn = wn * 32 + u * 8 + g;
                b[u][0] = Bb[(ks * 8 + tg) * 72 + nn];
                b[u][1] = Bb[(ks * 8 + tg + 4) * 72 + nn];
            }
#pragma unroll
            for (int t = 0; t < 2; ++t)
#pragma unroll
                for (int u = 0; u < 4; ++u) mma_tf32(acc[t][u], a[t], b[u]);
        }
        __syncthreads();
        if (c + 1 < C) {
            int nb = (c + 1) & 1;
#pragma unroll
            for (int it = 0; it < 4; ++it) {
                uint32_t* d = As[nb] + (ar + it * 32) * 36 + aks * 4;
                d[0] = f2tf32(ra[it].x); d[1] = f2tf32(ra[it].y);
                d[2] = f2tf32(ra[it].z); d[3] = f2tf32(ra[it].w);
            }
#pragma unroll
            for (int it = 0; it < 2; ++it) {
                uint32_t* d = Bs[nb] + (bk + it * 16) * 72 + bn4 * 4;
                d[0] = f2tf32(rb[it].x); d[1] = f2tf32(rb[it].y);
                d[2] = f2tf32(rb[it].z); d[3] = f2tf32(rb[it].w);
            }
            __syncthreads();
        }
    }

#pragma unroll
    for (int t = 0; t < 2; ++t) {
        int m1 = m0 + wm * 32 + t * 16 + g;
        int m2 = m1 + 8;
        float bv1 = bias[m1], bv2 = bias[m2];
#pragma unroll
        for (int u = 0; u < 4; ++u) {
            int n = n0 + wn * 32 + u * 8 + 2 * tg;
            float v0 = acc[t][u][0] + bv1;
            float v1 = acc[t][u][1] + bv1;
            float v2 = acc[t][u][2] + bv2;
            float v3 = acc[t][u][3] + bv2;
            if (ACT == 2) {
                v0 = 0.5f * v0 * (1.0f + erff(v0 * 0.70710678118654752f));
                v1 = 0.5f * v1 * (1.0f + erff(v1 * 0.70710678118654752f));
                v2 = 0.5f * v2 * (1.0f + erff(v2 * 0.70710678118654752f));
                v3 = 0.5f * v3 * (1.0f + erff(v3 * 0.70710678118654752f));
            }
            size_t gi1 = (size_t)m1 * N + n;
            size_t gi2 = (size_t)m2 * N + n;
            if (HAS_RES) {
                float2 r1 = *(const float2*)(res + gi1);
                float2 r2 = *(const float2*)(res + gi2);
                v0 += r1.x; v1 += r1.y; v2 += r2.x; v3 += r2.y;
            }
            *(float2*)(Y + gi1) = make_float2(v0, v1);
            *(float2*)(Y + gi2) = make_float2(v2, v3);
        }
    }
}

template <int ACT, int HAS_RES>
__global__ void __launch_bounds__(256, 2)
gemm_mma(const float* __restrict__ W, const float* __restrict__ X,
         const float* __restrict__ bias, const float* __restrict__ res,
         float* __restrict__ Y, int M, int K, int N) {
    gemm_body<ACT, HAS_RES>(W, X, bias, res, Y, M, K, N, blockIdx.y * 128, blockIdx.x * 64);
}

// Merged QKV: grid.z selects projection; fills the chip in one wave.
__global__ void __launch_bounds__(256, 2)
gemm_qkv(const float* __restrict__ wq, const float* __restrict__ wk, const float* __restrict__ wv,
         const float* __restrict__ bq, const float* __restrict__ bk, const float* __restrict__ bv,
         const float* __restrict__ xq, const float* __restrict__ xkv,
         float* __restrict__ q, float* __restrict__ k, float* __restrict__ v) {
    int z = blockIdx.z;
    const float* W = (z == 0) ? wq : (z == 1) ? wk : wv;
    const float* B = (z == 0) ? bq : (z == 1) ? bk : bv;
    const float* X = (z == 0) ? xq : xkv;
    float* Y = (z == 0) ? q : (z == 1) ? k : v;
    gemm_body<0, 0>(W, X, B, nullptr, Y, DIMC, DIMC, NPIX, blockIdx.y * 128, blockIdx.x * 64);
}

// ---------------------------------------------------------------------------
// LayerNorm over C=256 per pixel. 256 blocks (16 px x 16 channel-groups of
// 16 ch) -> >148 SMs in flight, values register-resident between passes.
// ---------------------------------------------------------------------------
__global__ void ln_kernel(const float* __restrict__ x, const float* __restrict__ g,
                          const float* __restrict__ b, const float* __restrict__ pos,
                          const float* __restrict__ pe, float* __restrict__ y) {
    __shared__ float ssum[16][16], ssq[16][16];
    int tid = threadIdx.x;
    int px = tid & 15, cg = tid >> 4;
    int p = blockIdx.x * 16 + px;
    const float* xp = x + (size_t)cg * 16 * NPIX + p;
    float v[16];
    float s = 0.0f, q = 0.0f;
#pragma unroll
    for (int i = 0; i < 16; ++i) {
        v[i] = xp[(size_t)i * NPIX];
        s += v[i];
        q = fmaf(v[i], v[i], q);
    }
    ssum[cg][px] = s;
    ssq[cg][px] = q;
    __syncthreads();
    float ts = 0.0f, tq = 0.0f;
#pragma unroll
    for (int j = 0; j < 16; ++j) {
        ts += ssum[j][px];
        tq += ssq[j][px];
    }
    float mean = ts * (1.0f / DIMC);
    float var = tq * (1.0f / DIMC) - mean * mean;
    float rstd = rsqrtf(var + 1e-5f);
#pragma unroll
    for (int i = 0; i < 16; ++i) {
        int c = cg * 16 + i;
        float o = (v[i] - mean) * rstd * g[c] + b[c];
        if (pos != nullptr) o += pos[c];
        if (pe != nullptr) o += pe[(size_t)c * NPIX + p];
        y[(size_t)c * NPIX + p] = o;
    }
}

// ---------------------------------------------------------------------------
// Flash attention, fp16 HMMA m16n8k16 + MUFU exp2 softmax.
// Q/K/V [head][d(32)][n(4096)]. CTA = (head, 128-q tile), 8 warps x m16.
// Key tiles of 64. log2e folded into Q prescale; online max keeps P<=1
// (fp16-safe); P stored as packed half2, one STS per key pair.
// Smem u32: Ks[64][20] ([key][dpair]), Vs[32][36] ([d][keypair]),
// Ps[128][36] ([q][keypair]; doubles as Q staging [128][20]).
// All fragment LDS phases conflict-free (strides 20/36 checked mod 32).
// ---------------------------------------------------------------------------
#define FL_SMEM 28160

__global__ void __launch_bounds__(256, 2)
flash_mma(const float* __restrict__ Q, const float* __restrict__ K,
          const float* __restrict__ V, const float* __restrict__ scale_ptr,
          float* __restrict__ O) {
    extern __shared__ uint32_t fsm[];
    uint32_t* Ks = fsm;               // [64][20]
    uint32_t* Vs = fsm + 1280;        // [32][36]
    uint32_t* Ps = fsm + 1280 + 1152; // [128][36]

    int tid = threadIdx.x;
    int wid = tid >> 5, lane = tid & 31;
    int g = lane >> 2, tg = lane & 3;
    int h = blockIdx.y;
    int n0 = blockIdx.x * 128;
    int r0 = wid * 16 + g, r1 = r0 + 8;

    const float* Qh = Q + (size_t)h * 32 * NPIX;
    const float* Kh = K + (size_t)h * 32 * NPIX;
    const float* Vh = V + (size_t)h * 32 * NPIX;
    // fold 1/scale * log2(e) into Q so softmax is pure exp2
    float qsc = 1.4426950408889634f / scale_ptr[0];

    // ---- stage Q[128][32] as fp16 into Ps region, grab A-fragments
    __half* Qh16 = (__half*)Ps;  // [128][40 halves] (stride 20 u32)
#pragma unroll
    for (int it = 0; it < 4; ++it) {
        int t = tid + it * 256;
        int q4 = t & 31, d = t >> 5;
        float4 qv = *(const float4*)(Qh + (size_t)d * NPIX + n0 + q4 * 4);
        Qh16[(q4 * 4 + 0) * 40 + d] = __float2half(qv.x * qsc);
        Qh16[(q4 * 4 + 1) * 40 + d] = __float2half(qv.y * qsc);
        Qh16[(q4 * 4 + 2) * 40 + d] = __float2half(qv.z * qsc);
        Qh16[(q4 * 4 + 3) * 40 + d] = __float2half(qv.w * qsc);
    }
    __syncthreads();
    uint32_t qa[2][4];
#pragma unroll
    for (int ks = 0; ks < 2; ++ks) {
        int kc = ks * 8 + tg;
        qa[ks][0] = Ps[r0 * 20 + kc];
        qa[ks][1] = Ps[r1 * 20 + kc];
        qa[ks][2] = Ps[r0 * 20 + kc + 4];
        qa[ks][3] = Ps[r1 * 20 + kc + 4];
    }
    __syncthreads();  // Ps region free for P use

    // ---- per-thread K/V gmem coords
    int kkey = tid & 63, kds = tid >> 6;  // K: key, d-slot (4 d per slot)
    int vd = tid >> 4, vms = tid & 15;    // V: d row, key-slot (4 keys)

    float kr[2][4];
    float4 vr[2];
#pragma unroll
    for (int i = 0; i < 2; ++i) {
        int ds = kds + i * 4;
#pragma unroll
        for (int j = 0; j < 4; ++j)
            kr[i][j] = Kh[(size_t)(ds * 4 + j) * NPIX + kkey];
        vr[i] = *(const float4*)(Vh + (size_t)(vd + i * 16) * NPIX + vms * 4);
    }

    float m0s = -1e30f, m1s = -1e30f, l0 = 0.0f, l1 = 0.0f;
    float oa[4][4];
#pragma unroll
    for (int u = 0; u < 4; ++u)
#pragma unroll
        for (int e = 0; e < 4; ++e) oa[u][e] = 0.0f;

    for (int kt = 0; kt < 64; ++kt) {
        __syncthreads();
#pragma unroll
        for (int i = 0; i < 2; ++i) {
            int ds = kds + i * 4;
            Ks[kkey * 20 + ds * 2] = packh2(kr[i][0], kr[i][1]);
            Ks[kkey * 20 + ds * 2 + 1] = packh2(kr[i][2], kr[i][3]);
            Vs[(vd + i * 16) * 36 + vms * 2] = packh2(vr[i].x, vr[i].y);
            Vs[(vd + i * 16) * 36 + vms * 2 + 1] = packh2(vr[i].z, vr[i].w);
        }
        __syncthreads();

        if (kt + 1 < 64) {
            int m1g = (kt + 1) * 64;
#pragma unroll
            for (int i = 0; i < 2; ++i) {
                int ds = kds + i * 4;
#pragma unroll
                for (int j = 0; j < 4; ++j)
                    kr[i][j] = Kh[(size_t)(ds * 4 + j) * NPIX + m1g + kkey];
                vr[i] = *(const float4*)(Vh + (size_t)(vd + i * 16) * NPIX + m1g + vms * 4);
            }
        }

        // ---- scores S = Q K^T (16q x 64key per warp); S already in log2e units
        float sc[8][4];
#pragma unroll
        for (int ns = 0; ns < 8; ++ns)
#pragma unroll
            for (int e = 0; e < 4; ++e) sc[ns][e] = 0.0f;
#pragma unroll
        for (int ks = 0; ks < 2; ++ks) {
            int kc = ks * 8 + tg;
#pragma unroll
            for (int ns = 0; ns < 8; ++ns) {
                uint32_t b[2];
                b[0] = Ks[(ns * 8 + g) * 20 + kc];
                b[1] = Ks[(ns * 8 + g) * 20 + kc + 4];
                mma_f16(sc[ns], qa[ks], b);
            }
        }

        // ---- online softmax (base-2), rows r0/r1, quad reductions
        float mx0 = -1e30f, mx1 = -1e30f;
#pragma unroll
        for (int ns = 0; ns < 8; ++ns) {
            mx0 = fmaxf(mx0, fmaxf(sc[ns][0], sc[ns][1]));
            mx1 = fmaxf(mx1, fmaxf(sc[ns][2], sc[ns][3]));
        }
        mx0 = fmaxf(mx0, __shfl_xor_sync(0xffffffffu, mx0, 1));
        mx0 = fmaxf(mx0, __shfl_xor_sync(0xffffffffu, mx0, 2));
        mx1 = fmaxf(mx1, __shfl_xor_sync(0xffffffffu, mx1, 1));
        mx1 = fmaxf(mx1, __shfl_xor_sync(0xffffffffu, mx1, 2));
        float mn0 = fmaxf(m0s, mx0), mn1 = fmaxf(m1s, mx1);
        float c0f = fexp2(m0s - mn0), c1f = fexp2(m1s - mn1);
        float rs0 = 0.0f, rs1 = 0.0f;
#pragma unroll
        for (int ns = 0; ns < 8; ++ns) {
            float p0 = fexp2(sc[ns][0] - mn0);
            float p1 = fexp2(sc[ns][1] - mn0);
            float p2 = fexp2(sc[ns][2] - mn1);
            float p3 = fexp2(sc[ns][3] - mn1);
            rs0 += p0 + p1;
            rs1 += p2 + p3;
            Ps[r0 * 36 + ns * 4 + tg] = packh2(p0, p1);
            Ps[r1 * 36 + ns * 4 + tg] = packh2(p2, p3);
        }
        rs0 += __shfl_xor_sync(0xffffffffu, rs0, 1);
        rs0 += __shfl_xor_sync(0xffffffffu, rs0, 2);
        rs1 += __shfl_xor_sync(0xffffffffu, rs1, 1);
        rs1 += __shfl_xor_sync(0xffffffffu, rs1, 2);
        l0 = l0 * c0f + rs0;
        l1 = l1 * c1f + rs1;
        m0s = mn0; m1s = mn1;
#pragma unroll
        for (int u = 0; u < 4; ++u) {
            oa[u][0] *= c0f; oa[u][1] *= c0f;
            oa[u][2] *= c1f; oa[u][3] *= c1f;
        }
        __syncwarp();  // P rows r0/r1 are warp-local

        // ---- O += P V (16q x 32d per warp, 64 keys = 4 ksteps of 16)
#pragma unroll
        for (int ks = 0; ks < 4; ++ks) {
            int kc = ks * 8 + tg;
            uint32_t pa[4];
            pa[0] = Ps[r0 * 36 + kc];
            pa[1] = Ps[r1 * 36 + kc];
            pa[2] = Ps[r0 * 36 + kc + 4];
            pa[3] = Ps[r1 * 36 + kc + 4];
#pragma unroll
            for (int ns = 0; ns < 4; ++ns) {
                uint32_t b[2];
                b[0] = Vs[(ns * 8 + g) * 36 + kc];
                b[1] = Vs[(ns * 8 + g) * 36 + kc + 4];
                mma_f16(oa[ns], pa, b);
            }
        }
        __syncwarp();
    }

    float il0 = 1.0f / l0, il1 = 1.0f / l1;
#pragma unroll
    for (int ns = 0; ns < 4; ++ns) {
        int d0 = ns * 8 + 2 * tg;
        O[(size_t)(h * 32 + d0) * NPIX + n0 + r0] = oa[ns][0] * il0;
        O[(size_t)(h * 32 + d0 + 1) * NPIX + n0 + r0] = oa[ns][1] * il0;
        O[(size_t)(h * 32 + d0) * NPIX + n0 + r1] = oa[ns][2] * il1;
        O[(size_t)(h * 32 + d0 + 1) * NPIX + n0 + r1] = oa[ns][3] * il1;
    }
}

// ---------------------------------------------------------------------------
extern "C" void kernel_launch(void* const* d_in, const int* in_sizes, int n_in,
                              void* d_out, int out_size) {
    const float* rgb   = (const float*)d_in[0];
    const float* dpt   = (const float*)d_in[1];
    const float* xdpt  = (const float*)d_in[2];
    const float* wq    = (const float*)d_in[3];
    const float* bq    = (const float*)d_in[4];
    const float* wk    = (const float*)d_in[5];
    const float* bk    = (const float*)d_in[6];
    const float* wv    = (const float*)d_in[7];
    const float* bv    = (const float*)d_in[8];
    const float* wo    = (const float*)d_in[9];
    const float* bo    = (const float*)d_in[10];
    const float* ga_rgb = (const float*)d_in[11];
    const float* be_rgb = (const float*)d_in[12];
    const float* ga_dpt = (const float*)d_in[13];
    const float* be_dpt = (const float*)d_in[14];
    const float* ga1   = (const float*)d_in[15];
    const float* be1   = (const float*)d_in[16];
    const float* ga2   = (const float*)d_in[17];
    const float* be2   = (const float*)d_in[18];
    const float* w_mlp1 = (const float*)d_in[19];
    const float* b_mlp1 = (const float*)d_in[20];
    const float* w_mlp2 = (const float*)d_in[21];
    const float* b_mlp2 = (const float*)d_in[22];
    const float* w_de1 = (const float*)d_in[23];
    const float* b_de1 = (const float*)d_in[24];
    const float* w_de2 = (const float*)d_in[25];
    const float* b_de2 = (const float*)d_in[26];
    const float* pos_emb = (const float*)d_in[27];
    const float* scale = (const float*)d_in[28];
    float* out = (float*)d_out;

    float *p_xd, *p_r1, *p_pe, *p_rgbln, *p_dptln, *p_q, *p_k, *p_v;
    float *p_fused, *p_o, *p_oln, *p_h, *p_o2;
    cudaGetSymbolAddress((void**)&p_xd, g_xd);
    cudaGetSymbolAddress((void**)&p_r1, g_r1);
    cudaGetSymbolAddress((void**)&p_pe, g_pe);
    cudaGetSymbolAddress((void**)&p_rgbln, g_rgbln);
    cudaGetSymbolAddress((void**)&p_dptln, g_dptln);
    cudaGetSymbolAddress((void**)&p_q, g_q);
    cudaGetSymbolAddress((void**)&p_k, g_k);
    cudaGetSymbolAddress((void**)&p_v, g_v);
    cudaGetSymbolAddress((void**)&p_fused, g_fused);
    cudaGetSymbolAddress((void**)&p_o, g_o);
    cudaGetSymbolAddress((void**)&p_oln, g_oln);
    cudaGetSymbolAddress((void**)&p_h, g_h);
    cudaGetSymbolAddress((void**)&p_o2, g_o2);

    static bool attr_done = false;
    if (!attr_done) {
        cudaFuncSetAttribute(gemm_mma<0, 0>, cudaFuncAttributeMaxDynamicSharedMemorySize, GEMM_SMEM);
        cudaFuncSetAttribute(gemm_mma<0, 1>, cudaFuncAttributeMaxDynamicSharedMemorySize, GEMM_SMEM);
        cudaFuncSetAttribute(gemm_mma<2, 0>, cudaFuncAttributeMaxDynamicSharedMemorySize, GEMM_SMEM);
        cudaFuncSetAttribute(gemm_qkv, cudaFuncAttributeMaxDynamicSharedMemorySize, GEMM_SMEM);
        cudaFuncSetAttribute(flash_mma, cudaFuncAttributeMaxDynamicSharedMemorySize, FL_SMEM);
        attr_done = true;
    }

    // depth positional-embedding path
    downsample_kernel<<<16, 256>>>(xdpt, p_xd);
    conv3_kernel<<<256, 256>>>(p_xd, w_de1, b_de1, p_r1);
    gemm_mma<0, 0><<<dim3(64, 2), 256, GEMM_SMEM>>>(w_de2, p_r1, b_de2, nullptr, p_pe, 256, 256, NPIX);

    // LN(+pos+pe) on both streams
    ln_kernel<<<256, 256>>>(rgb, ga_rgb, be_rgb, pos_emb, p_pe, p_rgbln);
    ln_kernel<<<256, 256>>>(dpt, ga_dpt, be_dpt, pos_emb, p_pe, p_dptln);

    // QKV projections — one launch, full chip
    gemm_qkv<<<dim3(64, 2, 3), 256, GEMM_SMEM>>>(wq, wk, wv, bq, bk, bv,
                                                 p_rgbln, p_dptln, p_q, p_k, p_v);

    // flash attention (fp16 HMMA, 8 heads x 32 q-tiles of 128)
    flash_mma<<<dim3(32, 8), 256, FL_SMEM>>>(p_q, p_k, p_v, scale, p_fused);

    // output proj + residual, LN
    gemm_mma<0, 1><<<dim3(64, 2), 256, GEMM_SMEM>>>(wo, p_fused, bo, rgb, p_o, 256, 256, NPIX);
    ln_kernel<<<256, 256>>>(p_o, ga1, be1, nullptr, nullptr, p_oln);

    // MLP (exact gelu), residual, final LN -> d_out
    gemm_mma<2, 0><<<dim3(64, 8), 256, GEMM_SMEM>>>(w_mlp1, p_oln, b_mlp1, nullptr, p_h, MLPC, 256, NPIX);
    gemm_mma<0, 1><<<dim3(64, 2), 256, GEMM_SMEM>>>(w_mlp2, p_h, b_mlp2, p_oln, p_o2, 256, MLPC, NPIX);
    ln_kernel<<<256, 256>>>(p_o2, ga2, be2, nullptr, nullptr, out);
}

// round 6
// speedup vs baseline: 8.4544x; 1.1058x over previous
#include <cuda_runtime.h>
#include <cuda_fp16.h>
#include <math.h>
#include <stdint.h>

// ---------------------------------------------------------------------------
// B=1, DIM=256, HEADS=8, HD=32, H=W=64 -> N=4096, MLP=1024
// Layout: [C][N] (NCHW flattened), row stride N=4096 floats.
// ---------------------------------------------------------------------------
#define NPIX 4096
#define DIMC 256
#define MLPC 1024

__device__ float g_xd[NPIX];
__device__ float g_r1[DIMC * NPIX];
__device__ float g_pe[DIMC * NPIX];
__device__ float g_rgbln[DIMC * NPIX];
__device__ float g_dptln[DIMC * NPIX];
__device__ float g_q[DIMC * NPIX];
__device__ float g_k[DIMC * NPIX];
__device__ float g_v[DIMC * NPIX];
__device__ float g_fused[DIMC * NPIX];
__device__ float g_o[DIMC * NPIX];
__device__ float g_oln[DIMC * NPIX];
__device__ float g_h[MLPC * NPIX];
__device__ float g_o2[DIMC * NPIX];

// MUFU exp2 (runs on MUFU pipe, overlaps tensor + FMA)
__device__ __forceinline__ float fexp2(float x) {
    float y;
    asm("ex2.approx.f32 %0, %1;" : "=f"(y) : "f"(x));
    return y;
}
__device__ __forceinline__ uint32_t packh2(float a, float b) {
    __half2 h = __floats2half2_rn(a, b);
    return *(uint32_t*)&h;
}
// fp16 m16n8k16 HMMA, fp32 accum (validated R5 in flash)
__device__ __forceinline__ void mma_f16(float c[4], const uint32_t a[4], const uint32_t b[2]) {
    asm volatile(
        "mma.sync.aligned.m16n8k16.row.col.f32.f16.f16.f32 "
        "{%0,%1,%2,%3}, {%4,%5,%6,%7}, {%8,%9}, {%0,%1,%2,%3};"
        : "+f"(c[0]), "+f"(c[1]), "+f"(c[2]), "+f"(c[3])
        : "r"(a[0]), "r"(a[1]), "r"(a[2]), "r"(a[3]), "r"(b[0]), "r"(b[1]));
}

// ---------------------------------------------------------------------------
// Bilinear 16x downsample 1024x1024 -> 64x64 (align_corners=False)
// ---------------------------------------------------------------------------
__global__ void downsample_kernel(const float* __restrict__ x, float* __restrict__ xd) {
    int p = blockIdx.x * 256 + threadIdx.x;
    int i = p >> 6, j = p & 63;
    int base = (16 * i + 7) * 1024 + (16 * j + 7);
    xd[p] = 0.25f * (x[base] + x[base + 1] + x[base + 1024] + x[base + 1025]);
}

// conv3x3 (1 in, 256 out) + bias + relu
__global__ void conv3_kernel(const float* __restrict__ xd, const float* __restrict__ w,
                             const float* __restrict__ bias, float* __restrict__ y) {
    __shared__ float s_xd[NPIX];
    int tid = threadIdx.x;
    int o = blockIdx.x;
    for (int e = tid; e < NPIX; e += 256) s_xd[e] = xd[e];
    __syncthreads();
    float wr[9];
#pragma unroll
    for (int t = 0; t < 9; ++t) wr[t] = w[o * 9 + t];
    float bv = bias[o];
    for (int it = 0; it < 16; ++it) {
        int p = tid + it * 256;
        int i = p >> 6, j = p & 63;
        float acc = bv;
#pragma unroll
        for (int di = 0; di < 3; ++di) {
            int ii = i + di - 1;
            if (ii < 0 || ii > 63) continue;
#pragma unroll
            for (int dj = 0; dj < 3; ++dj) {
                int jj = j + dj - 1;
                if (jj < 0 || jj > 63) continue;
                acc = fmaf(wr[di * 3 + dj], s_xd[ii * 64 + jj], acc);
            }
        }
        y[o * NPIX + p] = fmaxf(acc, 0.0f);
    }
}

// ---------------------------------------------------------------------------
// Tensor-core GEMM, fp16 m16n8k16, fp32 accum.
// Y[m][n] = act(sum_k W[m][k] X[k][n] + bias[m]) (+ res[m][n])
// CTA tile 128m x 64n, K chunked by 32 (2 ksteps of 16), 8 warps of 32x32.
// Smem u32 (30720B): A[2][128][20] ([m][kpair], flash-Q layout),
//                    B[2][64][20]  ([n][kpair], flash-K layout).
// Both fragment-read patterns (20g+tg mod 32) validated conflict-free in R4/R5.
// Register-prefetch double buffering over K chunks.
// ---------------------------------------------------------------------------
#define GEMM_SMEM 30720

template <int ACT, int HAS_RES>
__device__ __forceinline__ void gemm_body(
    const float* __restrict__ W, const float* __restrict__ X,
    const float* __restrict__ bias, const float* __restrict__ res,
    float* __restrict__ Y, int M, int K, int N, int m0, int n0) {
    extern __shared__ uint32_t sm[];
    uint32_t* As[2] = {sm, sm + 2560};         // [128][20]
    uint32_t* Bs[2] = {sm + 5120, sm + 6400};  // [64][20]

    int tid = threadIdx.x;
    int wid = tid >> 5, lane = tid & 31;
    int wm = wid >> 1, wn = wid & 1;
    int g = lane >> 2, tg = lane & 3;

    // A gmem coords: 4 iters, row ar+32*it, 4 k at aks*4
    int ar = tid >> 3, aks = tid & 7;
    // B gmem coords: n' = bn, 8 consecutive k at bks*8
    int bn = tid & 63, bks = tid >> 6;

    float4 ra[4];
    float br[8];
    const int C = K >> 5;

    // prefetch chunk 0
#pragma unroll
    for (int it = 0; it < 4; ++it)
        ra[it] = *(const float4*)(W + (size_t)(m0 + ar + it * 32) * K + aks * 4);
#pragma unroll
    for (int j = 0; j < 8; ++j)
        br[j] = X[(size_t)(bks * 8 + j) * N + n0 + bn];

    float acc[2][4][4];
#pragma unroll
    for (int t = 0; t < 2; ++t)
#pragma unroll
        for (int u = 0; u < 4; ++u)
#pragma unroll
            for (int e = 0; e < 4; ++e) acc[t][u][e] = 0.0f;

    // store chunk 0
#pragma unroll
    for (int it = 0; it < 4; ++it) {
        uint32_t* d = As[0] + (ar + it * 32) * 20 + aks * 2;
        d[0] = packh2(ra[it].x, ra[it].y);
        d[1] = packh2(ra[it].z, ra[it].w);
    }
#pragma unroll
    for (int j2 = 0; j2 < 4; ++j2)
        Bs[0][bn * 20 + bks * 4 + j2] = packh2(br[2 * j2], br[2 * j2 + 1]);
    __syncthreads();

    for (int c = 0; c < C; ++c) {
        if (c + 1 < C) {
            int k0 = (c + 1) << 5;
#pragma unroll
            for (int it = 0; it < 4; ++it)
                ra[it] = *(const float4*)(W + (size_t)(m0 + ar + it * 32) * K + k0 + aks * 4);
#pragma unroll
            for (int j = 0; j < 8; ++j)
                br[j] = X[(size_t)(k0 + bks * 8 + j) * N + n0 + bn];
        }

        const uint32_t* Ab = As[c & 1];
        const uint32_t* Bb = Bs[c & 1];
#pragma unroll
        for (int ks = 0; ks < 2; ++ks) {
            int kc = ks * 8 + tg;
            uint32_t a[2][4], b[4][2];
#pragma unroll
            for (int t = 0; t < 2; ++t) {
                int rr = wm * 32 + t * 16 + g;
                a[t][0] = Ab[rr * 20 + kc];
                a[t][1] = Ab[(rr + 8) * 20 + kc];
                a[t][2] = Ab[rr * 20 + kc + 4];
                a[t][3] = Ab[(rr + 8) * 20 + kc + 4];
            }
#pragma unroll
            for (int u = 0; u < 4; ++u) {
                int nn = wn * 32 + u * 8 + g;
                b[u][0] = Bb[nn * 20 + kc];
                b[u][1] = Bb[nn * 20 + kc + 4];
            }
#pragma unroll
            for (int t = 0; t < 2; ++t)
#pragma unroll
                for (int u = 0; u < 4; ++u) mma_f16(acc[t][u], a[t], b[u]);
        }
        __syncthreads();
        if (c + 1 < C) {
            int nb = (c + 1) & 1;
#pragma unroll
            for (int it = 0; it < 4; ++it) {
                uint32_t* d = As[nb] + (ar + it * 32) * 20 + aks * 2;
                d[0] = packh2(ra[it].x, ra[it].y);
                d[1] = packh2(ra[it].z, ra[it].w);
            }
#pragma unroll
            for (int j2 = 0; j2 < 4; ++j2)
                Bs[nb][bn * 20 + bks * 4 + j2] = packh2(br[2 * j2], br[2 * j2 + 1]);
            __syncthreads();
        }
    }

    // epilogue: bias/act(/res), float2 stores
#pragma unroll
    for (int t = 0; t < 2; ++t) {
        int m1 = m0 + wm * 32 + t * 16 + g;
        int m2 = m1 + 8;
        float bv1 = bias[m1], bv2 = bias[m2];
#pragma unroll
        for (int u = 0; u < 4; ++u) {
            int n = n0 + wn * 32 + u * 8 + 2 * tg;
            float v0 = acc[t][u][0] + bv1;
            float v1 = acc[t][u][1] + bv1;
            float v2 = acc[t][u][2] + bv2;
            float v3 = acc[t][u][3] + bv2;
            if (ACT == 2) {
                v0 = 0.5f * v0 * (1.0f + erff(v0 * 0.70710678118654752f));
                v1 = 0.5f * v1 * (1.0f + erff(v1 * 0.70710678118654752f));
                v2 = 0.5f * v2 * (1.0f + erff(v2 * 0.70710678118654752f));
                v3 = 0.5f * v3 * (1.0f + erff(v3 * 0.70710678118654752f));
            }
            size_t gi1 = (size_t)m1 * N + n;
            size_t gi2 = (size_t)m2 * N + n;
            if (HAS_RES) {
                float2 r1 = *(const float2*)(res + gi1);
                float2 r2 = *(const float2*)(res + gi2);
                v0 += r1.x; v1 += r1.y; v2 += r2.x; v3 += r2.y;
            }
            *(float2*)(Y + gi1) = make_float2(v0, v1);
            *(float2*)(Y + gi2) = make_float2(v2, v3);
        }
    }
}

template <int ACT, int HAS_RES>
__global__ void __launch_bounds__(256, 2)
gemm_mma(const float* __restrict__ W, const float* __restrict__ X,
         const float* __restrict__ bias, const float* __restrict__ res,
         float* __restrict__ Y, int M, int K, int N) {
    gemm_body<ACT, HAS_RES>(W, X, bias, res, Y, M, K, N, blockIdx.y * 128, blockIdx.x * 64);
}

// Merged QKV: grid.z selects projection; fills the chip in one wave.
__global__ void __launch_bounds__(256, 2)
gemm_qkv(const float* __restrict__ wq, const float* __restrict__ wk, const float* __restrict__ wv,
         const float* __restrict__ bq, const float* __restrict__ bk, const float* __restrict__ bv,
         const float* __restrict__ xq, const float* __restrict__ xkv,
         float* __restrict__ q, float* __restrict__ k, float* __restrict__ v) {
    int z = blockIdx.z;
    const float* W = (z == 0) ? wq : (z == 1) ? wk : wv;
    const float* B = (z == 0) ? bq : (z == 1) ? bk : bv;
    const float* X = (z == 0) ? xq : xkv;
    float* Y = (z == 0) ? q : (z == 1) ? k : v;
    gemm_body<0, 0>(W, X, B, nullptr, Y, DIMC, DIMC, NPIX, blockIdx.y * 128, blockIdx.x * 64);
}

// ---------------------------------------------------------------------------
// LayerNorm over C=256 per pixel. 512 thr = 16 px x 32 channel-groups of 8,
// values register-resident between passes. grid.x=256 (+grid.y stream select
// in the fused rgb/dpt variant).
// ---------------------------------------------------------------------------
__device__ __forceinline__ void ln_body(const float* __restrict__ x, const float* __restrict__ g,
                                        const float* __restrict__ b, const float* __restrict__ pos,
                                        const float* __restrict__ pe, float* __restrict__ y,
                                        float* ssum, float* ssq) {
    int tid = threadIdx.x;
    int px = tid & 15, cg = tid >> 4;
    int p = blockIdx.x * 16 + px;
    const float* xp = x + (size_t)cg * 8 * NPIX + p;
    float v[8];
    float s = 0.0f, q = 0.0f;
#pragma unroll
    for (int i = 0; i < 8; ++i) {
        v[i] = xp[(size_t)i * NPIX];
        s += v[i];
        q = fmaf(v[i], v[i], q);
    }
    ssum[cg * 16 + px] = s;
    ssq[cg * 16 + px] = q;
    __syncthreads();
    float ts = 0.0f, tq = 0.0f;
#pragma unroll
    for (int j = 0; j < 32; ++j) {
        ts += ssum[j * 16 + px];
        tq += ssq[j * 16 + px];
    }
    float mean = ts * (1.0f / DIMC);
    float var = tq * (1.0f / DIMC) - mean * mean;
    float rstd = rsqrtf(var + 1e-5f);
#pragma unroll
    for (int i = 0; i < 8; ++i) {
        int c = cg * 8 + i;
        float o = (v[i] - mean) * rstd * g[c] + b[c];
        if (pos != nullptr) o += pos[c];
        if (pe != nullptr) o += pe[(size_t)c * NPIX + p];
        y[(size_t)c * NPIX + p] = o;
    }
}

__global__ void ln_kernel(const float* __restrict__ x, const float* __restrict__ g,
                          const float* __restrict__ b, const float* __restrict__ pos,
                          const float* __restrict__ pe, float* __restrict__ y) {
    __shared__ float ssum[512], ssq[512];
    ln_body(x, g, b, pos, pe, y, ssum, ssq);
}

// rgb + dpt LN in one launch (grid.y picks the stream)
__global__ void ln2_kernel(const float* __restrict__ x1, const float* __restrict__ g1,
                           const float* __restrict__ b1, const float* __restrict__ x2,
                           const float* __restrict__ g2, const float* __restrict__ b2,
                           const float* __restrict__ pos, const float* __restrict__ pe,
                           float* __restrict__ y1, float* __restrict__ y2) {
    __shared__ float ssum[512], ssq[512];
    if (blockIdx.y == 0) ln_body(x1, g1, b1, pos, pe, y1, ssum, ssq);
    else                 ln_body(x2, g2, b2, pos, pe, y2, ssum, ssq);
}

// ---------------------------------------------------------------------------
// Flash attention, fp16 HMMA m16n8k16 + MUFU exp2 softmax (proven R5).
// ---------------------------------------------------------------------------
#define FL_SMEM 28160

__global__ void __launch_bounds__(256, 2)
flash_mma(const float* __restrict__ Q, const float* __restrict__ K,
          const float* __restrict__ V, const float* __restrict__ scale_ptr,
          float* __restrict__ O) {
    extern __shared__ uint32_t fsm[];
    uint32_t* Ks = fsm;               // [64][20]
    uint32_t* Vs = fsm + 1280;        // [32][36]
    uint32_t* Ps = fsm + 1280 + 1152; // [128][36]

    int tid = threadIdx.x;
    int wid = tid >> 5, lane = tid & 31;
    int g = lane >> 2, tg = lane & 3;
    int h = blockIdx.y;
    int n0 = blockIdx.x * 128;
    int r0 = wid * 16 + g, r1 = r0 + 8;

    const float* Qh = Q + (size_t)h * 32 * NPIX;
    const float* Kh = K + (size_t)h * 32 * NPIX;
    const float* Vh = V + (size_t)h * 32 * NPIX;
    float qsc = 1.4426950408889634f / scale_ptr[0];

    __half* Qh16 = (__half*)Ps;  // [128][40 halves]
#pragma unroll
    for (int it = 0; it < 4; ++it) {
        int t = tid + it * 256;
        int q4 = t & 31, d = t >> 5;
        float4 qv = *(const float4*)(Qh + (size_t)d * NPIX + n0 + q4 * 4);
        Qh16[(q4 * 4 + 0) * 40 + d] = __float2half(qv.x * qsc);
        Qh16[(q4 * 4 + 1) * 40 + d] = __float2half(qv.y * qsc);
        Qh16[(q4 * 4 + 2) * 40 + d] = __float2half(qv.z * qsc);
        Qh16[(q4 * 4 + 3) * 40 + d] = __float2half(qv.w * qsc);
    }
    __syncthreads();
    uint32_t qa[2][4];
#pragma unroll
    for (int ks = 0; ks < 2; ++ks) {
        int kc = ks * 8 + tg;
        qa[ks][0] = Ps[r0 * 20 + kc];
        qa[ks][1] = Ps[r1 * 20 + kc];
        qa[ks][2] = Ps[r0 * 20 + kc + 4];
        qa[ks][3] = Ps[r1 * 20 + kc + 4];
    }
    __syncthreads();

    int kkey = tid & 63, kds = tid >> 6;
    int vd = tid >> 4, vms = tid & 15;

    float kr[2][4];
    float4 vr[2];
#pragma unroll
    for (int i = 0; i < 2; ++i) {
        int ds = kds + i * 4;
#pragma unroll
        for (int j = 0; j < 4; ++j)
            kr[i][j] = Kh[(size_t)(ds * 4 + j) * NPIX + kkey];
        vr[i] = *(const float4*)(Vh + (size_t)(vd + i * 16) * NPIX + vms * 4);
    }

    float m0s = -1e30f, m1s = -1e30f, l0 = 0.0f, l1 = 0.0f;
    float oa[4][4];
#pragma unroll
    for (int u = 0; u < 4; ++u)
#pragma unroll
        for (int e = 0; e < 4; ++e) oa[u][e] = 0.0f;

    for (int kt = 0; kt < 64; ++kt) {
        __syncthreads();
#pragma unroll
        for (int i = 0; i < 2; ++i) {
            int ds = kds + i * 4;
            Ks[kkey * 20 + ds * 2] = packh2(kr[i][0], kr[i][1]);
            Ks[kkey * 20 + ds * 2 + 1] = packh2(kr[i][2], kr[i][3]);
            Vs[(vd + i * 16) * 36 + vms * 2] = packh2(vr[i].x, vr[i].y);
            Vs[(vd + i * 16) * 36 + vms * 2 + 1] = packh2(vr[i].z, vr[i].w);
        }
        __syncthreads();

        if (kt + 1 < 64) {
            int m1g = (kt + 1) * 64;
#pragma unroll
            for (int i = 0; i < 2; ++i) {
                int ds = kds + i * 4;
#pragma unroll
                for (int j = 0; j < 4; ++j)
                    kr[i][j] = Kh[(size_t)(ds * 4 + j) * NPIX + m1g + kkey];
                vr[i] = *(const float4*)(Vh + (size_t)(vd + i * 16) * NPIX + m1g + vms * 4);
            }
        }

        float sc[8][4];
#pragma unroll
        for (int ns = 0; ns < 8; ++ns)
#pragma unroll
            for (int e = 0; e < 4; ++e) sc[ns][e] = 0.0f;
#pragma unroll
        for (int ks = 0; ks < 2; ++ks) {
            int kc = ks * 8 + tg;
#pragma unroll
            for (int ns = 0; ns < 8; ++ns) {
                uint32_t b[2];
                b[0] = Ks[(ns * 8 + g) * 20 + kc];
                b[1] = Ks[(ns * 8 + g) * 20 + kc + 4];
                mma_f16(sc[ns], qa[ks], b);
            }
        }

        float mx0 = -1e30f, mx1 = -1e30f;
#pragma unroll
        for (int ns = 0; ns < 8; ++ns) {
            mx0 = fmaxf(mx0, fmaxf(sc[ns][0], sc[ns][1]));
            mx1 = fmaxf(mx1, fmaxf(sc[ns][2], sc[ns][3]));
        }
        mx0 = fmaxf(mx0, __shfl_xor_sync(0xffffffffu, mx0, 1));
        mx0 = fmaxf(mx0, __shfl_xor_sync(0xffffffffu, mx0, 2));
        mx1 = fmaxf(mx1, __shfl_xor_sync(0xffffffffu, mx1, 1));
        mx1 = fmaxf(mx1, __shfl_xor_sync(0xffffffffu, mx1, 2));
        float mn0 = fmaxf(m0s, mx0), mn1 = fmaxf(m1s, mx1);
        float c0f = fexp2(m0s - mn0), c1f = fexp2(m1s - mn1);
        float rs0 = 0.0f, rs1 = 0.0f;
#pragma unroll
        for (int ns = 0; ns < 8; ++ns) {
            float p0 = fexp2(sc[ns][0] - mn0);
            float p1 = fexp2(sc[ns][1] - mn0);
            float p2 = fexp2(sc[ns][2] - mn1);
            float p3 = fexp2(sc[ns][3] - mn1);
            rs0 += p0 + p1;
            rs1 += p2 + p3;
            Ps[r0 * 36 + ns * 4 + tg] = packh2(p0, p1);
            Ps[r1 * 36 + ns * 4 + tg] = packh2(p2, p3);
        }
        rs0 += __shfl_xor_sync(0xffffffffu, rs0, 1);
        rs0 += __shfl_xor_sync(0xffffffffu, rs0, 2);
        rs1 += __shfl_xor_sync(0xffffffffu, rs1, 1);
        rs1 += __shfl_xor_sync(0xffffffffu, rs1, 2);
        l0 = l0 * c0f + rs0;
        l1 = l1 * c1f + rs1;
        m0s = mn0; m1s = mn1;
#pragma unroll
        for (int u = 0; u < 4; ++u) {
            oa[u][0] *= c0f; oa[u][1] *= c0f;
            oa[u][2] *= c1f; oa[u][3] *= c1f;
        }
        __syncwarp();

#pragma unroll
        for (int ks = 0; ks < 4; ++ks) {
            int kc = ks * 8 + tg;
            uint32_t pa[4];
            pa[0] = Ps[r0 * 36 + kc];
            pa[1] = Ps[r1 * 36 + kc];
            pa[2] = Ps[r0 * 36 + kc + 4];
            pa[3] = Ps[r1 * 36 + kc + 4];
#pragma unroll
            for (int ns = 0; ns < 4; ++ns) {
                uint32_t b[2];
                b[0] = Vs[(ns * 8 + g) * 36 + kc];
                b[1] = Vs[(ns * 8 + g) * 36 + kc + 4];
                mma_f16(oa[ns], pa, b);
            }
        }
        __syncwarp();
    }

    float il0 = 1.0f / l0, il1 = 1.0f / l1;
#pragma unroll
    for (int ns = 0; ns < 4; ++ns) {
        int d0 = ns * 8 + 2 * tg;
        O[(size_t)(h * 32 + d0) * NPIX + n0 + r0] = oa[ns][0] * il0;
        O[(size_t)(h * 32 + d0 + 1) * NPIX + n0 + r0] = oa[ns][1] * il0;
        O[(size_t)(h * 32 + d0) * NPIX + n0 + r1] = oa[ns][2] * il1;
        O[(size_t)(h * 32 + d0 + 1) * NPIX + n0 + r1] = oa[ns][3] * il1;
    }
}

// ---------------------------------------------------------------------------
extern "C" void kernel_launch(void* const* d_in, const int* in_sizes, int n_in,
                              void* d_out, int out_size) {
    const float* rgb   = (const float*)d_in[0];
    const float* dpt   = (const float*)d_in[1];
    const float* xdpt  = (const float*)d_in[2];
    const float* wq    = (const float*)d_in[3];
    const float* bq    = (const float*)d_in[4];
    const float* wk    = (const float*)d_in[5];
    const float* bk    = (const float*)d_in[6];
    const float* wv    = (const float*)d_in[7];
    const float* bv    = (const float*)d_in[8];
    const float* wo    = (const float*)d_in[9];
    const float* bo    = (const float*)d_in[10];
    const float* ga_rgb = (const float*)d_in[11];
    const float* be_rgb = (const float*)d_in[12];
    const float* ga_dpt = (const float*)d_in[13];
    const float* be_dpt = (const float*)d_in[14];
    const float* ga1   = (const float*)d_in[15];
    const float* be1   = (const float*)d_in[16];
    const float* ga2   = (const float*)d_in[17];
    const float* be2   = (const float*)d_in[18];
    const float* w_mlp1 = (const float*)d_in[19];
    const float* b_mlp1 = (const float*)d_in[20];
    const float* w_mlp2 = (const float*)d_in[21];
    const float* b_mlp2 = (const float*)d_in[22];
    const float* w_de1 = (const float*)d_in[23];
    const float* b_de1 = (const float*)d_in[24];
    const float* w_de2 = (const float*)d_in[25];
    const float* b_de2 = (const float*)d_in[26];
    const float* pos_emb = (const float*)d_in[27];
    const float* scale = (const float*)d_in[28];
    float* out = (float*)d_out;

    float *p_xd, *p_r1, *p_pe, *p_rgbln, *p_dptln, *p_q, *p_k, *p_v;
    float *p_fused, *p_o, *p_oln, *p_h, *p_o2;
    cudaGetSymbolAddress((void**)&p_xd, g_xd);
    cudaGetSymbolAddress((void**)&p_r1, g_r1);
    cudaGetSymbolAddress((void**)&p_pe, g_pe);
    cudaGetSymbolAddress((void**)&p_rgbln, g_rgbln);
    cudaGetSymbolAddress((void**)&p_dptln, g_dptln);
    cudaGetSymbolAddress((void**)&p_q, g_q);
    cudaGetSymbolAddress((void**)&p_k, g_k);
    cudaGetSymbolAddress((void**)&p_v, g_v);
    cudaGetSymbolAddress((void**)&p_fused, g_fused);
    cudaGetSymbolAddress((void**)&p_o, g_o);
    cudaGetSymbolAddress((void**)&p_oln, g_oln);
    cudaGetSymbolAddress((void**)&p_h, g_h);
    cudaGetSymbolAddress((void**)&p_o2, g_o2);

    static bool attr_done = false;
    if (!attr_done) {
        cudaFuncSetAttribute(gemm_mma<0, 0>, cudaFuncAttributeMaxDynamicSharedMemorySize, GEMM_SMEM);
        cudaFuncSetAttribute(gemm_mma<0, 1>, cudaFuncAttributeMaxDynamicSharedMemorySize, GEMM_SMEM);
        cudaFuncSetAttribute(gemm_mma<2, 0>, cudaFuncAttributeMaxDynamicSharedMemorySize, GEMM_SMEM);
        cudaFuncSetAttribute(gemm_qkv, cudaFuncAttributeMaxDynamicSharedMemorySize, GEMM_SMEM);
        cudaFuncSetAttribute(flash_mma, cudaFuncAttributeMaxDynamicSharedMemorySize, FL_SMEM);
        attr_done = true;
    }

    // depth positional-embedding path
    downsample_kernel<<<16, 256>>>(xdpt, p_xd);
    conv3_kernel<<<256, 256>>>(p_xd, w_de1, b_de1, p_r1);
    gemm_mma<0, 0><<<dim3(64, 2), 256, GEMM_SMEM>>>(w_de2, p_r1, b_de2, nullptr, p_pe, 256, 256, NPIX);

    // LN(+pos+pe), rgb + dpt in one launch
    ln2_kernel<<<dim3(256, 2), 512>>>(rgb, ga_rgb, be_rgb, dpt, ga_dpt, be_dpt,
                                      pos_emb, p_pe, p_rgbln, p_dptln);

    // QKV projections — one launch, full chip
    gemm_qkv<<<dim3(64, 2, 3), 256, GEMM_SMEM>>>(wq, wk, wv, bq, bk, bv,
                                                 p_rgbln, p_dptln, p_q, p_k, p_v);

    // flash attention (fp16 HMMA, 8 heads x 32 q-tiles of 128)
    flash_mma<<<dim3(32, 8), 256, FL_SMEM>>>(p_q, p_k, p_v, scale, p_fused);

    // output proj + residual, LN
    gemm_mma<0, 1><<<dim3(64, 2), 256, GEMM_SMEM>>>(wo, p_fused, bo, rgb, p_o, 256, 256, NPIX);
    ln_kernel<<<256, 512>>>(p_o, ga1, be1, nullptr, nullptr, p_oln);

    // MLP (exact gelu), residual, final LN -> d_out
    gemm_mma<2, 0><<<dim3(64, 8), 256, GEMM_SMEM>>>(w_mlp1, p_oln, b_mlp1, nullptr, p_h, MLPC, 256, NPIX);
    gemm_mma<0, 1><<<dim3(64, 2), 256, GEMM_SMEM>>>(w_mlp2, p_h, b_mlp2, p_oln, p_o2, 256, MLPC, NPIX);
    ln_kernel<<<256, 512>>>(p_o2, ga2, be2, nullptr, nullptr, out);
}

// round 7
// speedup vs baseline: 8.5252x; 1.0084x over previous
#include <cuda_runtime.h>
#include <cuda_fp16.h>
#include <math.h>
#include <stdint.h>

// ---------------------------------------------------------------------------
// B=1, DIM=256, HEADS=8, HD=32, H=W=64 -> N=4096, MLP=1024
// Layout: [C][N] (NCHW flattened), row stride N=4096.
// ---------------------------------------------------------------------------
#define NPIX 4096
#define DIMC 256
#define MLPC 1024

__device__ float g_xd[NPIX];
__device__ float g_r1[DIMC * NPIX];
__device__ float g_pe[DIMC * NPIX];
__device__ float g_rgbln[DIMC * NPIX];
__device__ float g_dptln[DIMC * NPIX];
__device__ __half g_q16[DIMC * NPIX];
__device__ __half g_k16[DIMC * NPIX];
__device__ __half g_v16[DIMC * NPIX];
__device__ float g_fused[DIMC * NPIX];
__device__ float g_o[DIMC * NPIX];
__device__ float g_oln[DIMC * NPIX];
__device__ float g_h[MLPC * NPIX];
__device__ float g_o2[DIMC * NPIX];

// MUFU exp2 (MUFU pipe; overlaps tensor + FMA)
__device__ __forceinline__ float fexp2(float x) {
    float y;
    asm("ex2.approx.f32 %0, %1;" : "=f"(y) : "f"(x));
    return y;
}
__device__ __forceinline__ uint32_t packh2(float a, float b) {
    __half2 h = __floats2half2_rn(a, b);
    return *(uint32_t*)&h;
}
__device__ __forceinline__ uint32_t packhh(__half a, __half b) {
    __half2 h = __halves2half2(a, b);
    return *(uint32_t*)&h;
}
// fp16 m16n8k16 HMMA, fp32 accum (validated R5/R6)
__device__ __forceinline__ void mma_f16(float c[4], const uint32_t a[4], const uint32_t b[2]) {
    asm volatile(
        "mma.sync.aligned.m16n8k16.row.col.f32.f16.f16.f32 "
        "{%0,%1,%2,%3}, {%4,%5,%6,%7}, {%8,%9}, {%0,%1,%2,%3};"
        : "+f"(c[0]), "+f"(c[1]), "+f"(c[2]), "+f"(c[3])
        : "r"(a[0]), "r"(a[1]), "r"(a[2]), "r"(a[3]), "r"(b[0]), "r"(b[1]));
}

// ---------------------------------------------------------------------------
// Bilinear 16x downsample 1024x1024 -> 64x64 (align_corners=False)
// ---------------------------------------------------------------------------
__global__ void downsample_kernel(const float* __restrict__ x, float* __restrict__ xd) {
    int p = blockIdx.x * 256 + threadIdx.x;
    int i = p >> 6, j = p & 63;
    int base = (16 * i + 7) * 1024 + (16 * j + 7);
    xd[p] = 0.25f * (x[base] + x[base + 1] + x[base + 1024] + x[base + 1025]);
}

// conv3x3 (1 in, 256 out) + bias + relu
__global__ void conv3_kernel(const float* __restrict__ xd, const float* __restrict__ w,
                             const float* __restrict__ bias, float* __restrict__ y) {
    __shared__ float s_xd[NPIX];
    int tid = threadIdx.x;
    int o = blockIdx.x;
    for (int e = tid; e < NPIX; e += 256) s_xd[e] = xd[e];
    __syncthreads();
    float wr[9];
#pragma unroll
    for (int t = 0; t < 9; ++t) wr[t] = w[o * 9 + t];
    float bv = bias[o];
    for (int it = 0; it < 16; ++it) {
        int p = tid + it * 256;
        int i = p >> 6, j = p & 63;
        float acc = bv;
#pragma unroll
        for (int di = 0; di < 3; ++di) {
            int ii = i + di - 1;
            if (ii < 0 || ii > 63) continue;
#pragma unroll
            for (int dj = 0; dj < 3; ++dj) {
                int jj = j + dj - 1;
                if (jj < 0 || jj > 63) continue;
                acc = fmaf(wr[di * 3 + dj], s_xd[ii * 64 + jj], acc);
            }
        }
        y[o * NPIX + p] = fmaxf(acc, 0.0f);
    }
}

// ---------------------------------------------------------------------------
// Tensor-core GEMM, fp16 m16n8k16, fp32 accum (proven R6 structure).
// OUT16: store packed fp16 (half2 along n), optionally scaled by oscale.
// ---------------------------------------------------------------------------
#define GEMM_SMEM 30720

template <int ACT, int HAS_RES, int OUT16>
__device__ __forceinline__ void gemm_body(
    const float* __restrict__ W, const float* __restrict__ X,
    const float* __restrict__ bias, const float* __restrict__ res,
    void* __restrict__ Yv, int M, int K, int N, int m0, int n0, float oscale) {
    extern __shared__ uint32_t sm[];
    uint32_t* As[2] = {sm, sm + 2560};         // [128][20]
    uint32_t* Bs[2] = {sm + 5120, sm + 6400};  // [64][20]

    int tid = threadIdx.x;
    int wid = tid >> 5, lane = tid & 31;
    int wm = wid >> 1, wn = wid & 1;
    int g = lane >> 2, tg = lane & 3;

    int ar = tid >> 3, aks = tid & 7;
    int bn = tid & 63, bks = tid >> 6;

    float4 ra[4];
    float br[8];
    const int C = K >> 5;

#pragma unroll
    for (int it = 0; it < 4; ++it)
        ra[it] = *(const float4*)(W + (size_t)(m0 + ar + it * 32) * K + aks * 4);
#pragma unroll
    for (int j = 0; j < 8; ++j)
        br[j] = X[(size_t)(bks * 8 + j) * N + n0 + bn];

    float acc[2][4][4];
#pragma unroll
    for (int t = 0; t < 2; ++t)
#pragma unroll
        for (int u = 0; u < 4; ++u)
#pragma unroll
            for (int e = 0; e < 4; ++e) acc[t][u][e] = 0.0f;

#pragma unroll
    for (int it = 0; it < 4; ++it) {
        uint32_t* d = As[0] + (ar + it * 32) * 20 + aks * 2;
        d[0] = packh2(ra[it].x, ra[it].y);
        d[1] = packh2(ra[it].z, ra[it].w);
    }
#pragma unroll
    for (int j2 = 0; j2 < 4; ++j2)
        Bs[0][bn * 20 + bks * 4 + j2] = packh2(br[2 * j2], br[2 * j2 + 1]);
    __syncthreads();

    for (int c = 0; c < C; ++c) {
        if (c + 1 < C) {
            int k0 = (c + 1) << 5;
#pragma unroll
            for (int it = 0; it < 4; ++it)
                ra[it] = *(const float4*)(W + (size_t)(m0 + ar + it * 32) * K + k0 + aks * 4);
#pragma unroll
            for (int j = 0; j < 8; ++j)
                br[j] = X[(size_t)(k0 + bks * 8 + j) * N + n0 + bn];
        }

        const uint32_t* Ab = As[c & 1];
        const uint32_t* Bb = Bs[c & 1];
#pragma unroll
        for (int ks = 0; ks < 2; ++ks) {
            int kc = ks * 8 + tg;
            uint32_t a[2][4], b[4][2];
#pragma unroll
            for (int t = 0; t < 2; ++t) {
                int rr = wm * 32 + t * 16 + g;
                a[t][0] = Ab[rr * 20 + kc];
                a[t][1] = Ab[(rr + 8) * 20 + kc];
                a[t][2] = Ab[rr * 20 + kc + 4];
                a[t][3] = Ab[(rr + 8) * 20 + kc + 4];
            }
#pragma unroll
            for (int u = 0; u < 4; ++u) {
                int nn = wn * 32 + u * 8 + g;
                b[u][0] = Bb[nn * 20 + kc];
                b[u][1] = Bb[nn * 20 + kc + 4];
            }
#pragma unroll
            for (int t = 0; t < 2; ++t)
#pragma unroll
                for (int u = 0; u < 4; ++u) mma_f16(acc[t][u], a[t], b[u]);
        }
        __syncthreads();
        if (c + 1 < C) {
            int nb = (c + 1) & 1;
#pragma unroll
            for (int it = 0; it < 4; ++it) {
                uint32_t* d = As[nb] + (ar + it * 32) * 20 + aks * 2;
                d[0] = packh2(ra[it].x, ra[it].y);
                d[1] = packh2(ra[it].z, ra[it].w);
            }
#pragma unroll
            for (int j2 = 0; j2 < 4; ++j2)
                Bs[nb][bn * 20 + bks * 4 + j2] = packh2(br[2 * j2], br[2 * j2 + 1]);
            __syncthreads();
        }
    }

#pragma unroll
    for (int t = 0; t < 2; ++t) {
        int m1 = m0 + wm * 32 + t * 16 + g;
        int m2 = m1 + 8;
        float bv1 = bias[m1], bv2 = bias[m2];
#pragma unroll
        for (int u = 0; u < 4; ++u) {
            int n = n0 + wn * 32 + u * 8 + 2 * tg;
            float v0 = acc[t][u][0] + bv1;
            float v1 = acc[t][u][1] + bv1;
            float v2 = acc[t][u][2] + bv2;
            float v3 = acc[t][u][3] + bv2;
            if (ACT == 2) {
                v0 = 0.5f * v0 * (1.0f + erff(v0 * 0.70710678118654752f));
                v1 = 0.5f * v1 * (1.0f + erff(v1 * 0.70710678118654752f));
                v2 = 0.5f * v2 * (1.0f + erff(v2 * 0.70710678118654752f));
                v3 = 0.5f * v3 * (1.0f + erff(v3 * 0.70710678118654752f));
            }
            if (OUT16) {
                uint32_t* y16 = (uint32_t*)Yv;
                v0 *= oscale; v1 *= oscale; v2 *= oscale; v3 *= oscale;
                y16[(size_t)m1 * (N >> 1) + (n >> 1)] = packh2(v0, v1);
                y16[(size_t)m2 * (N >> 1) + (n >> 1)] = packh2(v2, v3);
            } else {
                float* Y = (float*)Yv;
                size_t gi1 = (size_t)m1 * N + n;
                size_t gi2 = (size_t)m2 * N + n;
                if (HAS_RES) {
                    float2 r1 = *(const float2*)(res + gi1);
                    float2 r2 = *(const float2*)(res + gi2);
                    v0 += r1.x; v1 += r1.y; v2 += r2.x; v3 += r2.y;
                }
                *(float2*)(Y + gi1) = make_float2(v0, v1);
                *(float2*)(Y + gi2) = make_float2(v2, v3);
            }
        }
    }
}

template <int ACT, int HAS_RES>
__global__ void __launch_bounds__(256, 2)
gemm_mma(const float* __restrict__ W, const float* __restrict__ X,
         const float* __restrict__ bias, const float* __restrict__ res,
         float* __restrict__ Y, int M, int K, int N) {
    gemm_body<ACT, HAS_RES, 0>(W, X, bias, res, Y, M, K, N,
                               blockIdx.y * 128, blockIdx.x * 64, 1.0f);
}

// Merged QKV (fp16 packed outputs; q pre-scaled by log2e/scale).
__global__ void __launch_bounds__(256, 2)
gemm_qkv(const float* __restrict__ wq, const float* __restrict__ wk, const float* __restrict__ wv,
         const float* __restrict__ bq, const float* __restrict__ bk, const float* __restrict__ bv,
         const float* __restrict__ xq, const float* __restrict__ xkv,
         __half* __restrict__ q, __half* __restrict__ k, __half* __restrict__ v,
         const float* __restrict__ scale_ptr) {
    int z = blockIdx.z;
    const float* W = (z == 0) ? wq : (z == 1) ? wk : wv;
    const float* B = (z == 0) ? bq : (z == 1) ? bk : bv;
    const float* X = (z == 0) ? xq : xkv;
    __half* Y = (z == 0) ? q : (z == 1) ? k : v;
    float osc = (z == 0) ? (1.4426950408889634f / scale_ptr[0]) : 1.0f;
    gemm_body<0, 0, 1>(W, X, B, nullptr, (void*)Y, DIMC, DIMC, NPIX,
                       blockIdx.y * 128, blockIdx.x * 64, osc);
}

// ---------------------------------------------------------------------------
// LayerNorm: warp = 4 pixels (float4), lane = 8-channel group; shfl-only
// reductions (no smem). 256 thr = 32 px/block; grid.x = 128.
// ---------------------------------------------------------------------------
__device__ __forceinline__ void ln4_body(const float* __restrict__ x, const float* __restrict__ g,
                                         const float* __restrict__ b, const float* __restrict__ pos,
                                         const float* __restrict__ pe, float* __restrict__ y) {
    int tid = threadIdx.x;
    int lane = tid & 31;
    int ps = tid >> 5;
    int p0 = blockIdx.x * 32 + ps * 4;
    const float* xp = x + (size_t)lane * 8 * NPIX + p0;
    float4 v[8];
    float sj[4] = {0, 0, 0, 0}, qj[4] = {0, 0, 0, 0};
#pragma unroll
    for (int i = 0; i < 8; ++i) {
        v[i] = *(const float4*)(xp + (size_t)i * NPIX);
        sj[0] += v[i].x; qj[0] = fmaf(v[i].x, v[i].x, qj[0]);
        sj[1] += v[i].y; qj[1] = fmaf(v[i].y, v[i].y, qj[1]);
        sj[2] += v[i].z; qj[2] = fmaf(v[i].z, v[i].z, qj[2]);
        sj[3] += v[i].w; qj[3] = fmaf(v[i].w, v[i].w, qj[3]);
    }
#pragma unroll
    for (int m = 16; m; m >>= 1) {
#pragma unroll
        for (int j = 0; j < 4; ++j) {
            sj[j] += __shfl_xor_sync(0xffffffffu, sj[j], m);
            qj[j] += __shfl_xor_sync(0xffffffffu, qj[j], m);
        }
    }
    float mean[4], rstd[4];
#pragma unroll
    for (int j = 0; j < 4; ++j) {
        mean[j] = sj[j] * (1.0f / DIMC);
        float var = qj[j] * (1.0f / DIMC) - mean[j] * mean[j];
        rstd[j] = rsqrtf(var + 1e-5f);
    }
#pragma unroll
    for (int i = 0; i < 8; ++i) {
        int c = lane * 8 + i;
        float gg = g[c], bb = b[c];
        float po = (pos != nullptr) ? pos[c] : 0.0f;
        float4 pv = make_float4(0, 0, 0, 0);
        if (pe != nullptr) pv = *(const float4*)(pe + (size_t)c * NPIX + p0);
        float4 o;
        o.x = (v[i].x - mean[0]) * rstd[0] * gg + bb + po + pv.x;
        o.y = (v[i].y - mean[1]) * rstd[1] * gg + bb + po + pv.y;
        o.z = (v[i].z - mean[2]) * rstd[2] * gg + bb + po + pv.z;
        o.w = (v[i].w - mean[3]) * rstd[3] * gg + bb + po + pv.w;
        *(float4*)(y + (size_t)c * NPIX + p0) = o;
    }
}

__global__ void ln4_kernel(const float* __restrict__ x, const float* __restrict__ g,
                           const float* __restrict__ b, const float* __restrict__ pos,
                           const float* __restrict__ pe, float* __restrict__ y) {
    ln4_body(x, g, b, pos, pe, y);
}

__global__ void ln4_2_kernel(const float* __restrict__ x1, const float* __restrict__ g1,
                             const float* __restrict__ b1, const float* __restrict__ x2,
                             const float* __restrict__ g2, const float* __restrict__ b2,
                             const float* __restrict__ pos, const float* __restrict__ pe,
                             float* __restrict__ y1, float* __restrict__ y2) {
    if (blockIdx.y == 0) ln4_body(x1, g1, b1, pos, pe, y1);
    else                 ln4_body(x2, g2, b2, pos, pe, y2);
}

// ---------------------------------------------------------------------------
// Flash attention, fp16 HMMA + MUFU exp2. Inputs pre-converted fp16 [c][n]
// (q pre-scaled by log2e/scale). Double-buffered K/V smem: ONE syncthreads
// per key tile. V staging is a raw u32 copy (v16 n-pairs == Vs keypairs).
// Smem u32: Ks[2][64][20], Vs[2][32][36], Ps[128][36] (Q staging reuses Ps).
// ---------------------------------------------------------------------------
#define FL_SMEM 37888

__global__ void __launch_bounds__(256, 2)
flash_mma(const __half* __restrict__ Q16, const __half* __restrict__ K16,
          const __half* __restrict__ V16, float* __restrict__ O) {
    extern __shared__ uint32_t fsm[];
    uint32_t* Ks = fsm;               // [2][64][20]
    uint32_t* Vs = fsm + 2560;        // [2][32][36]
    uint32_t* Ps = fsm + 4864;        // [128][36]

    int tid = threadIdx.x;
    int wid = tid >> 5, lane = tid & 31;
    int g = lane >> 2, tg = lane & 3;
    int h = blockIdx.y;
    int n0 = blockIdx.x * 128;
    int r0 = wid * 16 + g, r1 = r0 + 8;

    const __half* Qh = Q16 + (size_t)h * 32 * NPIX;
    const __half* Kh = K16 + (size_t)h * 32 * NPIX;
    const uint32_t* Vhu = (const uint32_t*)(V16 + (size_t)h * 32 * NPIX);

    // per-thread K/V staging coords
    int kkey = tid & 63, kds = tid >> 6;   // K: key row, d-slot (4 d)
    int vd = tid >> 4, vslot = tid & 15;   // V: d row (+16), keypair slot (2 u32)

    // prefetch tile 0
    __half kr[2][4];
    uint2 vr[2];
#pragma unroll
    for (int i = 0; i < 2; ++i) {
        int ds = kds + i * 4;
#pragma unroll
        for (int j = 0; j < 4; ++j)
            kr[i][j] = Kh[(size_t)(ds * 4 + j) * NPIX + kkey];
        vr[i] = *(const uint2*)(Vhu + (size_t)(vd + i * 16) * 2048 + vslot * 2);
    }

    // stage Q[128][32] halves into Ps region ([128][20] u32 rows)
    __half* Qsh = (__half*)Ps;  // stride 40 halves
#pragma unroll
    for (int it = 0; it < 4; ++it) {
        int t = tid + it * 256;
        int q4 = t & 31, d = t >> 5;
        uint2 qv = *(const uint2*)(Qh + (size_t)d * NPIX + n0 + q4 * 4);
        const __half* qp = (const __half*)&qv;
        Qsh[(q4 * 4 + 0) * 40 + d] = qp[0];
        Qsh[(q4 * 4 + 1) * 40 + d] = qp[1];
        Qsh[(q4 * 4 + 2) * 40 + d] = qp[2];
        Qsh[(q4 * 4 + 3) * 40 + d] = qp[3];
    }
    __syncthreads();
    uint32_t qa[2][4];
#pragma unroll
    for (int ks = 0; ks < 2; ++ks) {
        int kc = ks * 8 + tg;
        qa[ks][0] = Ps[r0 * 20 + kc];
        qa[ks][1] = Ps[r1 * 20 + kc];
        qa[ks][2] = Ps[r0 * 20 + kc + 4];
        qa[ks][3] = Ps[r1 * 20 + kc + 4];
    }
    // stage K/V tile 0 into buffer 0 (Ps untouched; q-frags already read)
#pragma unroll
    for (int i = 0; i < 2; ++i) {
        int ds = kds + i * 4;
        *(uint2*)(Ks + kkey * 20 + ds * 2) =
            make_uint2(packhh(kr[i][0], kr[i][1]), packhh(kr[i][2], kr[i][3]));
        *(uint2*)(Vs + (vd + i * 16) * 36 + vslot * 2) = vr[i];
    }
    __syncthreads();

    float m0s = -1e30f, m1s = -1e30f, l0 = 0.0f, l1 = 0.0f;
    float oa[4][4];
#pragma unroll
    for (int u = 0; u < 4; ++u)
#pragma unroll
        for (int e = 0; e < 4; ++e) oa[u][e] = 0.0f;

    for (int kt = 0; kt < 64; ++kt) {
        // prefetch next tile to regs
        if (kt + 1 < 64) {
            int mg = (kt + 1) * 64;
#pragma unroll
            for (int i = 0; i < 2; ++i) {
                int ds = kds + i * 4;
#pragma unroll
                for (int j = 0; j < 4; ++j)
                    kr[i][j] = Kh[(size_t)(ds * 4 + j) * NPIX + mg + kkey];
                vr[i] = *(const uint2*)(Vhu + (size_t)(vd + i * 16) * 2048 + (mg >> 1) + vslot * 2);
            }
        }

        const uint32_t* Ksb = Ks + (kt & 1) * 1280;
        const uint32_t* Vsb = Vs + (kt & 1) * 1152;

        // ---- scores S = Q K^T (16q x 64key per warp), log2e units
        float sc[8][4];
#pragma unroll
        for (int ns = 0; ns < 8; ++ns)
#pragma unroll
            for (int e = 0; e < 4; ++e) sc[ns][e] = 0.0f;
#pragma unroll
        for (int ks = 0; ks < 2; ++ks) {
            int kc = ks * 8 + tg;
#pragma unroll
            for (int ns = 0; ns < 8; ++ns) {
                uint32_t b[2];
                b[0] = Ksb[(ns * 8 + g) * 20 + kc];
                b[1] = Ksb[(ns * 8 + g) * 20 + kc + 4];
                mma_f16(sc[ns], qa[ks], b);
            }
        }

        // ---- online softmax (base-2), rows r0/r1, quad reductions
        float mx0 = -1e30f, mx1 = -1e30f;
#pragma unroll
        for (int ns = 0; ns < 8; ++ns) {
            mx0 = fmaxf(mx0, fmaxf(sc[ns][0], sc[ns][1]));
            mx1 = fmaxf(mx1, fmaxf(sc[ns][2], sc[ns][3]));
        }
        mx0 = fmaxf(mx0, __shfl_xor_sync(0xffffffffu, mx0, 1));
        mx0 = fmaxf(mx0, __shfl_xor_sync(0xffffffffu, mx0, 2));
        mx1 = fmaxf(mx1, __shfl_xor_sync(0xffffffffu, mx1, 1));
        mx1 = fmaxf(mx1, __shfl_xor_sync(0xffffffffu, mx1, 2));
        float mn0 = fmaxf(m0s, mx0), mn1 = fmaxf(m1s, mx1);
        float c0f = fexp2(m0s - mn0), c1f = fexp2(m1s - mn1);
        float rs0 = 0.0f, rs1 = 0.0f;
#pragma unroll
        for (int ns = 0; ns < 8; ++ns) {
            float p0 = fexp2(sc[ns][0] - mn0);
            float p1 = fexp2(sc[ns][1] - mn0);
            float p2 = fexp2(sc[ns][2] - mn1);
            float p3 = fexp2(sc[ns][3] - mn1);
            rs0 += p0 + p1;
            rs1 += p2 + p3;
            Ps[r0 * 36 + ns * 4 + tg] = packh2(p0, p1);
            Ps[r1 * 36 + ns * 4 + tg] = packh2(p2, p3);
        }
        rs0 += __shfl_xor_sync(0xffffffffu, rs0, 1);
        rs0 += __shfl_xor_sync(0xffffffffu, rs0, 2);
        rs1 += __shfl_xor_sync(0xffffffffu, rs1, 1);
        rs1 += __shfl_xor_sync(0xffffffffu, rs1, 2);
        l0 = l0 * c0f + rs0;
        l1 = l1 * c1f + rs1;
        m0s = mn0; m1s = mn1;
#pragma unroll
        for (int u = 0; u < 4; ++u) {
            oa[u][0] *= c0f; oa[u][1] *= c0f;
            oa[u][2] *= c1f; oa[u][3] *= c1f;
        }
        __syncwarp();  // P rows r0/r1 are warp-local

        // ---- O += P V (16q x 32d per warp, 64 keys = 4 ksteps of 16)
#pragma unroll
        for (int ks = 0; ks < 4; ++ks) {
            int kc = ks * 8 + tg;
            uint32_t pa[4];
            pa[0] = Ps[r0 * 36 + kc];
            pa[1] = Ps[r1 * 36 + kc];
            pa[2] = Ps[r0 * 36 + kc + 4];
            pa[3] = Ps[r1 * 36 + kc + 4];
#pragma unroll
            for (int ns = 0; ns < 4; ++ns) {
                uint32_t b[2];
                b[0] = Vsb[(ns * 8 + g) * 36 + kc];
                b[1] = Vsb[(ns * 8 + g) * 36 + kc + 4];
                mma_f16(oa[ns], pa, b);
            }
        }
        __syncwarp();

        // ---- stage next tile into the other buffer, single CTA sync
        if (kt + 1 < 64) {
            uint32_t* Ksn = Ks + ((kt + 1) & 1) * 1280;
            uint32_t* Vsn = Vs + ((kt + 1) & 1) * 1152;
#pragma unroll
            for (int i = 0; i < 2; ++i) {
                int ds = kds + i * 4;
                *(uint2*)(Ksn + kkey * 20 + ds * 2) =
                    make_uint2(packhh(kr[i][0], kr[i][1]), packhh(kr[i][2], kr[i][3]));
                *(uint2*)(Vsn + (vd + i * 16) * 36 + vslot * 2) = vr[i];
            }
            __syncthreads();
        }
    }

    float il0 = 1.0f / l0, il1 = 1.0f / l1;
#pragma unroll
    for (int ns = 0; ns < 4; ++ns) {
        int d0 = ns * 8 + 2 * tg;
        O[(size_t)(h * 32 + d0) * NPIX + n0 + r0] = oa[ns][0] * il0;
        O[(size_t)(h * 32 + d0 + 1) * NPIX + n0 + r0] = oa[ns][1] * il0;
        O[(size_t)(h * 32 + d0) * NPIX + n0 + r1] = oa[ns][2] * il1;
        O[(size_t)(h * 32 + d0 + 1) * NPIX + n0 + r1] = oa[ns][3] * il1;
    }
}

// ---------------------------------------------------------------------------
extern "C" void kernel_launch(void* const* d_in, const int* in_sizes, int n_in,
                              void* d_out, int out_size) {
    const float* rgb   = (const float*)d_in[0];
    const float* dpt   = (const float*)d_in[1];
    const float* xdpt  = (const float*)d_in[2];
    const float* wq    = (const float*)d_in[3];
    const float* bq    = (const float*)d_in[4];
    const float* wk    = (const float*)d_in[5];
    const float* bk    = (const float*)d_in[6];
    const float* wv    = (const float*)d_in[7];
    const float* bv    = (const float*)d_in[8];
    const float* wo    = (const float*)d_in[9];
    const float* bo    = (const float*)d_in[10];
    const float* ga_rgb = (const float*)d_in[11];
    const float* be_rgb = (const float*)d_in[12];
    const float* ga_dpt = (const float*)d_in[13];
    const float* be_dpt = (const float*)d_in[14];
    const float* ga1   = (const float*)d_in[15];
    const float* be1   = (const float*)d_in[16];
    const float* ga2   = (const float*)d_in[17];
    const float* be2   = (const float*)d_in[18];
    const float* w_mlp1 = (const float*)d_in[19];
    const float* b_mlp1 = (const float*)d_in[20];
    const float* w_mlp2 = (const float*)d_in[21];
    const float* b_mlp2 = (const float*)d_in[22];
    const float* w_de1 = (const float*)d_in[23];
    const float* b_de1 = (const float*)d_in[24];
    const float* w_de2 = (const float*)d_in[25];
    const float* b_de2 = (const float*)d_in[26];
    const float* pos_emb = (const float*)d_in[27];
    const float* scale = (const float*)d_in[28];
    float* out = (float*)d_out;

    float *p_xd, *p_r1, *p_pe, *p_rgbln, *p_dptln;
    float *p_fused, *p_o, *p_oln, *p_h, *p_o2;
    __half *p_q16, *p_k16, *p_v16;
    cudaGetSymbolAddress((void**)&p_xd, g_xd);
    cudaGetSymbolAddress((void**)&p_r1, g_r1);
    cudaGetSymbolAddress((void**)&p_pe, g_pe);
    cudaGetSymbolAddress((void**)&p_rgbln, g_rgbln);
    cudaGetSymbolAddress((void**)&p_dptln, g_dptln);
    cudaGetSymbolAddress((void**)&p_q16, g_q16);
    cudaGetSymbolAddress((void**)&p_k16, g_k16);
    cudaGetSymbolAddress((void**)&p_v16, g_v16);
    cudaGetSymbolAddress((void**)&p_fused, g_fused);
    cudaGetSymbolAddress((void**)&p_o, g_o);
    cudaGetSymbolAddress((void**)&p_oln, g_oln);
    cudaGetSymbolAddress((void**)&p_h, g_h);
    cudaGetSymbolAddress((void**)&p_o2, g_o2);

    static bool attr_done = false;
    if (!attr_done) {
        cudaFuncSetAttribute(gemm_mma<0, 0>, cudaFuncAttributeMaxDynamicSharedMemorySize, GEMM_SMEM);
        cudaFuncSetAttribute(gemm_mma<0, 1>, cudaFuncAttributeMaxDynamicSharedMemorySize, GEMM_SMEM);
        cudaFuncSetAttribute(gemm_mma<2, 0>, cudaFuncAttributeMaxDynamicSharedMemorySize, GEMM_SMEM);
        cudaFuncSetAttribute(gemm_qkv, cudaFuncAttributeMaxDynamicSharedMemorySize, GEMM_SMEM);
        cudaFuncSetAttribute(flash_mma, cudaFuncAttributeMaxDynamicSharedMemorySize, FL_SMEM);
        attr_done = true;
    }

    // depth positional-embedding path
    downsample_kernel<<<16, 256>>>(xdpt, p_xd);
    conv3_kernel<<<256, 256>>>(p_xd, w_de1, b_de1, p_r1);
    gemm_mma<0, 0><<<dim3(64, 2), 256, GEMM_SMEM>>>(w_de2, p_r1, b_de2, nullptr, p_pe, 256, 256, NPIX);

    // LN(+pos+pe), rgb + dpt in one launch
    ln4_2_kernel<<<dim3(128, 2), 256>>>(rgb, ga_rgb, be_rgb, dpt, ga_dpt, be_dpt,
                                        pos_emb, p_pe, p_rgbln, p_dptln);

    // QKV projections — one launch, fp16 outputs, q pre-scaled
    gemm_qkv<<<dim3(64, 2, 3), 256, GEMM_SMEM>>>(wq, wk, wv, bq, bk, bv,
                                                 p_rgbln, p_dptln, p_q16, p_k16, p_v16, scale);

    // flash attention (fp16 in, 8 heads x 32 q-tiles of 128)
    flash_mma<<<dim3(32, 8), 256, FL_SMEM>>>(p_q16, p_k16, p_v16, p_fused);

    // output proj + residual, LN
    gemm_mma<0, 1><<<dim3(64, 2), 256, GEMM_SMEM>>>(wo, p_fused, bo, rgb, p_o, 256, 256, NPIX);
    ln4_kernel<<<128, 256>>>(p_o, ga1, be1, nullptr, nullptr, p_oln);

    // MLP (exact gelu), residual, final LN -> d_out
    gemm_mma<2, 0><<<dim3(64, 8), 256, GEMM_SMEM>>>(w_mlp1, p_oln, b_mlp1, nullptr, p_h, MLPC, 256, NPIX);
    gemm_mma<0, 1><<<dim3(64, 2), 256, GEMM_SMEM>>>(w_mlp2, p_h, b_mlp2, p_oln, p_o2, 256, MLPC, NPIX);
    ln4_kernel<<<128, 256>>>(p_o2, ga2, be2, nullptr, nullptr, out);
}

// round 8
// speedup vs baseline: 9.3945x; 1.1020x over previous
#include <cuda_runtime.h>
#include <cuda_fp16.h>
#include <math.h>
#include <stdint.h>

// ---------------------------------------------------------------------------
// B=1, DIM=256, HEADS=8, HD=32, H=W=64 -> N=4096, MLP=1024
// Layout: [C][N] (NCHW flattened), row stride N=4096.
// ---------------------------------------------------------------------------
#define NPIX 4096
#define DIMC 256
#define MLPC 1024

__device__ float g_xd[NPIX];
__device__ float g_r1[DIMC * NPIX];
__device__ float g_rgbln[DIMC * NPIX];
__device__ float g_dptln[DIMC * NPIX];
__device__ __half g_q16[DIMC * NPIX];
__device__ __half g_k16[DIMC * NPIX];
__device__ __half g_v16[DIMC * NPIX];
__device__ float g_fused[DIMC * NPIX];
__device__ float g_oln[DIMC * NPIX];
__device__ float g_h[MLPC * NPIX];

// MUFU exp2 (MUFU pipe; overlaps tensor + FMA)
__device__ __forceinline__ float fexp2(float x) {
    float y;
    asm("ex2.approx.f32 %0, %1;" : "=f"(y) : "f"(x));
    return y;
}
__device__ __forceinline__ uint32_t packh2(float a, float b) {
    __half2 h = __floats2half2_rn(a, b);
    return *(uint32_t*)&h;
}
__device__ __forceinline__ uint32_t packhh(__half a, __half b) {
    __half2 h = __halves2half2(a, b);
    return *(uint32_t*)&h;
}
// fp16 m16n8k16 HMMA, fp32 accum (validated R5-R7)
__device__ __forceinline__ void mma_f16(float c[4], const uint32_t a[4], const uint32_t b[2]) {
    asm volatile(
        "mma.sync.aligned.m16n8k16.row.col.f32.f16.f16.f32 "
        "{%0,%1,%2,%3}, {%4,%5,%6,%7}, {%8,%9}, {%0,%1,%2,%3};"
        : "+f"(c[0]), "+f"(c[1]), "+f"(c[2]), "+f"(c[3])
        : "r"(a[0]), "r"(a[1]), "r"(a[2]), "r"(a[3]), "r"(b[0]), "r"(b[1]));
}

// ---------------------------------------------------------------------------
// Bilinear 16x downsample 1024x1024 -> 64x64 (align_corners=False)
// ---------------------------------------------------------------------------
__global__ void downsample_kernel(const float* __restrict__ x, float* __restrict__ xd) {
    int p = blockIdx.x * 256 + threadIdx.x;
    int i = p >> 6, j = p & 63;
    int base = (16 * i + 7) * 1024 + (16 * j + 7);
    xd[p] = 0.25f * (x[base] + x[base + 1] + x[base + 1024] + x[base + 1025]);
}

// conv3x3 (1 in, 256 out) + bias + relu
__global__ void conv3_kernel(const float* __restrict__ xd, const float* __restrict__ w,
                             const float* __restrict__ bias, float* __restrict__ y) {
    __shared__ float s_xd[NPIX];
    int tid = threadIdx.x;
    int o = blockIdx.x;
    for (int e = tid; e < NPIX; e += 256) s_xd[e] = xd[e];
    __syncthreads();
    float wr[9];
#pragma unroll
    for (int t = 0; t < 9; ++t) wr[t] = w[o * 9 + t];
    float bv = bias[o];
    for (int it = 0; it < 16; ++it) {
        int p = tid + it * 256;
        int i = p >> 6, j = p & 63;
        float acc = bv;
#pragma unroll
        for (int di = 0; di < 3; ++di) {
            int ii = i + di - 1;
            if (ii < 0 || ii > 63) continue;
#pragma unroll
            for (int dj = 0; dj < 3; ++dj) {
                int jj = j + dj - 1;
                if (jj < 0 || jj > 63) continue;
                acc = fmaf(wr[di * 3 + dj], s_xd[ii * 64 + jj], acc);
            }
        }
        y[o * NPIX + p] = fmaxf(acc, 0.0f);
    }
}

// ---------------------------------------------------------------------------
// Full-column GEMM (M=256) + fused LayerNorm epilogue.
// 512 threads = 16 warps x m16, N-tile 32 pixels, grid = 128.
// EPI=1: Y = LN(W X + bias + res) * lng + lnb   (wo+ln1, mlp2+ln2)
// EPI=0: pe = W X + bias stays in smem; write y1=LN(s1x)+pos+pe,
//        y2=LN(s2x)+pos+pe                       (pe-gemm + both input LNs)
// Smem u32 (46080B): A[2][256][20], B[2][32][20]; epilogue reuses as
// Es fp32[256][33] + partial sums. Fragment strides 20 are conflict-free.
// ---------------------------------------------------------------------------
#define GLN_SMEM 46080

template <int EPI>
__global__ void __launch_bounds__(512, 1)
gemm_ln(const float* __restrict__ W, const float* __restrict__ X,
        const float* __restrict__ bias, const float* __restrict__ res,
        const float* __restrict__ lng, const float* __restrict__ lnb,
        float* __restrict__ Y, int K,
        const float* __restrict__ s1x, const float* __restrict__ s1g,
        const float* __restrict__ s1b,
        const float* __restrict__ s2x, const float* __restrict__ s2g,
        const float* __restrict__ s2b,
        const float* __restrict__ pos,
        float* __restrict__ y1, float* __restrict__ y2) {
    extern __shared__ uint32_t sm[];
    uint32_t* As[2] = {sm, sm + 5120};          // [256][20]
    uint32_t* Bs[2] = {sm + 10240, sm + 10880}; // [32][20]

    int tid = threadIdx.x;
    int wid = tid >> 5, lane = tid & 31;
    int g = lane >> 2, tg = lane & 3;
    int wm = wid;  // m band wm*16
    int n0 = blockIdx.x * 32;

    int ar = tid >> 3, aks = tid & 7;  // A: rows ar+64*it, k-slot
    int bn = tid & 31, bj = tid >> 5;  // B: pixel, k-pair 0..15

    const int C = K >> 5;
    float4 ra[4];
    float b0r, b1r;

#pragma unroll
    for (int it = 0; it < 4; ++it)
        ra[it] = *(const float4*)(W + (size_t)(ar + it * 64) * K + aks * 4);
    b0r = X[(size_t)(bj * 2) * NPIX + n0 + bn];
    b1r = X[(size_t)(bj * 2 + 1) * NPIX + n0 + bn];

    float acc[4][4];
#pragma unroll
    for (int u = 0; u < 4; ++u)
#pragma unroll
        for (int e = 0; e < 4; ++e) acc[u][e] = 0.0f;

#pragma unroll
    for (int it = 0; it < 4; ++it) {
        uint32_t* d = As[0] + (ar + it * 64) * 20 + aks * 2;
        d[0] = packh2(ra[it].x, ra[it].y);
        d[1] = packh2(ra[it].z, ra[it].w);
    }
    Bs[0][bn * 20 + bj] = packh2(b0r, b1r);
    __syncthreads();

    for (int c = 0; c < C; ++c) {
        if (c + 1 < C) {
            int k0 = (c + 1) << 5;
#pragma unroll
            for (int it = 0; it < 4; ++it)
                ra[it] = *(const float4*)(W + (size_t)(ar + it * 64) * K + k0 + aks * 4);
            b0r = X[(size_t)(k0 + bj * 2) * NPIX + n0 + bn];
            b1r = X[(size_t)(k0 + bj * 2 + 1) * NPIX + n0 + bn];
        }
        const uint32_t* Ab = As[c & 1];
        const uint32_t* Bb = Bs[c & 1];
#pragma unroll
        for (int ks = 0; ks < 2; ++ks) {
            int kc = ks * 8 + tg;
            uint32_t a[4];
            int rr = wm * 16 + g;
            a[0] = Ab[rr * 20 + kc];
            a[1] = Ab[(rr + 8) * 20 + kc];
            a[2] = Ab[rr * 20 + kc + 4];
            a[3] = Ab[(rr + 8) * 20 + kc + 4];
#pragma unroll
            for (int u = 0; u < 4; ++u) {
                uint32_t b[2];
                int nn = u * 8 + g;
                b[0] = Bb[nn * 20 + kc];
                b[1] = Bb[nn * 20 + kc + 4];
                mma_f16(acc[u], a, b);
            }
        }
        __syncthreads();
        if (c + 1 < C) {
            int nb = (c + 1) & 1;
#pragma unroll
            for (int it = 0; it < 4; ++it) {
                uint32_t* d = As[nb] + (ar + it * 64) * 20 + aks * 2;
                d[0] = packh2(ra[it].x, ra[it].y);
                d[1] = packh2(ra[it].z, ra[it].w);
            }
            Bs[nb][bn * 20 + bj] = packh2(b0r, b1r);
            __syncthreads();
        }
    }

    // epilogue: Es[256][33] fp32 + partials (alias A/B smem; mainloop done)
    float* Es = (float*)sm;
    float* sp = Es + 8448;  // [16][32]
    float* sq = sp + 512;

    {
        int r0 = wm * 16 + g, r1 = r0 + 8;
        float bv0 = bias[r0], bv1 = bias[r1];
#pragma unroll
        for (int u = 0; u < 4; ++u) {
            int n = u * 8 + 2 * tg;
            float v0 = acc[u][0] + bv0, v1 = acc[u][1] + bv0;
            float v2 = acc[u][2] + bv1, v3 = acc[u][3] + bv1;
            if (EPI == 1) {
                size_t gi0 = (size_t)r0 * NPIX + n0 + n;
                size_t gi1 = (size_t)r1 * NPIX + n0 + n;
                float2 q0 = *(const float2*)(res + gi0);
                float2 q1 = *(const float2*)(res + gi1);
                v0 += q0.x; v1 += q0.y; v2 += q1.x; v3 += q1.y;
            }
            Es[r0 * 33 + n] = v0;
            Es[r0 * 33 + n + 1] = v1;
            Es[r1 * 33 + n] = v2;
            Es[r1 * 33 + n + 1] = v3;
        }
    }
    __syncthreads();

    int px = tid & 31, cg = tid >> 5;
    if (EPI == 1) {
        float e[16], s = 0.0f, q = 0.0f;
#pragma unroll
        for (int i = 0; i < 16; ++i) {
            e[i] = Es[(cg * 16 + i) * 33 + px];
            s += e[i];
            q = fmaf(e[i], e[i], q);
        }
        sp[cg * 32 + px] = s;
        sq[cg * 32 + px] = q;
        __syncthreads();
        float ts = 0.0f, tq = 0.0f;
#pragma unroll
        for (int j = 0; j < 16; ++j) {
            ts += sp[j * 32 + px];
            tq += sq[j * 32 + px];
        }
        float mean = ts * (1.0f / DIMC);
        float rstd = rsqrtf(tq * (1.0f / DIMC) - mean * mean + 1e-5f);
#pragma unroll
        for (int i = 0; i < 16; ++i) {
            int cc = cg * 16 + i;
            Y[(size_t)cc * NPIX + n0 + px] = (e[i] - mean) * rstd * lng[cc] + lnb[cc];
        }
    } else {
        // stream 1 (rgb)
        float v[16], s = 0.0f, q = 0.0f;
#pragma unroll
        for (int i = 0; i < 16; ++i) {
            v[i] = s1x[(size_t)(cg * 16 + i) * NPIX + n0 + px];
            s += v[i];
            q = fmaf(v[i], v[i], q);
        }
        sp[cg * 32 + px] = s;
        sq[cg * 32 + px] = q;
        __syncthreads();
        float ts = 0.0f, tq = 0.0f;
#pragma unroll
        for (int j = 0; j < 16; ++j) {
            ts += sp[j * 32 + px];
            tq += sq[j * 32 + px];
        }
        float mean = ts * (1.0f / DIMC);
        float rstd = rsqrtf(tq * (1.0f / DIMC) - mean * mean + 1e-5f);
#pragma unroll
        for (int i = 0; i < 16; ++i) {
            int cc = cg * 16 + i;
            y1[(size_t)cc * NPIX + n0 + px] =
                (v[i] - mean) * rstd * s1g[cc] + s1b[cc] + pos[cc] + Es[cc * 33 + px];
        }
        __syncthreads();
        // stream 2 (dpt)
        s = 0.0f; q = 0.0f;
#pragma unroll
        for (int i = 0; i < 16; ++i) {
            v[i] = s2x[(size_t)(cg * 16 + i) * NPIX + n0 + px];
            s += v[i];
            q = fmaf(v[i], v[i], q);
        }
        sp[cg * 32 + px] = s;
        sq[cg * 32 + px] = q;
        __syncthreads();
        ts = 0.0f; tq = 0.0f;
#pragma unroll
        for (int j = 0; j < 16; ++j) {
            ts += sp[j * 32 + px];
            tq += sq[j * 32 + px];
        }
        mean = ts * (1.0f / DIMC);
        rstd = rsqrtf(tq * (1.0f / DIMC) - mean * mean + 1e-5f);
#pragma unroll
        for (int i = 0; i < 16; ++i) {
            int cc = cg * 16 + i;
            y2[(size_t)cc * NPIX + n0 + px] =
                (v[i] - mean) * rstd * s2g[cc] + s2b[cc] + pos[cc] + Es[cc * 33 + px];
        }
    }
}

// ---------------------------------------------------------------------------
// Tensor-core GEMM fp16 (proven R6/R7 structure) — used for mlp1 (gelu) and
// the merged QKV projection (fp16 packed output, q pre-scaled).
// ---------------------------------------------------------------------------
#define GEMM_SMEM 30720

template <int ACT, int OUT16>
__device__ __forceinline__ void gemm_body(
    const float* __restrict__ W, const float* __restrict__ X,
    const float* __restrict__ bias, void* __restrict__ Yv,
    int M, int K, int N, int m0, int n0, float oscale) {
    extern __shared__ uint32_t sm[];
    uint32_t* As[2] = {sm, sm + 2560};         // [128][20]
    uint32_t* Bs[2] = {sm + 5120, sm + 6400};  // [64][20]

    int tid = threadIdx.x;
    int wid = tid >> 5, lane = tid & 31;
    int wm = wid >> 1, wn = wid & 1;
    int g = lane >> 2, tg = lane & 3;

    int ar = tid >> 3, aks = tid & 7;
    int bn = tid & 63, bks = tid >> 6;

    float4 ra[4];
    float br[8];
    const int C = K >> 5;

#pragma unroll
    for (int it = 0; it < 4; ++it)
        ra[it] = *(const float4*)(W + (size_t)(m0 + ar + it * 32) * K + aks * 4);
#pragma unroll
    for (int j = 0; j < 8; ++j)
        br[j] = X[(size_t)(bks * 8 + j) * N + n0 + bn];

    float acc[2][4][4];
#pragma unroll
    for (int t = 0; t < 2; ++t)
#pragma unroll
        for (int u = 0; u < 4; ++u)
#pragma unroll
            for (int e = 0; e < 4; ++e) acc[t][u][e] = 0.0f;

#pragma unroll
    for (int it = 0; it < 4; ++it) {
        uint32_t* d = As[0] + (ar + it * 32) * 20 + aks * 2;
        d[0] = packh2(ra[it].x, ra[it].y);
        d[1] = packh2(ra[it].z, ra[it].w);
    }
#pragma unroll
    for (int j2 = 0; j2 < 4; ++j2)
        Bs[0][bn * 20 + bks * 4 + j2] = packh2(br[2 * j2], br[2 * j2 + 1]);
    __syncthreads();

    for (int c = 0; c < C; ++c) {
        if (c + 1 < C) {
            int k0 = (c + 1) << 5;
#pragma unroll
            for (int it = 0; it < 4; ++it)
                ra[it] = *(const float4*)(W + (size_t)(m0 + ar + it * 32) * K + k0 + aks * 4);
#pragma unroll
            for (int j = 0; j < 8; ++j)
                br[j] = X[(size_t)(k0 + bks * 8 + j) * N + n0 + bn];
        }

        const uint32_t* Ab = As[c & 1];
        const uint32_t* Bb = Bs[c & 1];
#pragma unroll
        for (int ks = 0; ks < 2; ++ks) {
            int kc = ks * 8 + tg;
            uint32_t a[2][4], b[4][2];
#pragma unroll
            for (int t = 0; t < 2; ++t) {
                int rr = wm * 32 + t * 16 + g;
                a[t][0] = Ab[rr * 20 + kc];
                a[t][1] = Ab[(rr + 8) * 20 + kc];
                a[t][2] = Ab[rr * 20 + kc + 4];
                a[t][3] = Ab[(rr + 8) * 20 + kc + 4];
            }
#pragma unroll
            for (int u = 0; u < 4; ++u) {
                int nn = wn * 32 + u * 8 + g;
                b[u][0] = Bb[nn * 20 + kc];
                b[u][1] = Bb[nn * 20 + kc + 4];
            }
#pragma unroll
            for (int t = 0; t < 2; ++t)
#pragma unroll
                for (int u = 0; u < 4; ++u) mma_f16(acc[t][u], a[t], b[u]);
        }
        __syncthreads();
        if (c + 1 < C) {
            int nb = (c + 1) & 1;
#pragma unroll
            for (int it = 0; it < 4; ++it) {
                uint32_t* d = As[nb] + (ar + it * 32) * 20 + aks * 2;
                d[0] = packh2(ra[it].x, ra[it].y);
                d[1] = packh2(ra[it].z, ra[it].w);
            }
#pragma unroll
            for (int j2 = 0; j2 < 4; ++j2)
                Bs[nb][bn * 20 + bks * 4 + j2] = packh2(br[2 * j2], br[2 * j2 + 1]);
            __syncthreads();
        }
    }

#pragma unroll
    for (int t = 0; t < 2; ++t) {
        int m1 = m0 + wm * 32 + t * 16 + g;
        int m2 = m1 + 8;
        float bv1 = bias[m1], bv2 = bias[m2];
#pragma unroll
        for (int u = 0; u < 4; ++u) {
            int n = n0 + wn * 32 + u * 8 + 2 * tg;
            float v0 = acc[t][u][0] + bv1;
            float v1 = acc[t][u][1] + bv1;
            float v2 = acc[t][u][2] + bv2;
            float v3 = acc[t][u][3] + bv2;
            if (ACT == 2) {
                v0 = 0.5f * v0 * (1.0f + erff(v0 * 0.70710678118654752f));
                v1 = 0.5f * v1 * (1.0f + erff(v1 * 0.70710678118654752f));
                v2 = 0.5f * v2 * (1.0f + erff(v2 * 0.70710678118654752f));
                v3 = 0.5f * v3 * (1.0f + erff(v3 * 0.70710678118654752f));
            }
            if (OUT16) {
                uint32_t* y16 = (uint32_t*)Yv;
                v0 *= oscale; v1 *= oscale; v2 *= oscale; v3 *= oscale;
                y16[(size_t)m1 * (N >> 1) + (n >> 1)] = packh2(v0, v1);
                y16[(size_t)m2 * (N >> 1) + (n >> 1)] = packh2(v2, v3);
            } else {
                float* Y = (float*)Yv;
                *(float2*)(Y + (size_t)m1 * N + n) = make_float2(v0, v1);
                *(float2*)(Y + (size_t)m2 * N + n) = make_float2(v2, v3);
            }
        }
    }
}

template <int ACT>
__global__ void __launch_bounds__(256, 2)
gemm_mma(const float* __restrict__ W, const float* __restrict__ X,
         const float* __restrict__ bias, float* __restrict__ Y,
         int M, int K, int N) {
    gemm_body<ACT, 0>(W, X, bias, Y, M, K, N, blockIdx.y * 128, blockIdx.x * 64, 1.0f);
}

__global__ void __launch_bounds__(256, 2)
gemm_qkv(const float* __restrict__ wq, const float* __restrict__ wk, const float* __restrict__ wv,
         const float* __restrict__ bq, const float* __restrict__ bk, const float* __restrict__ bv,
         const float* __restrict__ xq, const float* __restrict__ xkv,
         __half* __restrict__ q, __half* __restrict__ k, __half* __restrict__ v,
         const float* __restrict__ scale_ptr) {
    int z = blockIdx.z;
    const float* W = (z == 0) ? wq : (z == 1) ? wk : wv;
    const float* B = (z == 0) ? bq : (z == 1) ? bk : bv;
    const float* X = (z == 0) ? xq : xkv;
    __half* Y = (z == 0) ? q : (z == 1) ? k : v;
    float osc = (z == 0) ? (1.4426950408889634f / scale_ptr[0]) : 1.0f;
    gemm_body<0, 1>(W, X, B, (void*)Y, DIMC, DIMC, NPIX,
                    blockIdx.y * 128, blockIdx.x * 64, osc);
}

// ---------------------------------------------------------------------------
// Flash attention, fp16 HMMA + MUFU exp2 (proven R7). Inputs fp16 [c][n],
// q pre-scaled by log2e/scale. Double-buffered K/V, one sync per tile.
// ---------------------------------------------------------------------------
#define FL_SMEM 37888

__global__ void __launch_bounds__(256, 2)
flash_mma(const __half* __restrict__ Q16, const __half* __restrict__ K16,
          const __half* __restrict__ V16, float* __restrict__ O) {
    extern __shared__ uint32_t fsm[];
    uint32_t* Ks = fsm;               // [2][64][20]
    uint32_t* Vs = fsm + 2560;        // [2][32][36]
    uint32_t* Ps = fsm + 4864;        // [128][36]

    int tid = threadIdx.x;
    int wid = tid >> 5, lane = tid & 31;
    int g = lane >> 2, tg = lane & 3;
    int h = blockIdx.y;
    int n0 = blockIdx.x * 128;
    int r0 = wid * 16 + g, r1 = r0 + 8;

    const __half* Qh = Q16 + (size_t)h * 32 * NPIX;
    const __half* Kh = K16 + (size_t)h * 32 * NPIX;
    const uint32_t* Vhu = (const uint32_t*)(V16 + (size_t)h * 32 * NPIX);

    int kkey = tid & 63, kds = tid >> 6;
    int vd = tid >> 4, vslot = tid & 15;

    __half kr[2][4];
    uint2 vr[2];
#pragma unroll
    for (int i = 0; i < 2; ++i) {
        int ds = kds + i * 4;
#pragma unroll
        for (int j = 0; j < 4; ++j)
            kr[i][j] = Kh[(size_t)(ds * 4 + j) * NPIX + kkey];
        vr[i] = *(const uint2*)(Vhu + (size_t)(vd + i * 16) * 2048 + vslot * 2);
    }

    __half* Qsh = (__half*)Ps;
#pragma unroll
    for (int it = 0; it < 4; ++it) {
        int t = tid + it * 256;
        int q4 = t & 31, d = t >> 5;
        uint2 qv = *(const uint2*)(Qh + (size_t)d * NPIX + n0 + q4 * 4);
        const __half* qp = (const __half*)&qv;
        Qsh[(q4 * 4 + 0) * 40 + d] = qp[0];
        Qsh[(q4 * 4 + 1) * 40 + d] = qp[1];
        Qsh[(q4 * 4 + 2) * 40 + d] = qp[2];
        Qsh[(q4 * 4 + 3) * 40 + d] = qp[3];
    }
    __syncthreads();
    uint32_t qa[2][4];
#pragma unroll
    for (int ks = 0; ks < 2; ++ks) {
        int kc = ks * 8 + tg;
        qa[ks][0] = Ps[r0 * 20 + kc];
        qa[ks][1] = Ps[r1 * 20 + kc];
        qa[ks][2] = Ps[r0 * 20 + kc + 4];
        qa[ks][3] = Ps[r1 * 20 + kc + 4];
    }
#pragma unroll
    for (int i = 0; i < 2; ++i) {
        int ds = kds + i * 4;
        *(uint2*)(Ks + kkey * 20 + ds * 2) =
            make_uint2(packhh(kr[i][0], kr[i][1]), packhh(kr[i][2], kr[i][3]));
        *(uint2*)(Vs + (vd + i * 16) * 36 + vslot * 2) = vr[i];
    }
    __syncthreads();

    float m0s = -1e30f, m1s = -1e30f, l0 = 0.0f, l1 = 0.0f;
    float oa[4][4];
#pragma unroll
    for (int u = 0; u < 4; ++u)
#pragma unroll
        for (int e = 0; e < 4; ++e) oa[u][e] = 0.0f;

    for (int kt = 0; kt < 64; ++kt) {
        if (kt + 1 < 64) {
            int mg = (kt + 1) * 64;
#pragma unroll
            for (int i = 0; i < 2; ++i) {
                int ds = kds + i * 4;
#pragma unroll
                for (int j = 0; j < 4; ++j)
                    kr[i][j] = Kh[(size_t)(ds * 4 + j) * NPIX + mg + kkey];
                vr[i] = *(const uint2*)(Vhu + (size_t)(vd + i * 16) * 2048 + (mg >> 1) + vslot * 2);
            }
        }

        const uint32_t* Ksb = Ks + (kt & 1) * 1280;
        const uint32_t* Vsb = Vs + (kt & 1) * 1152;

        float sc[8][4];
#pragma unroll
        for (int ns = 0; ns < 8; ++ns)
#pragma unroll
            for (int e = 0; e < 4; ++e) sc[ns][e] = 0.0f;
#pragma unroll
        for (int ks = 0; ks < 2; ++ks) {
            int kc = ks * 8 + tg;
#pragma unroll
            for (int ns = 0; ns < 8; ++ns) {
                uint32_t b[2];
                b[0] = Ksb[(ns * 8 + g) * 20 + kc];
                b[1] = Ksb[(ns * 8 + g) * 20 + kc + 4];
                mma_f16(sc[ns], qa[ks], b);
            }
        }

        float mx0 = -1e30f, mx1 = -1e30f;
#pragma unroll
        for (int ns = 0; ns < 8; ++ns) {
            mx0 = fmaxf(mx0, fmaxf(sc[ns][0], sc[ns][1]));
            mx1 = fmaxf(mx1, fmaxf(sc[ns][2], sc[ns][3]));
        }
        mx0 = fmaxf(mx0, __shfl_xor_sync(0xffffffffu, mx0, 1));
        mx0 = fmaxf(mx0, __shfl_xor_sync(0xffffffffu, mx0, 2));
        mx1 = fmaxf(mx1, __shfl_xor_sync(0xffffffffu, mx1, 1));
        mx1 = fmaxf(mx1, __shfl_xor_sync(0xffffffffu, mx1, 2));
        float mn0 = fmaxf(m0s, mx0), mn1 = fmaxf(m1s, mx1);
        float c0f = fexp2(m0s - mn0), c1f = fexp2(m1s - mn1);
        float rs0 = 0.0f, rs1 = 0.0f;
#pragma unroll
        for (int ns = 0; ns < 8; ++ns) {
            float p0 = fexp2(sc[ns][0] - mn0);
            float p1 = fexp2(sc[ns][1] - mn0);
            float p2 = fexp2(sc[ns][2] - mn1);
            float p3 = fexp2(sc[ns][3] - mn1);
            rs0 += p0 + p1;
            rs1 += p2 + p3;
            Ps[r0 * 36 + ns * 4 + tg] = packh2(p0, p1);
            Ps[r1 * 36 + ns * 4 + tg] = packh2(p2, p3);
        }
        rs0 += __shfl_xor_sync(0xffffffffu, rs0, 1);
        rs0 += __shfl_xor_sync(0xffffffffu, rs0, 2);
        rs1 += __shfl_xor_sync(0xffffffffu, rs1, 1);
        rs1 += __shfl_xor_sync(0xffffffffu, rs1, 2);
        l0 = l0 * c0f + rs0;
        l1 = l1 * c1f + rs1;
        m0s = mn0; m1s = mn1;
#pragma unroll
        for (int u = 0; u < 4; ++u) {
            oa[u][0] *= c0f; oa[u][1] *= c0f;
            oa[u][2] *= c1f; oa[u][3] *= c1f;
        }
        __syncwarp();

#pragma unroll
        for (int ks = 0; ks < 4; ++ks) {
            int kc = ks * 8 + tg;
            uint32_t pa[4];
            pa[0] = Ps[r0 * 36 + kc];
            pa[1] = Ps[r1 * 36 + kc];
            pa[2] = Ps[r0 * 36 + kc + 4];
            pa[3] = Ps[r1 * 36 + kc + 4];
#pragma unroll
            for (int ns = 0; ns < 4; ++ns) {
                uint32_t b[2];
                b[0] = Vsb[(ns * 8 + g) * 36 + kc];
                b[1] = Vsb[(ns * 8 + g) * 36 + kc + 4];
                mma_f16(oa[ns], pa, b);
            }
        }
        __syncwarp();

        if (kt + 1 < 64) {
            uint32_t* Ksn = Ks + ((kt + 1) & 1) * 1280;
            uint32_t* Vsn = Vs + ((kt + 1) & 1) * 1152;
#pragma unroll
            for (int i = 0; i < 2; ++i) {
                int ds = kds + i * 4;
                *(uint2*)(Ksn + kkey * 20 + ds * 2) =
                    make_uint2(packhh(kr[i][0], kr[i][1]), packhh(kr[i][2], kr[i][3]));
                *(uint2*)(Vsn + (vd + i * 16) * 36 + vslot * 2) = vr[i];
            }
            __syncthreads();
        }
    }

    float il0 = 1.0f / l0, il1 = 1.0f / l1;
#pragma unroll
    for (int ns = 0; ns < 4; ++ns) {
        int d0 = ns * 8 + 2 * tg;
        O[(size_t)(h * 32 + d0) * NPIX + n0 + r0] = oa[ns][0] * il0;
        O[(size_t)(h * 32 + d0 + 1) * NPIX + n0 + r0] = oa[ns][1] * il0;
        O[(size_t)(h * 32 + d0) * NPIX + n0 + r1] = oa[ns][2] * il1;
        O[(size_t)(h * 32 + d0 + 1) * NPIX + n0 + r1] = oa[ns][3] * il1;
    }
}

// ---------------------------------------------------------------------------
extern "C" void kernel_launch(void* const* d_in, const int* in_sizes, int n_in,
                              void* d_out, int out_size) {
    const float* rgb   = (const float*)d_in[0];
    const float* dpt   = (const float*)d_in[1];
    const float* xdpt  = (const float*)d_in[2];
    const float* wq    = (const float*)d_in[3];
    const float* bq    = (const float*)d_in[4];
    const float* wk    = (const float*)d_in[5];
    const float* bk    = (const float*)d_in[6];
    const float* wv    = (const float*)d_in[7];
    const float* bv    = (const float*)d_in[8];
    const float* wo    = (const float*)d_in[9];
    const float* bo    = (const float*)d_in[10];
    const float* ga_rgb = (const float*)d_in[11];
    const float* be_rgb = (const float*)d_in[12];
    const float* ga_dpt = (const float*)d_in[13];
    const float* be_dpt = (const float*)d_in[14];
    const float* ga1   = (const float*)d_in[15];
    const float* be1   = (const float*)d_in[16];
    const float* ga2   = (const float*)d_in[17];
    const float* be2   = (const float*)d_in[18];
    const float* w_mlp1 = (const float*)d_in[19];
    const float* b_mlp1 = (const float*)d_in[20];
    const float* w_mlp2 = (const float*)d_in[21];
    const float* b_mlp2 = (const float*)d_in[22];
    const float* w_de1 = (const float*)d_in[23];
    const float* b_de1 = (const float*)d_in[24];
    const float* w_de2 = (const float*)d_in[25];
    const float* b_de2 = (const float*)d_in[26];
    const float* pos_emb = (const float*)d_in[27];
    const float* scale = (const float*)d_in[28];
    float* out = (float*)d_out;

    float *p_xd, *p_r1, *p_rgbln, *p_dptln, *p_fused, *p_oln, *p_h;
    __half *p_q16, *p_k16, *p_v16;
    cudaGetSymbolAddress((void**)&p_xd, g_xd);
    cudaGetSymbolAddress((void**)&p_r1, g_r1);
    cudaGetSymbolAddress((void**)&p_rgbln, g_rgbln);
    cudaGetSymbolAddress((void**)&p_dptln, g_dptln);
    cudaGetSymbolAddress((void**)&p_q16, g_q16);
    cudaGetSymbolAddress((void**)&p_k16, g_k16);
    cudaGetSymbolAddress((void**)&p_v16, g_v16);
    cudaGetSymbolAddress((void**)&p_fused, g_fused);
    cudaGetSymbolAddress((void**)&p_oln, g_oln);
    cudaGetSymbolAddress((void**)&p_h, g_h);

    static bool attr_done = false;
    if (!attr_done) {
        cudaFuncSetAttribute(gemm_mma<2>, cudaFuncAttributeMaxDynamicSharedMemorySize, GEMM_SMEM);
        cudaFuncSetAttribute(gemm_qkv, cudaFuncAttributeMaxDynamicSharedMemorySize, GEMM_SMEM);
        cudaFuncSetAttribute(gemm_ln<0>, cudaFuncAttributeMaxDynamicSharedMemorySize, GLN_SMEM);
        cudaFuncSetAttribute(gemm_ln<1>, cudaFuncAttributeMaxDynamicSharedMemorySize, GLN_SMEM);
        cudaFuncSetAttribute(flash_mma, cudaFuncAttributeMaxDynamicSharedMemorySize, FL_SMEM);
        attr_done = true;
    }

    // depth positional-embedding path
    downsample_kernel<<<16, 256>>>(xdpt, p_xd);
    conv3_kernel<<<256, 256>>>(p_xd, w_de1, b_de1, p_r1);

    // pe GEMM fused with LN(rgb)+pos+pe and LN(dpt)+pos+pe (pe never hits gmem)
    gemm_ln<0><<<128, 512, GLN_SMEM>>>(w_de2, p_r1, b_de2, nullptr, nullptr, nullptr,
                                       nullptr, DIMC,
                                       rgb, ga_rgb, be_rgb, dpt, ga_dpt, be_dpt,
                                       pos_emb, p_rgbln, p_dptln);

    // QKV projections — one launch, fp16 outputs, q pre-scaled
    gemm_qkv<<<dim3(64, 2, 3), 256, GEMM_SMEM>>>(wq, wk, wv, bq, bk, bv,
                                                 p_rgbln, p_dptln, p_q16, p_k16, p_v16, scale);

    // flash attention (fp16 in, 8 heads x 32 q-tiles of 128)
    flash_mma<<<dim3(32, 8), 256, FL_SMEM>>>(p_q16, p_k16, p_v16, p_fused);

    // output proj + residual + LN1 fused -> oln
    gemm_ln<1><<<128, 512, GLN_SMEM>>>(wo, p_fused, bo, rgb, ga1, be1,
                                       p_oln, DIMC,
                                       nullptr, nullptr, nullptr, nullptr, nullptr,
                                       nullptr, nullptr, nullptr, nullptr);

    // MLP up (exact gelu)
    gemm_mma<2><<<dim3(64, 8), 256, GEMM_SMEM>>>(w_mlp1, p_oln, b_mlp1, p_h, MLPC, 256, NPIX);

    // MLP down + residual + final LN fused -> d_out
    gemm_ln<1><<<128, 512, GLN_SMEM>>>(w_mlp2, p_h, b_mlp2, p_oln, ga2, be2,
                                       out, MLPC,
                                       nullptr, nullptr, nullptr, nullptr, nullptr,
                                       nullptr, nullptr, nullptr, nullptr);
}

// round 9
// speedup vs baseline: 10.8759x; 1.1577x over previous
#include <cuda_runtime.h>
#include <cuda_fp16.h>
#include <math.h>
#include <stdint.h>

// ---------------------------------------------------------------------------
// B=1, DIM=256, HEADS=8, HD=32, H=W=64 -> N=4096, MLP=1024
// Layout: [C][N] (NCHW flattened), row stride N=4096.
// ---------------------------------------------------------------------------
#define NPIX 4096
#define DIMC 256
#define MLPC 1024

__device__ float g_xd[NPIX];
__device__ float g_r1[DIMC * NPIX];
__device__ float g_rgbln[DIMC * NPIX];
__device__ float g_dptln[DIMC * NPIX];
__device__ __half g_q16[DIMC * NPIX];
__device__ __half g_k16[DIMC * NPIX];
__device__ __half g_v16[DIMC * NPIX];
__device__ float g_fused[DIMC * NPIX];
__device__ float g_oln[DIMC * NPIX];
__device__ float g_h[MLPC * NPIX];

// fp16 weight pool (converted once per launch)
#define OFF_DE2 0
#define OFF_Q   65536
#define OFF_K   131072
#define OFF_V   196608
#define OFF_O   262144
#define OFF_M1  327680
#define OFF_M2  589824
__device__ __half g_w16[851968];

__device__ __forceinline__ float fexp2(float x) {
    float y;
    asm("ex2.approx.f32 %0, %1;" : "=f"(y) : "f"(x));
    return y;
}
__device__ __forceinline__ uint32_t packh2(float a, float b) {
    __half2 h = __floats2half2_rn(a, b);
    return *(uint32_t*)&h;
}
__device__ __forceinline__ uint32_t packhh(__half a, __half b) {
    __half2 h = __halves2half2(a, b);
    return *(uint32_t*)&h;
}
__device__ __forceinline__ uint32_t s2u(const void* p) {
    uint32_t a;
    asm("{ .reg .u64 t; cvta.to.shared.u64 t, %1; cvt.u32.u64 %0, t; }" : "=r"(a) : "l"(p));
    return a;
}
__device__ __forceinline__ void mma_f16(float c[4], const uint32_t a[4], const uint32_t b[2]) {
    asm volatile(
        "mma.sync.aligned.m16n8k16.row.col.f32.f16.f16.f32 "
        "{%0,%1,%2,%3}, {%4,%5,%6,%7}, {%8,%9}, {%0,%1,%2,%3};"
        : "+f"(c[0]), "+f"(c[1]), "+f"(c[2]), "+f"(c[3])
        : "r"(a[0]), "r"(a[1]), "r"(a[2]), "r"(a[3]), "r"(b[0]), "r"(b[1]));
}
#define LDSM4(r, addr) \
    asm volatile("ldmatrix.sync.aligned.m8n8.x4.shared.b16 {%0,%1,%2,%3}, [%4];" \
                 : "=r"((r)[0]), "=r"((r)[1]), "=r"((r)[2]), "=r"((r)[3]) : "r"(addr))
#define CP16(d, s) \
    asm volatile("cp.async.cg.shared.global [%0], [%1], 16;" :: "r"(d), "l"(s))
#define CP_COMMIT() asm volatile("cp.async.commit_group;")
#define CP_WAIT0() asm volatile("cp.async.wait_group 0;" ::: "memory")

// ---------------------------------------------------------------------------
// Weight fp32 -> fp16 conversion (once per launch). grid (128, 7).
// ---------------------------------------------------------------------------
__global__ void cvt_weights(const float* __restrict__ de2, const float* __restrict__ q,
                            const float* __restrict__ k, const float* __restrict__ v,
                            const float* __restrict__ o, const float* __restrict__ m1,
                            const float* __restrict__ m2, __half* __restrict__ out) {
    int r = blockIdx.y;
    const float* src;
    __half* dst;
    int n;
    switch (r) {
        case 0: src = de2; dst = out + OFF_DE2; n = 65536; break;
        case 1: src = q;   dst = out + OFF_Q;   n = 65536; break;
        case 2: src = k;   dst = out + OFF_K;   n = 65536; break;
        case 3: src = v;   dst = out + OFF_V;   n = 65536; break;
        case 4: src = o;   dst = out + OFF_O;   n = 65536; break;
        case 5: src = m1;  dst = out + OFF_M1;  n = 262144; break;
        default: src = m2; dst = out + OFF_M2;  n = 262144; break;
    }
    int idx = (blockIdx.x * 256 + threadIdx.x) * 8;
    if (idx >= n) return;
    float4 f0 = *(const float4*)(src + idx);
    float4 f1 = *(const float4*)(src + idx + 4);
    uint4 u;
    u.x = packh2(f0.x, f0.y); u.y = packh2(f0.z, f0.w);
    u.z = packh2(f1.x, f1.y); u.w = packh2(f1.z, f1.w);
    *(uint4*)(dst + idx) = u;
}

// ---------------------------------------------------------------------------
// Bilinear 16x downsample 1024x1024 -> 64x64 (align_corners=False)
// ---------------------------------------------------------------------------
__global__ void downsample_kernel(const float* __restrict__ x, float* __restrict__ xd) {
    int p = blockIdx.x * 256 + threadIdx.x;
    int i = p >> 6, j = p & 63;
    int base = (16 * i + 7) * 1024 + (16 * j + 7);
    xd[p] = 0.25f * (x[base] + x[base + 1] + x[base + 1024] + x[base + 1025]);
}

// conv3x3 (1 in, 256 out) + bias + relu
__global__ void conv3_kernel(const float* __restrict__ xd, const float* __restrict__ w,
                             const float* __restrict__ bias, float* __restrict__ y) {
    __shared__ float s_xd[NPIX];
    int tid = threadIdx.x;
    int o = blockIdx.x;
    for (int e = tid; e < NPIX; e += 256) s_xd[e] = xd[e];
    __syncthreads();
    float wr[9];
#pragma unroll
    for (int t = 0; t < 9; ++t) wr[t] = w[o * 9 + t];
    float bv = bias[o];
    for (int it = 0; it < 16; ++it) {
        int p = tid + it * 256;
        int i = p >> 6, j = p & 63;
        float acc = bv;
#pragma unroll
        for (int di = 0; di < 3; ++di) {
            int ii = i + di - 1;
            if (ii < 0 || ii > 63) continue;
#pragma unroll
            for (int dj = 0; dj < 3; ++dj) {
                int jj = j + dj - 1;
                if (jj < 0 || jj > 63) continue;
                acc = fmaf(wr[di * 3 + dj], s_xd[ii * 64 + jj], acc);
            }
        }
        y[o * NPIX + p] = fmaxf(acc, 0.0f);
    }
}

// ---------------------------------------------------------------------------
// GEMM fp16 m16n8k16 with ldmatrix fragments + cp.async A path.
// W16 [m][k] fp16, X [k][n] fp32. CTA 128m x 64n, K chunks of 32, 8 warps.
// Smem u32: A[2][128][20] (row=80B, k in first 64B), B[2][64][20].
// One __syncthreads per chunk (double-buffered, hazard-analyzed).
// ---------------------------------------------------------------------------
#define GEMM_SMEM 30720

template <int ACT, int OUT16>
__device__ __forceinline__ void gemm_body(
    const __half* __restrict__ W16, const float* __restrict__ X,
    const float* __restrict__ bias, void* __restrict__ Yv,
    int M, int K, int N, int m0, int n0, float oscale) {
    extern __shared__ uint32_t sm[];
    uint32_t sbase = s2u(sm);
    uint32_t Ab_[2] = {sbase, sbase + 10240};
    uint32_t Bb_[2] = {sbase + 20480, sbase + 25600};
    uint32_t* BsW[2] = {sm + 5120, sm + 6400};

    int tid = threadIdx.x;
    int wid = tid >> 5, lane = tid & 31;
    int wm = wid >> 1, wn = wid & 1;

    int arow = tid >> 2, aslot = tid & 3;   // cp.async: 2 rows per thread (+64)
    int bn = tid & 63, bks = tid >> 6;      // B: pixel, 8 k per thread

    // ldmatrix per-lane byte offsets (within buffer)
    uint32_t a_off = (uint32_t)(wm * 32 + (lane & 7) + ((lane >> 3) & 1) * 8) * 80
                   + (uint32_t)(lane >> 4) * 16;
    uint32_t b_off = (uint32_t)(wn * 32 + (lane & 7) + ((lane >> 4) & 1) * 8) * 80
                   + (uint32_t)((lane >> 3) & 1) * 16;

    const int C = K >> 5;
    float br[8];

    // prologue: chunk 0
    CP16(Ab_[0] + arow * 80 + aslot * 16, W16 + (size_t)(m0 + arow) * K + aslot * 8);
    CP16(Ab_[0] + (arow + 64) * 80 + aslot * 16, W16 + (size_t)(m0 + arow + 64) * K + aslot * 8);
    CP_COMMIT();
#pragma unroll
    for (int j = 0; j < 8; ++j)
        br[j] = X[(size_t)(bks * 8 + j) * N + n0 + bn];

    float acc[2][4][4];
#pragma unroll
    for (int t = 0; t < 2; ++t)
#pragma unroll
        for (int u = 0; u < 4; ++u)
#pragma unroll
            for (int e = 0; e < 4; ++e) acc[t][u][e] = 0.0f;

#pragma unroll
    for (int j2 = 0; j2 < 4; ++j2)
        BsW[0][bn * 20 + bks * 4 + j2] = packh2(br[2 * j2], br[2 * j2 + 1]);
    CP_WAIT0();
    __syncthreads();

    for (int c = 0; c < C; ++c) {
        if (c + 1 < C) {
            int k0 = (c + 1) << 5;
            uint32_t ab = Ab_[(c + 1) & 1];
            CP16(ab + arow * 80 + aslot * 16, W16 + (size_t)(m0 + arow) * K + k0 + aslot * 8);
            CP16(ab + (arow + 64) * 80 + aslot * 16,
                 W16 + (size_t)(m0 + arow + 64) * K + k0 + aslot * 8);
            CP_COMMIT();
#pragma unroll
            for (int j = 0; j < 8; ++j)
                br[j] = X[(size_t)(k0 + bks * 8 + j) * N + n0 + bn];
        }

        uint32_t Abuf = Ab_[c & 1], Bbuf = Bb_[c & 1];
#pragma unroll
        for (int ks = 0; ks < 2; ++ks) {
            uint32_t a0[4], a1[4], b01[4], b23[4];
            LDSM4(a0, Abuf + a_off + ks * 32);
            LDSM4(a1, Abuf + a_off + 16 * 80 + ks * 32);
            LDSM4(b01, Bbuf + b_off + ks * 32);
            LDSM4(b23, Bbuf + b_off + 16 * 80 + ks * 32);
            mma_f16(acc[0][0], a0, b01);
            mma_f16(acc[0][1], a0, b01 + 2);
            mma_f16(acc[0][2], a0, b23);
            mma_f16(acc[0][3], a0, b23 + 2);
            mma_f16(acc[1][0], a1, b01);
            mma_f16(acc[1][1], a1, b01 + 2);
            mma_f16(acc[1][2], a1, b23);
            mma_f16(acc[1][3], a1, b23 + 2);
        }

        if (c + 1 < C) {
            CP_WAIT0();
            uint32_t* bw = BsW[(c + 1) & 1];
#pragma unroll
            for (int j2 = 0; j2 < 4; ++j2)
                bw[bn * 20 + bks * 4 + j2] = packh2(br[2 * j2], br[2 * j2 + 1]);
        }
        __syncthreads();
    }

    int g = lane >> 2, tg = lane & 3;
#pragma unroll
    for (int t = 0; t < 2; ++t) {
        int m1 = m0 + wm * 32 + t * 16 + g;
        int m2 = m1 + 8;
        float bv1 = bias[m1], bv2 = bias[m2];
#pragma unroll
        for (int u = 0; u < 4; ++u) {
            int n = n0 + wn * 32 + u * 8 + 2 * tg;
            float v0 = acc[t][u][0] + bv1;
            float v1 = acc[t][u][1] + bv1;
            float v2 = acc[t][u][2] + bv2;
            float v3 = acc[t][u][3] + bv2;
            if (ACT == 2) {
                v0 = 0.5f * v0 * (1.0f + erff(v0 * 0.70710678118654752f));
                v1 = 0.5f * v1 * (1.0f + erff(v1 * 0.70710678118654752f));
                v2 = 0.5f * v2 * (1.0f + erff(v2 * 0.70710678118654752f));
                v3 = 0.5f * v3 * (1.0f + erff(v3 * 0.70710678118654752f));
            }
            if (OUT16) {
                uint32_t* y16 = (uint32_t*)Yv;
                v0 *= oscale; v1 *= oscale; v2 *= oscale; v3 *= oscale;
                y16[(size_t)m1 * (N >> 1) + (n >> 1)] = packh2(v0, v1);
                y16[(size_t)m2 * (N >> 1) + (n >> 1)] = packh2(v2, v3);
            } else {
                float* Y = (float*)Yv;
                *(float2*)(Y + (size_t)m1 * N + n) = make_float2(v0, v1);
                *(float2*)(Y + (size_t)m2 * N + n) = make_float2(v2, v3);
            }
        }
    }
}

template <int ACT>
__global__ void __launch_bounds__(256, 2)
gemm_mma(const __half* __restrict__ W16, const float* __restrict__ X,
         const float* __restrict__ bias, float* __restrict__ Y,
         int M, int K, int N) {
    gemm_body<ACT, 0>(W16, X, bias, Y, M, K, N, blockIdx.y * 128, blockIdx.x * 64, 1.0f);
}

__global__ void __launch_bounds__(256, 2)
gemm_qkv(const __half* __restrict__ w16, const float* __restrict__ bq,
         const float* __restrict__ bk, const float* __restrict__ bv,
         const float* __restrict__ xq, const float* __restrict__ xkv,
         __half* __restrict__ q, __half* __restrict__ k, __half* __restrict__ v,
         const float* __restrict__ scale_ptr) {
    int z = blockIdx.z;
    const __half* W = w16 + (z == 0 ? OFF_Q : (z == 1 ? OFF_K : OFF_V));
    const float* B = (z == 0) ? bq : (z == 1) ? bk : bv;
    const float* X = (z == 0) ? xq : xkv;
    __half* Y = (z == 0) ? q : (z == 1) ? k : v;
    float osc = (z == 0) ? (1.4426950408889634f / scale_ptr[0]) : 1.0f;
    gemm_body<0, 1>(W, X, B, (void*)Y, DIMC, DIMC, NPIX,
                    blockIdx.y * 128, blockIdx.x * 64, osc);
}

// ---------------------------------------------------------------------------
// Full-column GEMM (M=256) + fused LayerNorm epilogue (proven R8 epilogues),
// mainloop upgraded to ldmatrix + cp.async + single-sync.
// 512 thr = 16 warps x m16, N-tile 32, grid 128.
// Smem u32 (46080B): A[2][256][20], B[2][32][20]; epilogue aliases Es[256][33].
// ---------------------------------------------------------------------------
#define GLN_SMEM 46080

template <int EPI>
__global__ void __launch_bounds__(512, 1)
gemm_ln(const __half* __restrict__ W16, const float* __restrict__ X,
        const float* __restrict__ bias, const float* __restrict__ res,
        const float* __restrict__ lng, const float* __restrict__ lnb,
        float* __restrict__ Y, int K,
        const float* __restrict__ s1x, const float* __restrict__ s1g,
        const float* __restrict__ s1b,
        const float* __restrict__ s2x, const float* __restrict__ s2g,
        const float* __restrict__ s2b,
        const float* __restrict__ pos,
        float* __restrict__ y1, float* __restrict__ y2) {
    extern __shared__ uint32_t sm[];
    uint32_t sbase = s2u(sm);
    uint32_t Ab_[2] = {sbase, sbase + 20480};
    uint32_t Bb_[2] = {sbase + 40960, sbase + 43520};
    uint32_t* BsW[2] = {sm + 10240, sm + 10880};

    int tid = threadIdx.x;
    int wid = tid >> 5, lane = tid & 31;
    int wm = wid;
    int n0 = blockIdx.x * 32;

    int arow = tid >> 2, aslot = tid & 3;   // +128 rows on 2nd cp.async
    int bn = tid & 31, bj = tid >> 5;       // B: pixel, k-pair 0..15

    uint32_t a_off = (uint32_t)(wm * 16 + (lane & 7) + ((lane >> 3) & 1) * 8) * 80
                   + (uint32_t)(lane >> 4) * 16;
    uint32_t b_off = (uint32_t)((lane & 7) + ((lane >> 4) & 1) * 8) * 80
                   + (uint32_t)((lane >> 3) & 1) * 16;

    const int C = K >> 5;
    float b0r, b1r;

    CP16(Ab_[0] + arow * 80 + aslot * 16, W16 + (size_t)arow * K + aslot * 8);
    CP16(Ab_[0] + (arow + 128) * 80 + aslot * 16, W16 + (size_t)(arow + 128) * K + aslot * 8);
    CP_COMMIT();
    b0r = X[(size_t)(bj * 2) * NPIX + n0 + bn];
    b1r = X[(size_t)(bj * 2 + 1) * NPIX + n0 + bn];

    float acc[4][4];
#pragma unroll
    for (int u = 0; u < 4; ++u)
#pragma unroll
        for (int e = 0; e < 4; ++e) acc[u][e] = 0.0f;

    BsW[0][bn * 20 + bj] = packh2(b0r, b1r);
    CP_WAIT0();
    __syncthreads();

    for (int c = 0; c < C; ++c) {
        if (c + 1 < C) {
            int k0 = (c + 1) << 5;
            uint32_t ab = Ab_[(c + 1) & 1];
            CP16(ab + arow * 80 + aslot * 16, W16 + (size_t)arow * K + k0 + aslot * 8);
            CP16(ab + (arow + 128) * 80 + aslot * 16,
                 W16 + (size_t)(arow + 128) * K + k0 + aslot * 8);
            CP_COMMIT();
            b0r = X[(size_t)(k0 + bj * 2) * NPIX + n0 + bn];
            b1r = X[(size_t)(k0 + bj * 2 + 1) * NPIX + n0 + bn];
        }

        uint32_t Abuf = Ab_[c & 1], Bbuf = Bb_[c & 1];
#pragma unroll
        for (int ks = 0; ks < 2; ++ks) {
            uint32_t a[4], b01[4], b23[4];
            LDSM4(a, Abuf + a_off + ks * 32);
            LDSM4(b01, Bbuf + b_off + ks * 32);
            LDSM4(b23, Bbuf + b_off + 16 * 80 + ks * 32);
            mma_f16(acc[0], a, b01);
            mma_f16(acc[1], a, b01 + 2);
            mma_f16(acc[2], a, b23);
            mma_f16(acc[3], a, b23 + 2);
        }

        if (c + 1 < C) {
            CP_WAIT0();
            BsW[(c + 1) & 1][bn * 20 + bj] = packh2(b0r, b1r);
        }
        __syncthreads();
    }

    // epilogue (identical math to R8): Es[256][33] + partials alias the smem
    float* Es = (float*)sm;
    float* sp = Es + 8448;
    float* sq = sp + 512;
    int g = lane >> 2, tg = lane & 3;

    {
        int r0 = wm * 16 + g, r1 = r0 + 8;
        float bv0 = bias[r0], bv1 = bias[r1];
#pragma unroll
        for (int u = 0; u < 4; ++u) {
            int n = u * 8 + 2 * tg;
            float v0 = acc[u][0] + bv0, v1 = acc[u][1] + bv0;
            float v2 = acc[u][2] + bv1, v3 = acc[u][3] + bv1;
            if (EPI == 1) {
                size_t gi0 = (size_t)r0 * NPIX + n0 + n;
                size_t gi1 = (size_t)r1 * NPIX + n0 + n;
                float2 q0 = *(const float2*)(res + gi0);
                float2 q1 = *(const float2*)(res + gi1);
                v0 += q0.x; v1 += q0.y; v2 += q1.x; v3 += q1.y;
            }
            Es[r0 * 33 + n] = v0;
            Es[r0 * 33 + n + 1] = v1;
            Es[r1 * 33 + n] = v2;
            Es[r1 * 33 + n + 1] = v3;
        }
    }
    __syncthreads();

    int px = tid & 31, cg = tid >> 5;
    if (EPI == 1) {
        float e[16], s = 0.0f, q = 0.0f;
#pragma unroll
        for (int i = 0; i < 16; ++i) {
            e[i] = Es[(cg * 16 + i) * 33 + px];
            s += e[i];
            q = fmaf(e[i], e[i], q);
        }
        sp[cg * 32 + px] = s;
        sq[cg * 32 + px] = q;
        __syncthreads();
        float ts = 0.0f, tq = 0.0f;
#pragma unroll
        for (int j = 0; j < 16; ++j) {
            ts += sp[j * 32 + px];
            tq += sq[j * 32 + px];
        }
        float mean = ts * (1.0f / DIMC);
        float rstd = rsqrtf(tq * (1.0f / DIMC) - mean * mean + 1e-5f);
#pragma unroll
        for (int i = 0; i < 16; ++i) {
            int cc = cg * 16 + i;
            Y[(size_t)cc * NPIX + n0 + px] = (e[i] - mean) * rstd * lng[cc] + lnb[cc];
        }
    } else {
        float v[16], s = 0.0f, q = 0.0f;
#pragma unroll
        for (int i = 0; i < 16; ++i) {
            v[i] = s1x[(size_t)(cg * 16 + i) * NPIX + n0 + px];
            s += v[i];
            q = fmaf(v[i], v[i], q);
        }
        sp[cg * 32 + px] = s;
        sq[cg * 32 + px] = q;
        __syncthreads();
        float ts = 0.0f, tq = 0.0f;
#pragma unroll
        for (int j = 0; j < 16; ++j) {
            ts += sp[j * 32 + px];
            tq += sq[j * 32 + px];
        }
        float mean = ts * (1.0f / DIMC);
        float rstd = rsqrtf(tq * (1.0f / DIMC) - mean * mean + 1e-5f);
#pragma unroll
        for (int i = 0; i < 16; ++i) {
            int cc = cg * 16 + i;
            y1[(size_t)cc * NPIX + n0 + px] =
                (v[i] - mean) * rstd * s1g[cc] + s1b[cc] + pos[cc] + Es[cc * 33 + px];
        }
        __syncthreads();
        s = 0.0f; q = 0.0f;
#pragma unroll
        for (int i = 0; i < 16; ++i) {
            v[i] = s2x[(size_t)(cg * 16 + i) * NPIX + n0 + px];
            s += v[i];
            q = fmaf(v[i], v[i], q);
        }
        sp[cg * 32 + px] = s;
        sq[cg * 32 + px] = q;
        __syncthreads();
        ts = 0.0f; tq = 0.0f;
#pragma unroll
        for (int j = 0; j < 16; ++j) {
            ts += sp[j * 32 + px];
            tq += sq[j * 32 + px];
        }
        mean = ts * (1.0f / DIMC);
        rstd = rsqrtf(tq * (1.0f / DIMC) - mean * mean + 1e-5f);
#pragma unroll
        for (int i = 0; i < 16; ++i) {
            int cc = cg * 16 + i;
            y2[(size_t)cc * NPIX + n0 + px] =
                (v[i] - mean) * rstd * s2g[cc] + s2b[cc] + pos[cc] + Es[cc * 33 + px];
        }
    }
}

// ---------------------------------------------------------------------------
// Flash attention, fp16 HMMA + MUFU exp2 (proven R7/R8 — unchanged).
// ---------------------------------------------------------------------------
#define FL_SMEM 37888

__global__ void __launch_bounds__(256, 2)
flash_mma(const __half* __restrict__ Q16, const __half* __restrict__ K16,
          const __half* __restrict__ V16, float* __restrict__ O) {
    extern __shared__ uint32_t fsm[];
    uint32_t* Ks = fsm;               // [2][64][20]
    uint32_t* Vs = fsm + 2560;        // [2][32][36]
    uint32_t* Ps = fsm + 4864;        // [128][36]

    int tid = threadIdx.x;
    int wid = tid >> 5, lane = tid & 31;
    int g = lane >> 2, tg = lane & 3;
    int h = blockIdx.y;
    int n0 = blockIdx.x * 128;
    int r0 = wid * 16 + g, r1 = r0 + 8;

    const __half* Qh = Q16 + (size_t)h * 32 * NPIX;
    const __half* Kh = K16 + (size_t)h * 32 * NPIX;
    const uint32_t* Vhu = (const uint32_t*)(V16 + (size_t)h * 32 * NPIX);

    int kkey = tid & 63, kds = tid >> 6;
    int vd = tid >> 4, vslot = tid & 15;

    __half kr[2][4];
    uint2 vr[2];
#pragma unroll
    for (int i = 0; i < 2; ++i) {
        int ds = kds + i * 4;
#pragma unroll
        for (int j = 0; j < 4; ++j)
            kr[i][j] = Kh[(size_t)(ds * 4 + j) * NPIX + kkey];
        vr[i] = *(const uint2*)(Vhu + (size_t)(vd + i * 16) * 2048 + vslot * 2);
    }

    __half* Qsh = (__half*)Ps;
#pragma unroll
    for (int it = 0; it < 4; ++it) {
        int t = tid + it * 256;
        int q4 = t & 31, d = t >> 5;
        uint2 qv = *(const uint2*)(Qh + (size_t)d * NPIX + n0 + q4 * 4);
        const __half* qp = (const __half*)&qv;
        Qsh[(q4 * 4 + 0) * 40 + d] = qp[0];
        Qsh[(q4 * 4 + 1) * 40 + d] = qp[1];
        Qsh[(q4 * 4 + 2) * 40 + d] = qp[2];
        Qsh[(q4 * 4 + 3) * 40 + d] = qp[3];
    }
    __syncthreads();
    uint32_t qa[2][4];
#pragma unroll
    for (int ks = 0; ks < 2; ++ks) {
        int kc = ks * 8 + tg;
        qa[ks][0] = Ps[r0 * 20 + kc];
        qa[ks][1] = Ps[r1 * 20 + kc];
        qa[ks][2] = Ps[r0 * 20 + kc + 4];
        qa[ks][3] = Ps[r1 * 20 + kc + 4];
    }
#pragma unroll
    for (int i = 0; i < 2; ++i) {
        int ds = kds + i * 4;
        *(uint2*)(Ks + kkey * 20 + ds * 2) =
            make_uint2(packhh(kr[i][0], kr[i][1]), packhh(kr[i][2], kr[i][3]));
        *(uint2*)(Vs + (vd + i * 16) * 36 + vslot * 2) = vr[i];
    }
    __syncthreads();

    float m0s = -1e30f, m1s = -1e30f, l0 = 0.0f, l1 = 0.0f;
    float oa[4][4];
#pragma unroll
    for (int u = 0; u < 4; ++u)
#pragma unroll
        for (int e = 0; e < 4; ++e) oa[u][e] = 0.0f;

    for (int kt = 0; kt < 64; ++kt) {
        if (kt + 1 < 64) {
            int mg = (kt + 1) * 64;
#pragma unroll
            for (int i = 0; i < 2; ++i) {
                int ds = kds + i * 4;
#pragma unroll
                for (int j = 0; j < 4; ++j)
                    kr[i][j] = Kh[(size_t)(ds * 4 + j) * NPIX + mg + kkey];
                vr[i] = *(const uint2*)(Vhu + (size_t)(vd + i * 16) * 2048 + (mg >> 1) + vslot * 2);
            }
        }

        const uint32_t* Ksb = Ks + (kt & 1) * 1280;
        const uint32_t* Vsb = Vs + (kt & 1) * 1152;

        float sc[8][4];
#pragma unroll
        for (int ns = 0; ns < 8; ++ns)
#pragma unroll
            for (int e = 0; e < 4; ++e) sc[ns][e] = 0.0f;
#pragma unroll
        for (int ks = 0; ks < 2; ++ks) {
            int kc = ks * 8 + tg;
#pragma unroll
            for (int ns = 0; ns < 8; ++ns) {
                uint32_t b[2];
                b[0] = Ksb[(ns * 8 + g) * 20 + kc];
                b[1] = Ksb[(ns * 8 + g) * 20 + kc + 4];
                mma_f16(sc[ns], qa[ks], b);
            }
        }

        float mx0 = -1e30f, mx1 = -1e30f;
#pragma unroll
        for (int ns = 0; ns < 8; ++ns) {
            mx0 = fmaxf(mx0, fmaxf(sc[ns][0], sc[ns][1]));
            mx1 = fmaxf(mx1, fmaxf(sc[ns][2], sc[ns][3]));
        }
        mx0 = fmaxf(mx0, __shfl_xor_sync(0xffffffffu, mx0, 1));
        mx0 = fmaxf(mx0, __shfl_xor_sync(0xffffffffu, mx0, 2));
        mx1 = fmaxf(mx1, __shfl_xor_sync(0xffffffffu, mx1, 1));
        mx1 = fmaxf(mx1, __shfl_xor_sync(0xffffffffu, mx1, 2));
        float mn0 = fmaxf(m0s, mx0), mn1 = fmaxf(m1s, mx1);
        float c0f = fexp2(m0s - mn0), c1f = fexp2(m1s - mn1);
        float rs0 = 0.0f, rs1 = 0.0f;
#pragma unroll
        for (int ns = 0; ns < 8; ++ns) {
            float p0 = fexp2(sc[ns][0] - mn0);
            float p1 = fexp2(sc[ns][1] - mn0);
            float p2 = fexp2(sc[ns][2] - mn1);
            float p3 = fexp2(sc[ns][3] - mn1);
            rs0 += p0 + p1;
            rs1 += p2 + p3;
            Ps[r0 * 36 + ns * 4 + tg] = packh2(p0, p1);
            Ps[r1 * 36 + ns * 4 + tg] = packh2(p2, p3);
        }
        rs0 += __shfl_xor_sync(0xffffffffu, rs0, 1);
        rs0 += __shfl_xor_sync(0xffffffffu, rs0, 2);
        rs1 += __shfl_xor_sync(0xffffffffu, rs1, 1);
        rs1 += __shfl_xor_sync(0xffffffffu, rs1, 2);
        l0 = l0 * c0f + rs0;
        l1 = l1 * c1f + rs1;
        m0s = mn0; m1s = mn1;
#pragma unroll
        for (int u = 0; u < 4; ++u) {
            oa[u][0] *= c0f; oa[u][1] *= c0f;
            oa[u][2] *= c1f; oa[u][3] *= c1f;
        }
        __syncwarp();

#pragma unroll
        for (int ks = 0; ks < 4; ++ks) {
            int kc = ks * 8 + tg;
            uint32_t pa[4];
            pa[0] = Ps[r0 * 36 + kc];
            pa[1] = Ps[r1 * 36 + kc];
            pa[2] = Ps[r0 * 36 + kc + 4];
            pa[3] = Ps[r1 * 36 + kc + 4];
#pragma unroll
            for (int ns = 0; ns < 4; ++ns) {
                uint32_t b[2];
                b[0] = Vsb[(ns * 8 + g) * 36 + kc];
                b[1] = Vsb[(ns * 8 + g) * 36 + kc + 4];
                mma_f16(oa[ns], pa, b);
            }
        }
        __syncwarp();

        if (kt + 1 < 64) {
            uint32_t* Ksn = Ks + ((kt + 1) & 1) * 1280;
            uint32_t* Vsn = Vs + ((kt + 1) & 1) * 1152;
#pragma unroll
            for (int i = 0; i < 2; ++i) {
                int ds = kds + i * 4;
                *(uint2*)(Ksn + kkey * 20 + ds * 2) =
                    make_uint2(packhh(kr[i][0], kr[i][1]), packhh(kr[i][2], kr[i][3]));
                *(uint2*)(Vsn + (vd + i * 16) * 36 + vslot * 2) = vr[i];
            }
            __syncthreads();
        }
    }

    float il0 = 1.0f / l0, il1 = 1.0f / l1;
#pragma unroll
    for (int ns = 0; ns < 4; ++ns) {
        int d0 = ns * 8 + 2 * tg;
        O[(size_t)(h * 32 + d0) * NPIX + n0 + r0] = oa[ns][0] * il0;
        O[(size_t)(h * 32 + d0 + 1) * NPIX + n0 + r0] = oa[ns][1] * il0;
        O[(size_t)(h * 32 + d0) * NPIX + n0 + r1] = oa[ns][2] * il1;
        O[(size_t)(h * 32 + d0 + 1) * NPIX + n0 + r1] = oa[ns][3] * il1;
    }
}

// ---------------------------------------------------------------------------
extern "C" void kernel_launch(void* const* d_in, const int* in_sizes, int n_in,
                              void* d_out, int out_size) {
    const float* rgb   = (const float*)d_in[0];
    const float* dpt   = (const float*)d_in[1];
    const float* xdpt  = (const float*)d_in[2];
    const float* wq    = (const float*)d_in[3];
    const float* bq    = (const float*)d_in[4];
    const float* wk    = (const float*)d_in[5];
    const float* bk    = (const float*)d_in[6];
    const float* wv    = (const float*)d_in[7];
    const float* bv    = (const float*)d_in[8];
    const float* wo    = (const float*)d_in[9];
    const float* bo    = (const float*)d_in[10];
    const float* ga_rgb = (const float*)d_in[11];
    const float* be_rgb = (const float*)d_in[12];
    const float* ga_dpt = (const float*)d_in[13];
    const float* be_dpt = (const float*)d_in[14];
    const float* ga1   = (const float*)d_in[15];
    const float* be1   = (const float*)d_in[16];
    const float* ga2   = (const float*)d_in[17];
    const float* be2   = (const float*)d_in[18];
    const float* w_mlp1 = (const float*)d_in[19];
    const float* b_mlp1 = (const float*)d_in[20];
    const float* w_mlp2 = (const float*)d_in[21];
    const float* b_mlp2 = (const float*)d_in[22];
    const float* w_de1 = (const float*)d_in[23];
    const float* b_de1 = (const float*)d_in[24];
    const float* w_de2 = (const float*)d_in[25];
    const float* b_de2 = (const float*)d_in[26];
    const float* pos_emb = (const float*)d_in[27];
    const float* scale = (const float*)d_in[28];
    float* out = (float*)d_out;

    float *p_xd, *p_r1, *p_rgbln, *p_dptln, *p_fused, *p_oln, *p_h;
    __half *p_q16, *p_k16, *p_v16, *p_w16;
    cudaGetSymbolAddress((void**)&p_xd, g_xd);
    cudaGetSymbolAddress((void**)&p_r1, g_r1);
    cudaGetSymbolAddress((void**)&p_rgbln, g_rgbln);
    cudaGetSymbolAddress((void**)&p_dptln, g_dptln);
    cudaGetSymbolAddress((void**)&p_q16, g_q16);
    cudaGetSymbolAddress((void**)&p_k16, g_k16);
    cudaGetSymbolAddress((void**)&p_v16, g_v16);
    cudaGetSymbolAddress((void**)&p_fused, g_fused);
    cudaGetSymbolAddress((void**)&p_oln, g_oln);
    cudaGetSymbolAddress((void**)&p_h, g_h);
    cudaGetSymbolAddress((void**)&p_w16, g_w16);

    static bool attr_done = false;
    if (!attr_done) {
        cudaFuncSetAttribute(gemm_mma<2>, cudaFuncAttributeMaxDynamicSharedMemorySize, GEMM_SMEM);
        cudaFuncSetAttribute(gemm_qkv, cudaFuncAttributeMaxDynamicSharedMemorySize, GEMM_SMEM);
        cudaFuncSetAttribute(gemm_ln<0>, cudaFuncAttributeMaxDynamicSharedMemorySize, GLN_SMEM);
        cudaFuncSetAttribute(gemm_ln<1>, cudaFuncAttributeMaxDynamicSharedMemorySize, GLN_SMEM);
        cudaFuncSetAttribute(flash_mma, cudaFuncAttributeMaxDynamicSharedMemorySize, FL_SMEM);
        attr_done = true;
    }

    // weights -> fp16 pool (once per call; part of the graph)
    cvt_weights<<<dim3(128, 7), 256>>>(w_de2, wq, wk, wv, wo, w_mlp1, w_mlp2, p_w16);

    // depth positional-embedding path
    downsample_kernel<<<16, 256>>>(xdpt, p_xd);
    conv3_kernel<<<256, 256>>>(p_xd, w_de1, b_de1, p_r1);

    // pe GEMM fused with LN(rgb)+pos+pe and LN(dpt)+pos+pe
    gemm_ln<0><<<128, 512, GLN_SMEM>>>(p_w16 + OFF_DE2, p_r1, b_de2, nullptr, nullptr, nullptr,
                                       nullptr, DIMC,
                                       rgb, ga_rgb, be_rgb, dpt, ga_dpt, be_dpt,
                                       pos_emb, p_rgbln, p_dptln);

    // QKV projections — one launch, fp16 outputs, q pre-scaled
    gemm_qkv<<<dim3(64, 2, 3), 256, GEMM_SMEM>>>(p_w16, bq, bk, bv,
                                                 p_rgbln, p_dptln, p_q16, p_k16, p_v16, scale);

    // flash attention (fp16 in, 8 heads x 32 q-tiles of 128)
    flash_mma<<<dim3(32, 8), 256, FL_SMEM>>>(p_q16, p_k16, p_v16, p_fused);

    // output proj + residual + LN1 fused -> oln
    gemm_ln<1><<<128, 512, GLN_SMEM>>>(p_w16 + OFF_O, p_fused, bo, rgb, ga1, be1,
                                       p_oln, DIMC,
                                       nullptr, nullptr, nullptr, nullptr, nullptr,
                                       nullptr, nullptr, nullptr, nullptr);

    // MLP up (exact gelu)
    gemm_mma<2><<<dim3(64, 8), 256, GEMM_SMEM>>>(p_w16 + OFF_M1, p_oln, b_mlp1, p_h,
                                                 MLPC, DIMC, NPIX);

    // MLP down + residual + final LN fused -> d_out
    gemm_ln<1><<<128, 512, GLN_SMEM>>>(p_w16 + OFF_M2, p_h, b_mlp2, p_oln, ga2, be2,
                                       out, MLPC,
                                       nullptr, nullptr, nullptr, nullptr, nullptr,
                                       nullptr, nullptr, nullptr, nullptr);
}

// round 10
// speedup vs baseline: 11.2323x; 1.0328x over previous
#include <cuda_runtime.h>
#include <cuda_fp16.h>
#include <math.h>
#include <stdint.h>

// ---------------------------------------------------------------------------
// B=1, DIM=256, HEADS=8, HD=32, H=W=64 -> N=4096, MLP=1024
// Layout: [C][N] (NCHW flattened), row stride N=4096.
// ---------------------------------------------------------------------------
#define NPIX 4096
#define DIMC 256
#define MLPC 1024

__device__ float g_xd[NPIX];
__device__ float g_r1[DIMC * NPIX];
__device__ float g_rgbln[DIMC * NPIX];
__device__ float g_dptln[DIMC * NPIX];
__device__ __half g_q16[DIMC * NPIX];
__device__ __half g_k16[DIMC * NPIX];
__device__ __half g_v16[DIMC * NPIX];
__device__ float g_fused[DIMC * NPIX];
__device__ float g_oln[DIMC * NPIX];
__device__ float g_h[MLPC * NPIX];

// fp16 weight pool (converted once per launch)
#define OFF_DE2 0
#define OFF_Q   65536
#define OFF_K   131072
#define OFF_V   196608
#define OFF_O   262144
#define OFF_M1  327680
#define OFF_M2  589824
__device__ __half g_w16[851968];

__device__ __forceinline__ float fexp2(float x) {
    float y;
    asm("ex2.approx.f32 %0, %1;" : "=f"(y) : "f"(x));
    return y;
}
__device__ __forceinline__ uint32_t packh2(float a, float b) {
    __half2 h = __floats2half2_rn(a, b);
    return *(uint32_t*)&h;
}
__device__ __forceinline__ uint32_t packhh(__half a, __half b) {
    __half2 h = __halves2half2(a, b);
    return *(uint32_t*)&h;
}
__device__ __forceinline__ uint32_t s2u(const void* p) {
    uint32_t a;
    asm("{ .reg .u64 t; cvta.to.shared.u64 t, %1; cvt.u32.u64 %0, t; }" : "=r"(a) : "l"(p));
    return a;
}
__device__ __forceinline__ void mma_f16(float c[4], const uint32_t a[4], const uint32_t b[2]) {
    asm volatile(
        "mma.sync.aligned.m16n8k16.row.col.f32.f16.f16.f32 "
        "{%0,%1,%2,%3}, {%4,%5,%6,%7}, {%8,%9}, {%0,%1,%2,%3};"
        : "+f"(c[0]), "+f"(c[1]), "+f"(c[2]), "+f"(c[3])
        : "r"(a[0]), "r"(a[1]), "r"(a[2]), "r"(a[3]), "r"(b[0]), "r"(b[1]));
}
#define LDSM4(r, addr) \
    asm volatile("ldmatrix.sync.aligned.m8n8.x4.shared.b16 {%0,%1,%2,%3}, [%4];" \
                 : "=r"((r)[0]), "=r"((r)[1]), "=r"((r)[2]), "=r"((r)[3]) : "r"(addr))
#define CP16(d, s) \
    asm volatile("cp.async.cg.shared.global [%0], [%1], 16;" :: "r"(d), "l"(s))
#define CP_COMMIT() asm volatile("cp.async.commit_group;")
#define CP_WAIT0() asm volatile("cp.async.wait_group 0;" ::: "memory")

// ---------------------------------------------------------------------------
// Weight fp32 -> fp16 conversion (once per launch). grid (128, 7).
// ---------------------------------------------------------------------------
__global__ void cvt_weights(const float* __restrict__ de2, const float* __restrict__ q,
                            const float* __restrict__ k, const float* __restrict__ v,
                            const float* __restrict__ o, const float* __restrict__ m1,
                            const float* __restrict__ m2, __half* __restrict__ out) {
    int r = blockIdx.y;
    const float* src;
    __half* dst;
    int n;
    switch (r) {
        case 0: src = de2; dst = out + OFF_DE2; n = 65536; break;
        case 1: src = q;   dst = out + OFF_Q;   n = 65536; break;
        case 2: src = k;   dst = out + OFF_K;   n = 65536; break;
        case 3: src = v;   dst = out + OFF_V;   n = 65536; break;
        case 4: src = o;   dst = out + OFF_O;   n = 65536; break;
        case 5: src = m1;  dst = out + OFF_M1;  n = 262144; break;
        default: src = m2; dst = out + OFF_M2;  n = 262144; break;
    }
    int idx = (blockIdx.x * 256 + threadIdx.x) * 8;
    if (idx >= n) return;
    float4 f0 = *(const float4*)(src + idx);
    float4 f1 = *(const float4*)(src + idx + 4);
    uint4 u;
    u.x = packh2(f0.x, f0.y); u.y = packh2(f0.z, f0.w);
    u.z = packh2(f1.x, f1.y); u.w = packh2(f1.z, f1.w);
    *(uint4*)(dst + idx) = u;
}

// ---------------------------------------------------------------------------
// Bilinear 16x downsample 1024x1024 -> 64x64 (align_corners=False)
// ---------------------------------------------------------------------------
__global__ void downsample_kernel(const float* __restrict__ x, float* __restrict__ xd) {
    int p = blockIdx.x * 256 + threadIdx.x;
    int i = p >> 6, j = p & 63;
    int base = (16 * i + 7) * 1024 + (16 * j + 7);
    xd[p] = 0.25f * (x[base] + x[base + 1] + x[base + 1024] + x[base + 1025]);
}

// conv3x3 (1 in, 256 out) + bias + relu
__global__ void conv3_kernel(const float* __restrict__ xd, const float* __restrict__ w,
                             const float* __restrict__ bias, float* __restrict__ y) {
    __shared__ float s_xd[NPIX];
    int tid = threadIdx.x;
    int o = blockIdx.x;
    for (int e = tid; e < NPIX; e += 256) s_xd[e] = xd[e];
    __syncthreads();
    float wr[9];
#pragma unroll
    for (int t = 0; t < 9; ++t) wr[t] = w[o * 9 + t];
    float bv = bias[o];
    for (int it = 0; it < 16; ++it) {
        int p = tid + it * 256;
        int i = p >> 6, j = p & 63;
        float acc = bv;
#pragma unroll
        for (int di = 0; di < 3; ++di) {
            int ii = i + di - 1;
            if (ii < 0 || ii > 63) continue;
#pragma unroll
            for (int dj = 0; dj < 3; ++dj) {
                int jj = j + dj - 1;
                if (jj < 0 || jj > 63) continue;
                acc = fmaf(wr[di * 3 + dj], s_xd[ii * 64 + jj], acc);
            }
        }
        y[o * NPIX + p] = fmaxf(acc, 0.0f);
    }
}

// ---------------------------------------------------------------------------
// GEMM fp16 m16n8k16, ldmatrix + cp.async (validated R9).
// ---------------------------------------------------------------------------
#define GEMM_SMEM 30720

template <int ACT, int OUT16>
__device__ __forceinline__ void gemm_body(
    const __half* __restrict__ W16, const float* __restrict__ X,
    const float* __restrict__ bias, void* __restrict__ Yv,
    int M, int K, int N, int m0, int n0, float oscale) {
    extern __shared__ uint32_t sm[];
    uint32_t sbase = s2u(sm);
    uint32_t Ab_[2] = {sbase, sbase + 10240};
    uint32_t Bb_[2] = {sbase + 20480, sbase + 25600};
    uint32_t* BsW[2] = {sm + 5120, sm + 6400};

    int tid = threadIdx.x;
    int wid = tid >> 5, lane = tid & 31;
    int wm = wid >> 1, wn = wid & 1;

    int arow = tid >> 2, aslot = tid & 3;
    int bn = tid & 63, bks = tid >> 6;

    uint32_t a_off = (uint32_t)(wm * 32 + (lane & 7) + ((lane >> 3) & 1) * 8) * 80
                   + (uint32_t)(lane >> 4) * 16;
    uint32_t b_off = (uint32_t)(wn * 32 + (lane & 7) + ((lane >> 4) & 1) * 8) * 80
                   + (uint32_t)((lane >> 3) & 1) * 16;

    const int C = K >> 5;
    float br[8];

    CP16(Ab_[0] + arow * 80 + aslot * 16, W16 + (size_t)(m0 + arow) * K + aslot * 8);
    CP16(Ab_[0] + (arow + 64) * 80 + aslot * 16, W16 + (size_t)(m0 + arow + 64) * K + aslot * 8);
    CP_COMMIT();
#pragma unroll
    for (int j = 0; j < 8; ++j)
        br[j] = X[(size_t)(bks * 8 + j) * N + n0 + bn];

    float acc[2][4][4];
#pragma unroll
    for (int t = 0; t < 2; ++t)
#pragma unroll
        for (int u = 0; u < 4; ++u)
#pragma unroll
            for (int e = 0; e < 4; ++e) acc[t][u][e] = 0.0f;

#pragma unroll
    for (int j2 = 0; j2 < 4; ++j2)
        BsW[0][bn * 20 + bks * 4 + j2] = packh2(br[2 * j2], br[2 * j2 + 1]);
    CP_WAIT0();
    __syncthreads();

    for (int c = 0; c < C; ++c) {
        if (c + 1 < C) {
            int k0 = (c + 1) << 5;
            uint32_t ab = Ab_[(c + 1) & 1];
            CP16(ab + arow * 80 + aslot * 16, W16 + (size_t)(m0 + arow) * K + k0 + aslot * 8);
            CP16(ab + (arow + 64) * 80 + aslot * 16,
                 W16 + (size_t)(m0 + arow + 64) * K + k0 + aslot * 8);
            CP_COMMIT();
#pragma unroll
            for (int j = 0; j < 8; ++j)
                br[j] = X[(size_t)(k0 + bks * 8 + j) * N + n0 + bn];
        }

        uint32_t Abuf = Ab_[c & 1], Bbuf = Bb_[c & 1];
#pragma unroll
        for (int ks = 0; ks < 2; ++ks) {
            uint32_t a0[4], a1[4], b01[4], b23[4];
            LDSM4(a0, Abuf + a_off + ks * 32);
            LDSM4(a1, Abuf + a_off + 16 * 80 + ks * 32);
            LDSM4(b01, Bbuf + b_off + ks * 32);
            LDSM4(b23, Bbuf + b_off + 16 * 80 + ks * 32);
            mma_f16(acc[0][0], a0, b01);
            mma_f16(acc[0][1], a0, b01 + 2);
            mma_f16(acc[0][2], a0, b23);
            mma_f16(acc[0][3], a0, b23 + 2);
            mma_f16(acc[1][0], a1, b01);
            mma_f16(acc[1][1], a1, b01 + 2);
            mma_f16(acc[1][2], a1, b23);
            mma_f16(acc[1][3], a1, b23 + 2);
        }

        if (c + 1 < C) {
            CP_WAIT0();
            uint32_t* bw = BsW[(c + 1) & 1];
#pragma unroll
            for (int j2 = 0; j2 < 4; ++j2)
                bw[bn * 20 + bks * 4 + j2] = packh2(br[2 * j2], br[2 * j2 + 1]);
        }
        __syncthreads();
    }

    int g = lane >> 2, tg = lane & 3;
#pragma unroll
    for (int t = 0; t < 2; ++t) {
        int m1 = m0 + wm * 32 + t * 16 + g;
        int m2 = m1 + 8;
        float bv1 = bias[m1], bv2 = bias[m2];
#pragma unroll
        for (int u = 0; u < 4; ++u) {
            int n = n0 + wn * 32 + u * 8 + 2 * tg;
            float v0 = acc[t][u][0] + bv1;
            float v1 = acc[t][u][1] + bv1;
            float v2 = acc[t][u][2] + bv2;
            float v3 = acc[t][u][3] + bv2;
            if (ACT == 2) {
                v0 = 0.5f * v0 * (1.0f + erff(v0 * 0.70710678118654752f));
                v1 = 0.5f * v1 * (1.0f + erff(v1 * 0.70710678118654752f));
                v2 = 0.5f * v2 * (1.0f + erff(v2 * 0.70710678118654752f));
                v3 = 0.5f * v3 * (1.0f + erff(v3 * 0.70710678118654752f));
            }
            if (OUT16) {
                uint32_t* y16 = (uint32_t*)Yv;
                v0 *= oscale; v1 *= oscale; v2 *= oscale; v3 *= oscale;
                y16[(size_t)m1 * (N >> 1) + (n >> 1)] = packh2(v0, v1);
                y16[(size_t)m2 * (N >> 1) + (n >> 1)] = packh2(v2, v3);
            } else {
                float* Y = (float*)Yv;
                *(float2*)(Y + (size_t)m1 * N + n) = make_float2(v0, v1);
                *(float2*)(Y + (size_t)m2 * N + n) = make_float2(v2, v3);
            }
        }
    }
}

template <int ACT>
__global__ void __launch_bounds__(256, 2)
gemm_mma(const __half* __restrict__ W16, const float* __restrict__ X,
         const float* __restrict__ bias, float* __restrict__ Y,
         int M, int K, int N) {
    gemm_body<ACT, 0>(W16, X, bias, Y, M, K, N, blockIdx.y * 128, blockIdx.x * 64, 1.0f);
}

__global__ void __launch_bounds__(256, 2)
gemm_qkv(const __half* __restrict__ w16, const float* __restrict__ bq,
         const float* __restrict__ bk, const float* __restrict__ bv,
         const float* __restrict__ xq, const float* __restrict__ xkv,
         __half* __restrict__ q, __half* __restrict__ k, __half* __restrict__ v,
         const float* __restrict__ scale_ptr) {
    int z = blockIdx.z;
    const __half* W = w16 + (z == 0 ? OFF_Q : (z == 1 ? OFF_K : OFF_V));
    const float* B = (z == 0) ? bq : (z == 1) ? bk : bv;
    const float* X = (z == 0) ? xq : xkv;
    __half* Y = (z == 0) ? q : (z == 1) ? k : v;
    float osc = (z == 0) ? (1.4426950408889634f / scale_ptr[0]) : 1.0f;
    gemm_body<0, 1>(W, X, B, (void*)Y, DIMC, DIMC, NPIX,
                    blockIdx.y * 128, blockIdx.x * 64, osc);
}

// ---------------------------------------------------------------------------
// Full-column GEMM (M=256) + fused LayerNorm epilogue (validated R9).
// ---------------------------------------------------------------------------
#define GLN_SMEM 46080

template <int EPI>
__global__ void __launch_bounds__(512, 1)
gemm_ln(const __half* __restrict__ W16, const float* __restrict__ X,
        const float* __restrict__ bias, const float* __restrict__ res,
        const float* __restrict__ lng, const float* __restrict__ lnb,
        float* __restrict__ Y, int K,
        const float* __restrict__ s1x, const float* __restrict__ s1g,
        const float* __restrict__ s1b,
        const float* __restrict__ s2x, const float* __restrict__ s2g,
        const float* __restrict__ s2b,
        const float* __restrict__ pos,
        float* __restrict__ y1, float* __restrict__ y2) {
    extern __shared__ uint32_t sm[];
    uint32_t sbase = s2u(sm);
    uint32_t Ab_[2] = {sbase, sbase + 20480};
    uint32_t Bb_[2] = {sbase + 40960, sbase + 43520};
    uint32_t* BsW[2] = {sm + 10240, sm + 10880};

    int tid = threadIdx.x;
    int wid = tid >> 5, lane = tid & 31;
    int wm = wid;
    int n0 = blockIdx.x * 32;

    int arow = tid >> 2, aslot = tid & 3;
    int bn = tid & 31, bj = tid >> 5;

    uint32_t a_off = (uint32_t)(wm * 16 + (lane & 7) + ((lane >> 3) & 1) * 8) * 80
                   + (uint32_t)(lane >> 4) * 16;
    uint32_t b_off = (uint32_t)((lane & 7) + ((lane >> 4) & 1) * 8) * 80
                   + (uint32_t)((lane >> 3) & 1) * 16;

    const int C = K >> 5;
    float b0r, b1r;

    CP16(Ab_[0] + arow * 80 + aslot * 16, W16 + (size_t)arow * K + aslot * 8);
    CP16(Ab_[0] + (arow + 128) * 80 + aslot * 16, W16 + (size_t)(arow + 128) * K + aslot * 8);
    CP_COMMIT();
    b0r = X[(size_t)(bj * 2) * NPIX + n0 + bn];
    b1r = X[(size_t)(bj * 2 + 1) * NPIX + n0 + bn];

    float acc[4][4];
#pragma unroll
    for (int u = 0; u < 4; ++u)
#pragma unroll
        for (int e = 0; e < 4; ++e) acc[u][e] = 0.0f;

    BsW[0][bn * 20 + bj] = packh2(b0r, b1r);
    CP_WAIT0();
    __syncthreads();

    for (int c = 0; c < C; ++c) {
        if (c + 1 < C) {
            int k0 = (c + 1) << 5;
            uint32_t ab = Ab_[(c + 1) & 1];
            CP16(ab + arow * 80 + aslot * 16, W16 + (size_t)arow * K + k0 + aslot * 8);
            CP16(ab + (arow + 128) * 80 + aslot * 16,
                 W16 + (size_t)(arow + 128) * K + k0 + aslot * 8);
            CP_COMMIT();
            b0r = X[(size_t)(k0 + bj * 2) * NPIX + n0 + bn];
            b1r = X[(size_t)(k0 + bj * 2 + 1) * NPIX + n0 + bn];
        }

        uint32_t Abuf = Ab_[c & 1], Bbuf = Bb_[c & 1];
#pragma unroll
        for (int ks = 0; ks < 2; ++ks) {
            uint32_t a[4], b01[4], b23[4];
            LDSM4(a, Abuf + a_off + ks * 32);
            LDSM4(b01, Bbuf + b_off + ks * 32);
            LDSM4(b23, Bbuf + b_off + 16 * 80 + ks * 32);
            mma_f16(acc[0], a, b01);
            mma_f16(acc[1], a, b01 + 2);
            mma_f16(acc[2], a, b23);
            mma_f16(acc[3], a, b23 + 2);
        }

        if (c + 1 < C) {
            CP_WAIT0();
            BsW[(c + 1) & 1][bn * 20 + bj] = packh2(b0r, b1r);
        }
        __syncthreads();
    }

    float* Es = (float*)sm;
    float* sp = Es + 8448;
    float* sq = sp + 512;
    int g = lane >> 2, tg = lane & 3;

    {
        int r0 = wm * 16 + g, r1 = r0 + 8;
        float bv0 = bias[r0], bv1 = bias[r1];
#pragma unroll
        for (int u = 0; u < 4; ++u) {
            int n = u * 8 + 2 * tg;
            float v0 = acc[u][0] + bv0, v1 = acc[u][1] + bv0;
            float v2 = acc[u][2] + bv1, v3 = acc[u][3] + bv1;
            if (EPI == 1) {
                size_t gi0 = (size_t)r0 * NPIX + n0 + n;
                size_t gi1 = (size_t)r1 * NPIX + n0 + n;
                float2 q0 = *(const float2*)(res + gi0);
                float2 q1 = *(const float2*)(res + gi1);
                v0 += q0.x; v1 += q0.y; v2 += q1.x; v3 += q1.y;
            }
            Es[r0 * 33 + n] = v0;
            Es[r0 * 33 + n + 1] = v1;
            Es[r1 * 33 + n] = v2;
            Es[r1 * 33 + n + 1] = v3;
        }
    }
    __syncthreads();

    int px = tid & 31, cg = tid >> 5;
    if (EPI == 1) {
        float e[16], s = 0.0f, q = 0.0f;
#pragma unroll
        for (int i = 0; i < 16; ++i) {
            e[i] = Es[(cg * 16 + i) * 33 + px];
            s += e[i];
            q = fmaf(e[i], e[i], q);
        }
        sp[cg * 32 + px] = s;
        sq[cg * 32 + px] = q;
        __syncthreads();
        float ts = 0.0f, tq = 0.0f;
#pragma unroll
        for (int j = 0; j < 16; ++j) {
            ts += sp[j * 32 + px];
            tq += sq[j * 32 + px];
        }
        float mean = ts * (1.0f / DIMC);
        float rstd = rsqrtf(tq * (1.0f / DIMC) - mean * mean + 1e-5f);
#pragma unroll
        for (int i = 0; i < 16; ++i) {
            int cc = cg * 16 + i;
            Y[(size_t)cc * NPIX + n0 + px] = (e[i] - mean) * rstd * lng[cc] + lnb[cc];
        }
    } else {
        float v[16], s = 0.0f, q = 0.0f;
#pragma unroll
        for (int i = 0; i < 16; ++i) {
            v[i] = s1x[(size_t)(cg * 16 + i) * NPIX + n0 + px];
            s += v[i];
            q = fmaf(v[i], v[i], q);
        }
        sp[cg * 32 + px] = s;
        sq[cg * 32 + px] = q;
        __syncthreads();
        float ts = 0.0f, tq = 0.0f;
#pragma unroll
        for (int j = 0; j < 16; ++j) {
            ts += sp[j * 32 + px];
            tq += sq[j * 32 + px];
        }
        float mean = ts * (1.0f / DIMC);
        float rstd = rsqrtf(tq * (1.0f / DIMC) - mean * mean + 1e-5f);
#pragma unroll
        for (int i = 0; i < 16; ++i) {
            int cc = cg * 16 + i;
            y1[(size_t)cc * NPIX + n0 + px] =
                (v[i] - mean) * rstd * s1g[cc] + s1b[cc] + pos[cc] + Es[cc * 33 + px];
        }
        __syncthreads();
        s = 0.0f; q = 0.0f;
#pragma unroll
        for (int i = 0; i < 16; ++i) {
            v[i] = s2x[(size_t)(cg * 16 + i) * NPIX + n0 + px];
            s += v[i];
            q = fmaf(v[i], v[i], q);
        }
        sp[cg * 32 + px] = s;
        sq[cg * 32 + px] = q;
        __syncthreads();
        ts = 0.0f; tq = 0.0f;
#pragma unroll
        for (int j = 0; j < 16; ++j) {
            ts += sp[j * 32 + px];
            tq += sq[j * 32 + px];
        }
        mean = ts * (1.0f / DIMC);
        rstd = rsqrtf(tq * (1.0f / DIMC) - mean * mean + 1e-5f);
#pragma unroll
        for (int i = 0; i < 16; ++i) {
            int cc = cg * 16 + i;
            y2[(size_t)cc * NPIX + n0 + px] =
                (v[i] - mean) * rstd * s2g[cc] + s2b[cc] + pos[cc] + Es[cc * 33 + px];
        }
    }
}

// ---------------------------------------------------------------------------
// Flash attention, fp16 HMMA + MUFU exp2 + LDMATRIX fragments.
// Smem u32: Ks[2][64][20] (80B rows), Vs[2][32][36] (144B rows),
// Ps[128][36] (144B rows). All ldmatrix phases conflict-free:
// stride 20 u32 -> 20i mod 32 distinct; stride 36 u32 -> 4i mod 32 distinct.
// ---------------------------------------------------------------------------
#define FL_SMEM 37888

__global__ void __launch_bounds__(256, 2)
flash_mma(const __half* __restrict__ Q16, const __half* __restrict__ K16,
          const __half* __restrict__ V16, float* __restrict__ O) {
    extern __shared__ uint32_t fsm[];
    uint32_t* Ks = fsm;               // [2][64][20]
    uint32_t* Vs = fsm + 2560;        // [2][32][36]
    uint32_t* Ps = fsm + 4864;        // [128][36]

    int tid = threadIdx.x;
    int wid = tid >> 5, lane = tid & 31;
    int g = lane >> 2, tg = lane & 3;
    int h = blockIdx.y;
    int n0 = blockIdx.x * 128;
    int r0 = wid * 16 + g, r1 = r0 + 8;

    const __half* Qh = Q16 + (size_t)h * 32 * NPIX;
    const __half* Kh = K16 + (size_t)h * 32 * NPIX;
    const uint32_t* Vhu = (const uint32_t*)(V16 + (size_t)h * 32 * NPIX);

    // byte bases for ldmatrix
    uint32_t ks_b = s2u(fsm);
    uint32_t vs_b = ks_b + 2560 * 4;
    uint32_t ps_b = ks_b + 4864 * 4;
    uint32_t kfrag = (uint32_t)((lane & 7) + ((lane >> 4) & 1) * 8) * 80
                   + (uint32_t)((lane >> 3) & 1) * 16;
    uint32_t vfrag = (uint32_t)((lane & 7) + ((lane >> 4) & 1) * 8) * 144
                   + (uint32_t)((lane >> 3) & 1) * 16;
    uint32_t pfrag = (uint32_t)(wid * 16 + (lane & 7) + ((lane >> 3) & 1) * 8) * 144
                   + (uint32_t)(lane >> 4) * 16;

    int kkey = tid & 63, kds = tid >> 6;
    int vd = tid >> 4, vslot = tid & 15;

    __half kr[2][4];
    uint2 vr[2];
#pragma unroll
    for (int i = 0; i < 2; ++i) {
        int ds = kds + i * 4;
#pragma unroll
        for (int j = 0; j < 4; ++j)
            kr[i][j] = Kh[(size_t)(ds * 4 + j) * NPIX + kkey];
        vr[i] = *(const uint2*)(Vhu + (size_t)(vd + i * 16) * 2048 + vslot * 2);
    }

    __half* Qsh = (__half*)Ps;
#pragma unroll
    for (int it = 0; it < 4; ++it) {
        int t = tid + it * 256;
        int q4 = t & 31, d = t >> 5;
        uint2 qv = *(const uint2*)(Qh + (size_t)d * NPIX + n0 + q4 * 4);
        const __half* qp = (const __half*)&qv;
        Qsh[(q4 * 4 + 0) * 40 + d] = qp[0];
        Qsh[(q4 * 4 + 1) * 40 + d] = qp[1];
        Qsh[(q4 * 4 + 2) * 40 + d] = qp[2];
        Qsh[(q4 * 4 + 3) * 40 + d] = qp[3];
    }
    __syncthreads();
    uint32_t qa[2][4];
#pragma unroll
    for (int ks = 0; ks < 2; ++ks) {
        int kc = ks * 8 + tg;
        qa[ks][0] = Ps[r0 * 20 + kc];
        qa[ks][1] = Ps[r1 * 20 + kc];
        qa[ks][2] = Ps[r0 * 20 + kc + 4];
        qa[ks][3] = Ps[r1 * 20 + kc + 4];
    }
#pragma unroll
    for (int i = 0; i < 2; ++i) {
        int ds = kds + i * 4;
        *(uint2*)(Ks + kkey * 20 + ds * 2) =
            make_uint2(packhh(kr[i][0], kr[i][1]), packhh(kr[i][2], kr[i][3]));
        *(uint2*)(Vs + (vd + i * 16) * 36 + vslot * 2) = vr[i];
    }
    __syncthreads();

    float m0s = -1e30f, m1s = -1e30f, l0 = 0.0f, l1 = 0.0f;
    float oa[4][4];
#pragma unroll
    for (int u = 0; u < 4; ++u)
#pragma unroll
        for (int e = 0; e < 4; ++e) oa[u][e] = 0.0f;

    for (int kt = 0; kt < 64; ++kt) {
        if (kt + 1 < 64) {
            int mg = (kt + 1) * 64;
#pragma unroll
            for (int i = 0; i < 2; ++i) {
                int ds = kds + i * 4;
#pragma unroll
                for (int j = 0; j < 4; ++j)
                    kr[i][j] = Kh[(size_t)(ds * 4 + j) * NPIX + mg + kkey];
                vr[i] = *(const uint2*)(Vhu + (size_t)(vd + i * 16) * 2048 + (mg >> 1) + vslot * 2);
            }
        }

        uint32_t KsA = ks_b + (kt & 1) * 5120;   // 1280 u32
        uint32_t VsA = vs_b + (kt & 1) * 4608;   // 1152 u32

        // ---- scores S = Q K^T via ldmatrix B-frags (8 LDSM4)
        float sc[8][4];
#pragma unroll
        for (int ns = 0; ns < 8; ++ns)
#pragma unroll
            for (int e = 0; e < 4; ++e) sc[ns][e] = 0.0f;
#pragma unroll
        for (int ks = 0; ks < 2; ++ks) {
#pragma unroll
            for (int nb = 0; nb < 4; ++nb) {
                uint32_t bb[4];
                LDSM4(bb, KsA + nb * 1280 + kfrag + ks * 32);
                mma_f16(sc[2 * nb], qa[ks], bb);
                mma_f16(sc[2 * nb + 1], qa[ks], bb + 2);
            }
        }

        // ---- online softmax (base-2)
        float mx0 = -1e30f, mx1 = -1e30f;
#pragma unroll
        for (int ns = 0; ns < 8; ++ns) {
            mx0 = fmaxf(mx0, fmaxf(sc[ns][0], sc[ns][1]));
            mx1 = fmaxf(mx1, fmaxf(sc[ns][2], sc[ns][3]));
        }
        mx0 = fmaxf(mx0, __shfl_xor_sync(0xffffffffu, mx0, 1));
        mx0 = fmaxf(mx0, __shfl_xor_sync(0xffffffffu, mx0, 2));
        mx1 = fmaxf(mx1, __shfl_xor_sync(0xffffffffu, mx1, 1));
        mx1 = fmaxf(mx1, __shfl_xor_sync(0xffffffffu, mx1, 2));
        float mn0 = fmaxf(m0s, mx0), mn1 = fmaxf(m1s, mx1);
        float c0f = fexp2(m0s - mn0), c1f = fexp2(m1s - mn1);
        float rs0 = 0.0f, rs1 = 0.0f;
#pragma unroll
        for (int ns = 0; ns < 8; ++ns) {
            float p0 = fexp2(sc[ns][0] - mn0);
            float p1 = fexp2(sc[ns][1] - mn0);
            float p2 = fexp2(sc[ns][2] - mn1);
            float p3 = fexp2(sc[ns][3] - mn1);
            rs0 += p0 + p1;
            rs1 += p2 + p3;
            Ps[r0 * 36 + ns * 4 + tg] = packh2(p0, p1);
            Ps[r1 * 36 + ns * 4 + tg] = packh2(p2, p3);
        }
        rs0 += __shfl_xor_sync(0xffffffffu, rs0, 1);
        rs0 += __shfl_xor_sync(0xffffffffu, rs0, 2);
        rs1 += __shfl_xor_sync(0xffffffffu, rs1, 1);
        rs1 += __shfl_xor_sync(0xffffffffu, rs1, 2);
        l0 = l0 * c0f + rs0;
        l1 = l1 * c1f + rs1;
        m0s = mn0; m1s = mn1;
#pragma unroll
        for (int u = 0; u < 4; ++u) {
            oa[u][0] *= c0f; oa[u][1] *= c0f;
            oa[u][2] *= c1f; oa[u][3] *= c1f;
        }
        __syncwarp();  // P rows r0/r1 warp-local

        // ---- O += P V via ldmatrix (12 LDSM4)
#pragma unroll
        for (int ks = 0; ks < 4; ++ks) {
            uint32_t pa[4], v0[4], v1[4];
            LDSM4(pa, ps_b + pfrag + ks * 32);
            LDSM4(v0, VsA + vfrag + ks * 32);
            LDSM4(v1, VsA + vfrag + 2304 + ks * 32);  // +16 d rows
            mma_f16(oa[0], pa, v0);
            mma_f16(oa[1], pa, v0 + 2);
            mma_f16(oa[2], pa, v1);
            mma_f16(oa[3], pa, v1 + 2);
        }
        __syncwarp();

        if (kt + 1 < 64) {
            uint32_t* Ksn = Ks + ((kt + 1) & 1) * 1280;
            uint32_t* Vsn = Vs + ((kt + 1) & 1) * 1152;
#pragma unroll
            for (int i = 0; i < 2; ++i) {
                int ds = kds + i * 4;
                *(uint2*)(Ksn + kkey * 20 + ds * 2) =
                    make_uint2(packhh(kr[i][0], kr[i][1]), packhh(kr[i][2], kr[i][3]));
                *(uint2*)(Vsn + (vd + i * 16) * 36 + vslot * 2) = vr[i];
            }
            __syncthreads();
        }
    }

    float il0 = 1.0f / l0, il1 = 1.0f / l1;
#pragma unroll
    for (int ns = 0; ns < 4; ++ns) {
        int d0 = ns * 8 + 2 * tg;
        O[(size_t)(h * 32 + d0) * NPIX + n0 + r0] = oa[ns][0] * il0;
        O[(size_t)(h * 32 + d0 + 1) * NPIX + n0 + r0] = oa[ns][1] * il0;
        O[(size_t)(h * 32 + d0) * NPIX + n0 + r1] = oa[ns][2] * il1;
        O[(size_t)(h * 32 + d0 + 1) * NPIX + n0 + r1] = oa[ns][3] * il1;
    }
}

// ---------------------------------------------------------------------------
extern "C" void kernel_launch(void* const* d_in, const int* in_sizes, int n_in,
                              void* d_out, int out_size) {
    const float* rgb   = (const float*)d_in[0];
    const float* dpt   = (const float*)d_in[1];
    const float* xdpt  = (const float*)d_in[2];
    const float* wq    = (const float*)d_in[3];
    const float* bq    = (const float*)d_in[4];
    const float* wk    = (const float*)d_in[5];
    const float* bk    = (const float*)d_in[6];
    const float* wv    = (const float*)d_in[7];
    const float* bv    = (const float*)d_in[8];
    const float* wo    = (const float*)d_in[9];
    const float* bo    = (const float*)d_in[10];
    const float* ga_rgb = (const float*)d_in[11];
    const float* be_rgb = (const float*)d_in[12];
    const float* ga_dpt = (const float*)d_in[13];
    const float* be_dpt = (const float*)d_in[14];
    const float* ga1   = (const float*)d_in[15];
    const float* be1   = (const float*)d_in[16];
    const float* ga2   = (const float*)d_in[17];
    const float* be2   = (const float*)d_in[18];
    const float* w_mlp1 = (const float*)d_in[19];
    const float* b_mlp1 = (const float*)d_in[20];
    const float* w_mlp2 = (const float*)d_in[21];
    const float* b_mlp2 = (const float*)d_in[22];
    const float* w_de1 = (const float*)d_in[23];
    const float* b_de1 = (const float*)d_in[24];
    const float* w_de2 = (const float*)d_in[25];
    const float* b_de2 = (const float*)d_in[26];
    const float* pos_emb = (const float*)d_in[27];
    const float* scale = (const float*)d_in[28];
    float* out = (float*)d_out;

    float *p_xd, *p_r1, *p_rgbln, *p_dptln, *p_fused, *p_oln, *p_h;
    __half *p_q16, *p_k16, *p_v16, *p_w16;
    cudaGetSymbolAddress((void**)&p_xd, g_xd);
    cudaGetSymbolAddress((void**)&p_r1, g_r1);
    cudaGetSymbolAddress((void**)&p_rgbln, g_rgbln);
    cudaGetSymbolAddress((void**)&p_dptln, g_dptln);
    cudaGetSymbolAddress((void**)&p_q16, g_q16);
    cudaGetSymbolAddress((void**)&p_k16, g_k16);
    cudaGetSymbolAddress((void**)&p_v16, g_v16);
    cudaGetSymbolAddress((void**)&p_fused, g_fused);
    cudaGetSymbolAddress((void**)&p_oln, g_oln);
    cudaGetSymbolAddress((void**)&p_h, g_h);
    cudaGetSymbolAddress((void**)&p_w16, g_w16);

    static bool attr_done = false;
    if (!attr_done) {
        cudaFuncSetAttribute(gemm_mma<2>, cudaFuncAttributeMaxDynamicSharedMemorySize, GEMM_SMEM);
        cudaFuncSetAttribute(gemm_qkv, cudaFuncAttributeMaxDynamicSharedMemorySize, GEMM_SMEM);
        cudaFuncSetAttribute(gemm_ln<0>, cudaFuncAttributeMaxDynamicSharedMemorySize, GLN_SMEM);
        cudaFuncSetAttribute(gemm_ln<1>, cudaFuncAttributeMaxDynamicSharedMemorySize, GLN_SMEM);
        cudaFuncSetAttribute(flash_mma, cudaFuncAttributeMaxDynamicSharedMemorySize, FL_SMEM);
        attr_done = true;
    }

    // weights -> fp16 pool
    cvt_weights<<<dim3(128, 7), 256>>>(w_de2, wq, wk, wv, wo, w_mlp1, w_mlp2, p_w16);

    // depth positional-embedding path
    downsample_kernel<<<16, 256>>>(xdpt, p_xd);
    conv3_kernel<<<256, 256>>>(p_xd, w_de1, b_de1, p_r1);

    // pe GEMM fused with LN(rgb)+pos+pe and LN(dpt)+pos+pe
    gemm_ln<0><<<128, 512, GLN_SMEM>>>(p_w16 + OFF_DE2, p_r1, b_de2, nullptr, nullptr, nullptr,
                                       nullptr, DIMC,
                                       rgb, ga_rgb, be_rgb, dpt, ga_dpt, be_dpt,
                                       pos_emb, p_rgbln, p_dptln);

    // QKV projections
    gemm_qkv<<<dim3(64, 2, 3), 256, GEMM_SMEM>>>(p_w16, bq, bk, bv,
                                                 p_rgbln, p_dptln, p_q16, p_k16, p_v16, scale);

    // flash attention
    flash_mma<<<dim3(32, 8), 256, FL_SMEM>>>(p_q16, p_k16, p_v16, p_fused);

    // output proj + residual + LN1 fused
    gemm_ln<1><<<128, 512, GLN_SMEM>>>(p_w16 + OFF_O, p_fused, bo, rgb, ga1, be1,
                                       p_oln, DIMC,
                                       nullptr, nullptr, nullptr, nullptr, nullptr,
                                       nullptr, nullptr, nullptr, nullptr);

    // MLP up (exact gelu)
    gemm_mma<2><<<dim3(64, 8), 256, GEMM_SMEM>>>(p_w16 + OFF_M1, p_oln, b_mlp1, p_h,
                                                 MLPC, DIMC, NPIX);

    // MLP down + residual + final LN fused -> d_out
    gemm_ln<1><<<128, 512, GLN_SMEM>>>(p_w16 + OFF_M2, p_h, b_mlp2, p_oln, ga2, be2,
                                       out, MLPC,
                                       nullptr, nullptr, nullptr, nullptr, nullptr,
                                       nullptr, nullptr, nullptr, nullptr);
}